// round 2
// baseline (speedup 1.0000x reference)
#include <cuda_runtime.h>
#include <math.h>

#define BB    4
#define NTOK  4096
#define CDIM  1024
#define HH    4
#define DH    256
#define BHN   (BB*HH)        /* 16 */
#define EPSV   1e-5f
#define SCALEV 0.03125f      /* 1/sqrt(1024) */

// ---------------- scratch (device globals; no allocation) ----------------
__device__ __align__(16) float g_Q  [(size_t)BB*HH*NTOK*DH];
__device__ __align__(16) float g_Qd [(size_t)BB*HH*NTOK*DH];
__device__ __align__(16) float g_K  [(size_t)BB*HH*NTOK*DH];
__device__ __align__(16) float g_V  [(size_t)BB*HH*NTOK*DH];
__device__ __align__(16) float g_Kd [(size_t)BB*HH*NTOK*DH];
__device__ __align__(16) float g_Vd [(size_t)BB*HH*NTOK*DH];
__device__ __align__(16) float g_s1 [(size_t)BHN*DH*DH];
__device__ __align__(16) float g_sd1[(size_t)BHN*DH*DH];
__device__ __align__(16) float g_ctx1 [(size_t)BB*NTOK*CDIM];
__device__ __align__(16) float g_ctxd1[(size_t)BB*NTOK*CDIM];
__device__ float g_mv[2*BHN*2];   // [path][bh][{mean,var}]

// ---------------- 64x64 tile compute core (4x4 per thread) ----------------
__device__ __forceinline__ void mma16(const float (*As)[64], const float (*Ws)[64],
                                      int tx, int ty, float acc[4][4])
{
#pragma unroll
    for (int kk = 0; kk < 16; ++kk) {
        float4 a4 = *reinterpret_cast<const float4*>(&As[kk][ty*4]);
        float4 b4 = *reinterpret_cast<const float4*>(&Ws[kk][tx*4]);
        float av[4] = {a4.x, a4.y, a4.z, a4.w};
        float bv[4] = {b4.x, b4.y, b4.z, b4.w};
#pragma unroll
        for (int i = 0; i < 4; ++i)
#pragma unroll
            for (int j = 0; j < 4; ++j)
                acc[i][j] = fmaf(av[i], bv[j], acc[i][j]);
    }
}

// C[m,n] = sum_k A[m,k] * W[n,k]   (both row-major, NT). A/W pre-offset to tile origin.
__device__ __forceinline__ void gemm64_nt_body(const float* __restrict__ A, int lda,
                                               const float* __restrict__ W, int ldw,
                                               int K, float acc[4][4])
{
    __shared__ float As[16][64];
    __shared__ float Ws[16][64];
    const int tid = threadIdx.x;
    const int tx = tid & 15, ty = tid >> 4;
    const int lm = tid >> 2;          // 0..63
    const int lk = (tid & 3) * 4;     // 0,4,8,12
    for (int k0 = 0; k0 < K; k0 += 16) {
        float4 va = *reinterpret_cast<const float4*>(A + (size_t)lm*lda + k0 + lk);
        float4 vw = *reinterpret_cast<const float4*>(W + (size_t)lm*ldw + k0 + lk);
        As[lk+0][lm] = va.x; As[lk+1][lm] = va.y; As[lk+2][lm] = va.z; As[lk+3][lm] = va.w;
        Ws[lk+0][lm] = vw.x; Ws[lk+1][lm] = vw.y; Ws[lk+2][lm] = vw.z; Ws[lk+3][lm] = vw.w;
        __syncthreads();
        mma16(As, Ws, tx, ty, acc);
        __syncthreads();
    }
}

// C[c,k] = sum_n A[n,c] * B[n,k]   (TN: contract leading dim). A/B pre-offset to col origin.
__device__ __forceinline__ void gemm64_tn_body(const float* __restrict__ A, int lda,
                                               const float* __restrict__ Bm, int ldb,
                                               int K, float acc[4][4])
{
    __shared__ float As[16][64];
    __shared__ float Bs[16][64];
    const int tid = threadIdx.x;
    const int tx = tid & 15, ty = tid >> 4;
    const int lr = tid >> 4;          // 0..15 (k-step row)
    const int lc = (tid & 15) * 4;    // 0..60
    for (int k0 = 0; k0 < K; k0 += 16) {
        *reinterpret_cast<float4*>(&As[lr][lc]) =
            *reinterpret_cast<const float4*>(A  + (size_t)(k0+lr)*lda + lc);
        *reinterpret_cast<float4*>(&Bs[lr][lc]) =
            *reinterpret_cast<const float4*>(Bm + (size_t)(k0+lr)*ldb + lc);
        __syncthreads();
        mma16(As, Bs, tx, ty, acc);
        __syncthreads();
    }
}

// ---------------- stage kernels ----------------

// which: 0 Q, 1 Qd, 2 K, 3 V, 4 Kd, 5 Vd
__global__ void __launch_bounds__(256) k_proj(const float* __restrict__ in,
                                              const float* __restrict__ W,
                                              int which, int perHead)
{
    float* out = (which == 0) ? g_Q  : (which == 1) ? g_Qd :
                 (which == 2) ? g_K  : (which == 3) ? g_V  :
                 (which == 4) ? g_Kd : g_Vd;
    const int bh = blockIdx.z;
    const int b = bh >> 2, h = bh & 3;
    const int n0 = blockIdx.x * 64, o0 = blockIdx.y * 64;
    const float* A  = in + ((size_t)b*NTOK + n0)*CDIM + h*DH;
    const float* Wp = W + (perHead ? (size_t)h*DH*DH : 0) + (size_t)o0*DH;
    float acc[4][4] = {};
    gemm64_nt_body(A, CDIM, Wp, DH, DH, acc);
    const int tx = threadIdx.x & 15, ty = threadIdx.x >> 4;
    float* O = out + ((size_t)bh*NTOK + n0)*DH + o0;
#pragma unroll
    for (int i = 0; i < 4; ++i) {
        float4 v = make_float4(acc[i][0], acc[i][1], acc[i][2], acc[i][3]);
        *reinterpret_cast<float4*>(O + (size_t)(ty*4+i)*DH + tx*4) = v;
    }
}

// which 0: s1 = scale * Q^T Kd ; which 1: sd1 = scale * Qd^T K
__global__ void __launch_bounds__(256) k_score(int which)
{
    const float* Am = which ? g_Qd : g_Q;
    const float* Bm = which ? g_K  : g_Kd;
    float*       S  = which ? g_sd1 : g_s1;
    const int bh = blockIdx.z;
    const int c0 = blockIdx.y * 64, kk0 = blockIdx.x * 64;
    const float* Ap = Am + (size_t)bh*NTOK*DH + c0;
    const float* Bp = Bm + (size_t)bh*NTOK*DH + kk0;
    float acc[4][4] = {};
    gemm64_tn_body(Ap, DH, Bp, DH, NTOK, acc);
    const int tx = threadIdx.x & 15, ty = threadIdx.x >> 4;
    float* Sp = S + (size_t)bh*DH*DH + (size_t)c0*DH + kk0;
#pragma unroll
    for (int i = 0; i < 4; ++i) {
        float4 v = make_float4(acc[i][0]*SCALEV, acc[i][1]*SCALEV,
                               acc[i][2]*SCALEV, acc[i][3]*SCALEV);
        *reinterpret_cast<float4*>(Sp + (size_t)(ty*4+i)*DH + tx*4) = v;
    }
}

// per (path, bh): mean & var over the 256x256 score plane
__global__ void __launch_bounds__(256) k_moments()
{
    const int idx = blockIdx.x;                 // 0..31
    const float* s = (idx < BHN ? g_s1 : g_sd1) + (size_t)(idx & 15)*DH*DH;
    __shared__ float sh[256], sh2[256];
    float sum = 0.f, sq = 0.f;
    for (int i = threadIdx.x; i < DH*DH; i += 256) {
        float v = s[i];
        sum += v; sq = fmaf(v, v, sq);
    }
    sh[threadIdx.x] = sum; sh2[threadIdx.x] = sq;
    __syncthreads();
    for (int o = 128; o; o >>= 1) {
        if (threadIdx.x < o) { sh[threadIdx.x] += sh[threadIdx.x+o]; sh2[threadIdx.x] += sh2[threadIdx.x+o]; }
        __syncthreads();
    }
    if (threadIdx.x == 0) {
        float m   = sh[0]  * (1.f/65536.f);
        float var = sh2[0] * (1.f/65536.f) - m*m;
        g_mv[idx*2]   = m;
        g_mv[idx*2+1] = var;
    }
}

// instance-norm (per bh moments) + row softmax over k (256), in-place
__global__ void __launch_bounds__(256) k_softmax()
{
    const int path = blockIdx.z;
    const int bh   = blockIdx.y;
    const int c    = blockIdx.x;
    float* row = (path ? g_sd1 : g_s1) + ((size_t)bh*DH + c)*DH;
    const int mvi = path*BHN + bh;
    const float mean = g_mv[mvi*2];
    const float inv  = rsqrtf(g_mv[mvi*2+1] + EPSV);
    const int tid = threadIdx.x;
    float y = (row[tid] - mean) * inv;

    __shared__ float red[8];
    float m = y;
#pragma unroll
    for (int o = 16; o; o >>= 1) m = fmaxf(m, __shfl_xor_sync(0xffffffffu, m, o));
    if ((tid & 31) == 0) red[tid >> 5] = m;
    __syncthreads();
    if (tid == 0) {
        float mm = red[0];
        for (int i = 1; i < 8; ++i) mm = fmaxf(mm, red[i]);
        red[0] = mm;
    }
    __syncthreads();
    float e = expf(y - red[0]);
    __syncthreads();
    float s = e;
#pragma unroll
    for (int o = 16; o; o >>= 1) s += __shfl_xor_sync(0xffffffffu, s, o);
    if ((tid & 31) == 0) red[tid >> 5] = s;
    __syncthreads();
    if (tid == 0) {
        float t = 0.f;
        for (int i = 0; i < 8; ++i) t += red[i];
        red[0] = t;
    }
    __syncthreads();
    row[tid] = e / red[0];
}

// which 0: ctx1[b,n,c*4+h] = sum_k p1 * Vd ; which 1: ctxd1 with (sd1, V)
__global__ void __launch_bounds__(256) k_ctx(int which)
{
    const float* Vm = which ? g_V   : g_Vd;
    const float* P  = which ? g_sd1 : g_s1;
    float*      ctx = which ? g_ctxd1 : g_ctx1;
    const int bh = blockIdx.z, b = bh >> 2, h = bh & 3;
    const int n0 = blockIdx.x * 64, c0 = blockIdx.y * 64;
    const float* A = Vm + ((size_t)bh*NTOK + n0)*DH;
    const float* W = P  + (size_t)bh*DH*DH + (size_t)c0*DH;
    float acc[4][4] = {};
    gemm64_nt_body(A, DH, W, DH, DH, acc);
    const int tx = threadIdx.x & 15, ty = threadIdx.x >> 4;
    float* O = ctx + ((size_t)b*NTOK + n0)*CDIM + h;
#pragma unroll
    for (int i = 0; i < 4; ++i)
#pragma unroll
        for (int j = 0; j < 4; ++j)
            O[(size_t)(ty*4+i)*CDIM + (size_t)(c0 + tx*4 + j)*4] = acc[i][j];
}

// O = ctx @ Wout^T  (M = B*N flat)
__global__ void __launch_bounds__(256) k_out(const float* __restrict__ W,
                                             float* __restrict__ O, int which)
{
    const float* ctx = which ? g_ctxd1 : g_ctx1;
    const int m0 = blockIdx.x * 64, j0 = blockIdx.y * 64;
    const float* A  = ctx + (size_t)m0*CDIM;
    const float* Wp = W   + (size_t)j0*CDIM;
    float acc[4][4] = {};
    gemm64_nt_body(A, CDIM, Wp, CDIM, CDIM, acc);
    const int tx = threadIdx.x & 15, ty = threadIdx.x >> 4;
    float* Op = O + (size_t)m0*CDIM + j0;
#pragma unroll
    for (int i = 0; i < 4; ++i) {
        float4 v = make_float4(acc[i][0], acc[i][1], acc[i][2], acc[i][3]);
        *reinterpret_cast<float4*>(Op + (size_t)(ty*4+i)*CDIM + tx*4) = v;
    }
}

// ---------------- launch ----------------
extern "C" void kernel_launch(void* const* d_in, const int* in_sizes, int n_in,
                              void* d_out, int out_size)
{
    const float* emb1     = (const float*)d_in[0];
    const float* emb_all  = (const float*)d_in[1];
    const float* embd1    = (const float*)d_in[2];
    const float* emb_alld = (const float*)d_in[3];
    const float* Wq    = (const float*)d_in[4];
    const float* Wqd   = (const float*)d_in[5];
    const float* Wk0   = (const float*)d_in[6];
    const float* Wv0   = (const float*)d_in[7];
    const float* Wkd0  = (const float*)d_in[8];
    const float* Wvd0  = (const float*)d_in[9];
    const float* Wout  = (const float*)d_in[10];
    const float* Woutd = (const float*)d_in[11];
    float* out = (float*)d_out;

    dim3 gp(NTOK/64, DH/64, BHN);
    k_proj<<<gp, 256>>>(emb1,     Wq,   0, 1);
    k_proj<<<gp, 256>>>(embd1,    Wqd,  1, 1);
    k_proj<<<gp, 256>>>(emb_all,  Wk0,  2, 0);
    k_proj<<<gp, 256>>>(emb_all,  Wv0,  3, 0);
    k_proj<<<gp, 256>>>(emb_alld, Wkd0, 4, 0);
    k_proj<<<gp, 256>>>(emb_alld, Wvd0, 5, 0);

    dim3 gs(DH/64, DH/64, BHN);
    k_score<<<gs, 256>>>(0);
    k_score<<<gs, 256>>>(1);

    k_moments<<<32, 256>>>();
    k_softmax<<<dim3(DH, BHN, 2), 256>>>();

    dim3 gc(NTOK/64, DH/64, BHN);
    k_ctx<<<gc, 256>>>(0);
    k_ctx<<<gc, 256>>>(1);

    dim3 go(BB*NTOK/64, CDIM/64);
    k_out<<<go, 256>>>(Wout,  out, 0);
    k_out<<<go, 256>>>(Woutd, out + (size_t)BB*NTOK*CDIM, 1);
}

// round 4
// speedup vs baseline: 2.3566x; 2.3566x over previous
#include <cuda_runtime.h>
#include <cuda_bf16.h>
#include <stdint.h>
#include <math.h>

typedef __nv_bfloat16 bf;

#define NTOK 4096
#define EPSV 1e-5f
#define SCALEV 0.03125f
#define BM 128
#define BN 128
#define BK 32
#define SMEM_BYTES 81920   /* 2 buffers x 4 tiles x 128 rows x 80B; epilogue stg 66KB fits */

// ---------------- scratch ----------------
__device__ __align__(16) bf g_x1h[16777216], g_x1l[16777216];
__device__ __align__(16) bf g_xah[16777216], g_xal[16777216];
__device__ __align__(16) bf g_xdh[16777216], g_xdl[16777216];
__device__ __align__(16) bf g_xbh[16777216], g_xbl[16777216];
__device__ __align__(16) bf g_qth[16777216], g_qtl[16777216];
__device__ __align__(16) bf g_qdth[16777216], g_qdtl[16777216];
__device__ __align__(16) bf g_kth[16777216], g_ktl[16777216];
__device__ __align__(16) bf g_kdth[16777216], g_kdtl[16777216];
__device__ __align__(16) bf g_vh[16777216],  g_vl[16777216];
__device__ __align__(16) bf g_vdh[16777216], g_vdl[16777216];
__device__ __align__(16) bf g_wqh[262144],  g_wql[262144];
__device__ __align__(16) bf g_wqdh[262144], g_wqdl[262144];
__device__ __align__(16) bf g_wkh[65536],  g_wkl[65536];
__device__ __align__(16) bf g_wvh[65536],  g_wvl[65536];
__device__ __align__(16) bf g_wkdh[65536], g_wkdl[65536];
__device__ __align__(16) bf g_wvdh[65536], g_wvdl[65536];
__device__ __align__(16) bf g_woh[1048576], g_wol[1048576];
__device__ __align__(16) bf g_wodh[1048576], g_wodl[1048576];
__device__ __align__(16) float g_s[2097152];
__device__ __align__(16) bf g_ph[2097152], g_pl[2097152];
__device__ __align__(16) bf g_ch[33554432], g_cl[33554432];
__device__ float g_mv[64];

// ---------------- helpers ----------------
__device__ __forceinline__ uint32_t smem_u32(const void* p){
    uint32_t a;
    asm("{ .reg .u64 t; cvta.to.shared.u64 t, %1; cvt.u32.u64 %0, t; }" : "=r"(a) : "l"(p));
    return a;
}
__device__ __forceinline__ void cp16(uint32_t sa, const void* g){
    asm volatile("cp.async.cg.shared.global [%0], [%1], 16;" :: "r"(sa), "l"(g));
}
__device__ __forceinline__ void mma16816(float* d, const uint32_t* a, const uint32_t* b){
    asm volatile("mma.sync.aligned.m16n8k16.row.col.f32.bf16.bf16.f32 "
        "{%0,%1,%2,%3}, {%4,%5,%6,%7}, {%8,%9}, {%0,%1,%2,%3};"
        : "+f"(d[0]),"+f"(d[1]),"+f"(d[2]),"+f"(d[3])
        : "r"(a[0]),"r"(a[1]),"r"(a[2]),"r"(a[3]),"r"(b[0]),"r"(b[1]));
}
__device__ __forceinline__ uint32_t lds32(const char* p){ return *(const uint32_t*)p; }
__device__ __forceinline__ void split2(float v, bf& h, bf& l){
    h = __float2bfloat16(v);
    l = __float2bfloat16(v - __bfloat162float(h));
}

// ---------------- generic split-2 bf16 mma.sync GEMM ----------------
// C[m,n] = sum_k A[m,k]*B[n,k] (row-major hi/lo pairs), 128x128 tile/CTA.
// mode 0: fp32*scale -> oF ; mode 1: split bf16 natural ; mode 2: split bf16 transposed
__global__ void __launch_bounds__(256, 1) k_gemm(
    const bf* __restrict__ Ah, const bf* __restrict__ Al, long sAb, long sAh, int lda,
    const bf* __restrict__ Bh, const bf* __restrict__ Bl, long sBb, long sBh, int ldb,
    int K, int mode, float scale,
    float* __restrict__ oF, bf* __restrict__ oH, bf* __restrict__ oL,
    long sOb, long sOh, int ldo)
{
    extern __shared__ char dyn[];
    const uint32_t smb = smem_u32(dyn);
    const int tid = threadIdx.x;
    const int l = tid & 31, wid = tid >> 5;
    const int wm = wid >> 2, wn = wid & 3;           // warp tile (wm*64, wn*32)
    const int quad = l >> 2, lane2 = (l & 3) * 2;
    const int z = blockIdx.z;
    const int m0 = blockIdx.x * BM, n0 = blockIdx.y * BN;
    const long offA = (long)(z>>2)*sAb + (long)(z&3)*sAh;
    const long offB = (long)(z>>2)*sBb + (long)(z&3)*sBh;
    const long offO = (long)(z>>2)*sOb + (long)(z&3)*sOh;

    const bf* pAh = Ah + offA + (size_t)m0*lda;
    const bf* pAl = Al + offA + (size_t)m0*lda;
    const bf* pBh = Bh + offB + (size_t)n0*ldb;
    const bf* pBl = Bl + offB + (size_t)n0*ldb;

    float acc[4][4][4];
#pragma unroll
    for (int a = 0; a < 4; ++a)
#pragma unroll
        for (int b = 0; b < 4; ++b)
#pragma unroll
            for (int c = 0; c < 4; ++c) acc[a][b][c] = 0.f;

    const int NC = K / BK;
    const int crow = tid >> 2, ccc = (tid & 3) * 16;     // copy: 256 thr -> rows 0..63 x4, two passes

    // ---- copy chunk c into buffer bufi ----
    auto copy_chunk = [&](int c, int bufi){
        const bf* srcs[4] = {pAh + c*BK, pAl + c*BK, pBh + c*BK, pBl + c*BK};
#pragma unroll
        for (int t = 0; t < 4; ++t){
            const int ld = (t < 2) ? lda : ldb;
            const uint32_t sb = smb + bufi*40960 + t*10240;
#pragma unroll
            for (int i = 0; i < 2; ++i){
                int e = tid + i*256;           // 0..511
                int row = e >> 2, cc = e & 3;
                cp16(sb + row*80 + cc*16, srcs[t] + (size_t)row*ld + cc*8);
            }
        }
    };

    copy_chunk(0, 0);
    asm volatile("cp.async.commit_group;");

    // fragment base byte offsets (within a tile)
    int aob[4], bob[4];
#pragma unroll
    for (int mt = 0; mt < 4; ++mt) aob[mt] = (wm*64 + mt*16 + quad)*80 + lane2*2;
#pragma unroll
    for (int nt = 0; nt < 4; ++nt) bob[nt] = (wn*32 + nt*8 + quad)*80 + lane2*2;

    for (int c = 0; c < NC; ++c){
        if (c + 1 < NC){
            copy_chunk(c+1, (c+1)&1);
            asm volatile("cp.async.commit_group;");
            asm volatile("cp.async.wait_group 1;");
        } else {
            asm volatile("cp.async.wait_group 0;");
        }
        __syncthreads();

        const char* tA  = dyn + (c&1)*40960;
        const char* tAl = tA + 10240;
        const char* tB  = tA + 20480;
        const char* tBl = tA + 30720;

#pragma unroll
        for (int ks = 0; ks < 2; ++ks){
            const int kb = ks * 32;   // 16 bf16 = 32 bytes
            uint32_t aH[4][4], aT[4][4], bX[4][2];
#pragma unroll
            for (int mt = 0; mt < 4; ++mt){
                aH[mt][0] = lds32(tA + aob[mt] + kb);
                aH[mt][1] = lds32(tA + aob[mt] + kb + 640);
                aH[mt][2] = lds32(tA + aob[mt] + kb + 16);
                aH[mt][3] = lds32(tA + aob[mt] + kb + 656);
            }
#pragma unroll
            for (int nt = 0; nt < 4; ++nt){
                bX[nt][0] = lds32(tB + bob[nt] + kb);
                bX[nt][1] = lds32(tB + bob[nt] + kb + 16);
            }
#pragma unroll
            for (int mt = 0; mt < 4; ++mt)
#pragma unroll
                for (int nt = 0; nt < 4; ++nt) mma16816(acc[mt][nt], aH[mt], bX[nt]);
            // lo(A) x hi(B)
#pragma unroll
            for (int mt = 0; mt < 4; ++mt){
                aT[mt][0] = lds32(tAl + aob[mt] + kb);
                aT[mt][1] = lds32(tAl + aob[mt] + kb + 640);
                aT[mt][2] = lds32(tAl + aob[mt] + kb + 16);
                aT[mt][3] = lds32(tAl + aob[mt] + kb + 656);
            }
#pragma unroll
            for (int mt = 0; mt < 4; ++mt)
#pragma unroll
                for (int nt = 0; nt < 4; ++nt) mma16816(acc[mt][nt], aT[mt], bX[nt]);
            // hi(A) x lo(B)
#pragma unroll
            for (int nt = 0; nt < 4; ++nt){
                bX[nt][0] = lds32(tBl + bob[nt] + kb);
                bX[nt][1] = lds32(tBl + bob[nt] + kb + 16);
            }
#pragma unroll
            for (int mt = 0; mt < 4; ++mt)
#pragma unroll
                for (int nt = 0; nt < 4; ++nt) mma16816(acc[mt][nt], aH[mt], bX[nt]);
        }
        __syncthreads();
    }

    // ---- epilogue: regs -> smem stage [128][129] -> global ----
    float* stg = reinterpret_cast<float*>(dyn);
#pragma unroll
    for (int mt = 0; mt < 4; ++mt){
        const int r = wm*64 + mt*16 + quad;
#pragma unroll
        for (int nt = 0; nt < 4; ++nt){
            const int cc = wn*32 + nt*8 + lane2;
            stg[r*129 + cc]       = acc[mt][nt][0];
            stg[r*129 + cc + 1]   = acc[mt][nt][1];
            stg[(r+8)*129 + cc]   = acc[mt][nt][2];
            stg[(r+8)*129 + cc+1] = acc[mt][nt][3];
        }
    }
    __syncthreads();
    if (mode == 0){
        for (int idx = tid; idx < 16384; idx += 256){
            int r = idx >> 7, cc = idx & 127;
            oF[offO + (size_t)(m0+r)*ldo + n0 + cc] = stg[r*129 + cc] * scale;
        }
    } else if (mode == 1){
        for (int idx = tid; idx < 16384; idx += 256){
            int r = idx >> 7, cc = idx & 127;
            bf h, lo; split2(stg[r*129 + cc], h, lo);
            size_t o = offO + (size_t)(m0+r)*ldo + n0 + cc;
            oH[o] = h; oL[o] = lo;
        }
    } else {
        for (int idx = tid; idx < 16384; idx += 256){
            int cc = idx >> 7, r = idx & 127;
            bf h, lo; split2(stg[r*129 + cc], h, lo);
            size_t o = offO + (size_t)(n0+cc)*ldo + m0 + r;
            oH[o] = h; oL[o] = lo;
        }
    }
}

// ---------------- elementwise ----------------
__global__ void __launch_bounds__(256) k_split(const float* __restrict__ s, bf* __restrict__ h, bf* __restrict__ l){
    size_t i = ((size_t)blockIdx.x*256 + threadIdx.x) * 4;
    float4 v = *reinterpret_cast<const float4*>(s + i);
    bf hh, ll;
    split2(v.x, hh, ll); h[i]   = hh; l[i]   = ll;
    split2(v.y, hh, ll); h[i+1] = hh; l[i+1] = ll;
    split2(v.z, hh, ll); h[i+2] = hh; l[i+2] = ll;
    split2(v.w, hh, ll); h[i+3] = hh; l[i+3] = ll;
}
// Wout gather-block: dst[j][h*256+c] = src[j][c*4+h]
__global__ void __launch_bounds__(256) k_split_wo(const float* __restrict__ s, bf* __restrict__ h, bf* __restrict__ l){
    int idx = blockIdx.x*256 + threadIdx.x;
    int j = idx >> 10, t = idx & 1023;
    float v = s[((size_t)j<<10) + ((t & 255)<<2) + (t>>8)];
    bf hh, ll; split2(v, hh, ll);
    h[idx] = hh; l[idx] = ll;
}
__global__ void __launch_bounds__(256) k_moments(){
    const int idx = blockIdx.x;
    const float* s = g_s + (size_t)idx*65536;
    __shared__ float sh[256], sh2[256];
    float sum = 0.f, sq = 0.f;
    for (int i = threadIdx.x; i < 65536; i += 256){ float v = s[i]; sum += v; sq = fmaf(v,v,sq); }
    sh[threadIdx.x] = sum; sh2[threadIdx.x] = sq;
    __syncthreads();
    for (int o = 128; o; o >>= 1){
        if (threadIdx.x < o){ sh[threadIdx.x] += sh[threadIdx.x+o]; sh2[threadIdx.x] += sh2[threadIdx.x+o]; }
        __syncthreads();
    }
    if (threadIdx.x == 0){
        float m = sh[0]*(1.f/65536.f);
        g_mv[idx*2] = m;
        g_mv[idx*2+1] = sh2[0]*(1.f/65536.f) - m*m;
    }
}
__global__ void __launch_bounds__(256) k_softmax(){
    const int pb = blockIdx.z*16 + blockIdx.y;
    const size_t rb = ((size_t)pb*256 + blockIdx.x)*256;
    const float mean = g_mv[pb*2];
    const float inv  = rsqrtf(g_mv[pb*2+1] + EPSV);
    const int tid = threadIdx.x;
    float y = (g_s[rb + tid] - mean) * inv;
    __shared__ float red[8];
    float m = y;
#pragma unroll
    for (int o = 16; o; o >>= 1) m = fmaxf(m, __shfl_xor_sync(~0u, m, o));
    if ((tid & 31) == 0) red[tid>>5] = m;
    __syncthreads();
    if (tid == 0){ float mm = red[0]; for (int i=1;i<8;++i) mm = fmaxf(mm, red[i]); red[0] = mm; }
    __syncthreads();
    float e = expf(y - red[0]);
    __syncthreads();
    float ssum = e;
#pragma unroll
    for (int o = 16; o; o >>= 1) ssum += __shfl_xor_sync(~0u, ssum, o);
    if ((tid & 31) == 0) red[tid>>5] = ssum;
    __syncthreads();
    if (tid == 0){ float t = 0.f; for (int i=0;i<8;++i) t += red[i]; red[0] = t; }
    __syncthreads();
    bf h, lo; split2(e / red[0], h, lo);
    g_ph[rb + tid] = h; g_pl[rb + tid] = lo;
}

// ---------------- launch ----------------
static void* dsym(const void* s){ void* p = 0; cudaGetSymbolAddress(&p, s); return p; }

extern "C" void kernel_launch(void* const* d_in, const int* in_sizes, int n_in,
                              void* d_out, int out_size)
{
    const float* emb1     = (const float*)d_in[0];
    const float* emb_all  = (const float*)d_in[1];
    const float* embd1    = (const float*)d_in[2];
    const float* emb_alld = (const float*)d_in[3];
    const float* Wq = (const float*)d_in[4];  const float* Wqd = (const float*)d_in[5];
    const float* Wk = (const float*)d_in[6];  const float* Wv  = (const float*)d_in[7];
    const float* Wkd= (const float*)d_in[8];  const float* Wvd = (const float*)d_in[9];
    const float* Wo = (const float*)d_in[10]; const float* Wod = (const float*)d_in[11];
    float* out = (float*)d_out;

    cudaFuncSetAttribute(k_gemm, cudaFuncAttributeMaxDynamicSharedMemorySize, SMEM_BYTES);

#define GA(x) ((bf*)dsym(x))
    k_split<<<16384,256>>>(emb1,     GA(g_x1h), GA(g_x1l));
    k_split<<<16384,256>>>(emb_all,  GA(g_xah), GA(g_xal));
    k_split<<<16384,256>>>(embd1,    GA(g_xdh), GA(g_xdl));
    k_split<<<16384,256>>>(emb_alld, GA(g_xbh), GA(g_xbl));
    k_split<<<256,256>>>(Wq,  GA(g_wqh),  GA(g_wql));
    k_split<<<256,256>>>(Wqd, GA(g_wqdh), GA(g_wqdl));
    k_split<<<64,256>>>(Wk,  GA(g_wkh),  GA(g_wkl));
    k_split<<<64,256>>>(Wv,  GA(g_wvh),  GA(g_wvl));
    k_split<<<64,256>>>(Wkd, GA(g_wkdh), GA(g_wkdl));
    k_split<<<64,256>>>(Wvd, GA(g_wvdh), GA(g_wvdl));
    k_split_wo<<<4096,256>>>(Wo,  GA(g_woh),  GA(g_wol));
    k_split_wo<<<4096,256>>>(Wod, GA(g_wodh), GA(g_wodl));

    const long SEMB = 4194304, SQT = 1048576;
    dim3 gp(32,2,16), gs(2,2,16), gc(32,2,16), go(128,8,1);
    const int SM = SMEM_BYTES;
    // projections: Q,Qd,K,Kd transposed out (mode2); V,Vd natural (mode1)
    k_gemm<<<gp,256,SM>>>(GA(g_x1h),GA(g_x1l),SEMB,256,1024, GA(g_wqh),GA(g_wql),0,65536,256,
                          256,2,1.f, 0, GA(g_qth),GA(g_qtl), SEMB,SQT,4096);
    k_gemm<<<gp,256,SM>>>(GA(g_xdh),GA(g_xdl),SEMB,256,1024, GA(g_wqdh),GA(g_wqdl),0,65536,256,
                          256,2,1.f, 0, GA(g_qdth),GA(g_qdtl), SEMB,SQT,4096);
    k_gemm<<<gp,256,SM>>>(GA(g_xah),GA(g_xal),SEMB,256,1024, GA(g_wkh),GA(g_wkl),0,0,256,
                          256,2,1.f, 0, GA(g_kth),GA(g_ktl), SEMB,SQT,4096);
    k_gemm<<<gp,256,SM>>>(GA(g_xbh),GA(g_xbl),SEMB,256,1024, GA(g_wkdh),GA(g_wkdl),0,0,256,
                          256,2,1.f, 0, GA(g_kdth),GA(g_kdtl), SEMB,SQT,4096);
    k_gemm<<<gp,256,SM>>>(GA(g_xah),GA(g_xal),SEMB,256,1024, GA(g_wvh),GA(g_wvl),0,0,256,
                          256,1,1.f, 0, GA(g_vh),GA(g_vl), SEMB,SQT,256);
    k_gemm<<<gp,256,SM>>>(GA(g_xbh),GA(g_xbl),SEMB,256,1024, GA(g_wvdh),GA(g_wvdl),0,0,256,
                          256,1,1.f, 0, GA(g_vdh),GA(g_vdl), SEMB,SQT,256);
    // scores
    float* gs_p = (float*)dsym(g_s);
    k_gemm<<<gs,256,SM>>>(GA(g_qth),GA(g_qtl),SEMB,SQT,4096, GA(g_kdth),GA(g_kdtl),SEMB,SQT,4096,
                          4096,0,SCALEV, gs_p, 0,0, 262144,65536,256);
    k_gemm<<<gs,256,SM>>>(GA(g_qdth),GA(g_qdtl),SEMB,SQT,4096, GA(g_kth),GA(g_ktl),SEMB,SQT,4096,
                          4096,0,SCALEV, gs_p + 1048576, 0,0, 262144,65536,256);
    // inorm + softmax
    k_moments<<<32,256>>>();
    k_softmax<<<dim3(256,16,2),256>>>();
    // ctx -> blocked [b][n][h*256+c]
    k_gemm<<<gc,256,SM>>>(GA(g_vdh),GA(g_vdl),SEMB,SQT,256, GA(g_ph),GA(g_pl),262144,65536,256,
                          256,1,1.f, 0, GA(g_ch),GA(g_cl), SEMB,256,1024);
    k_gemm<<<gc,256,SM>>>(GA(g_vh),GA(g_vl),SEMB,SQT,256, GA(g_ph)+1048576,GA(g_pl)+1048576,262144,65536,256,
                          256,1,1.f, 0, GA(g_ch)+16777216,GA(g_cl)+16777216, SEMB,256,1024);
    // out projections
    k_gemm<<<go,256,SM>>>(GA(g_ch),GA(g_cl),0,0,1024, GA(g_woh),GA(g_wol),0,0,1024,
                          1024,0,1.f, out, 0,0, 0,0,1024);
    k_gemm<<<go,256,SM>>>(GA(g_ch)+16777216,GA(g_cl)+16777216,0,0,1024, GA(g_wodh),GA(g_wodl),0,0,1024,
                          1024,0,1.f, out + 16777216, 0,0, 0,0,1024);
#undef GA
}

// round 5
// speedup vs baseline: 3.2370x; 1.3736x over previous
#include <cuda_runtime.h>
#include <cuda_fp16.h>
#include <stdint.h>
#include <math.h>

typedef __half hf;

#define EPSV 1e-5f
#define SCALEV 0.03125f

// ---------------- scratch ----------------
__device__ __align__(16) hf g_qAh[33554432], g_qAl[33554432];   // [Qt; Qdt]
__device__ __align__(16) hf g_kBh[33554432], g_kBl[33554432];   // [Kdt; Kt]
__device__ __align__(16) hf g_vh[16777216],  g_vl[16777216];
__device__ __align__(16) hf g_vdh[16777216], g_vdl[16777216];
__device__ __align__(16) hf g_wqh[262144],  g_wql[262144];
__device__ __align__(16) hf g_wqdh[262144], g_wqdl[262144];
__device__ __align__(16) hf g_wkh[65536],  g_wkl[65536];
__device__ __align__(16) hf g_wvh[65536],  g_wvl[65536];
__device__ __align__(16) hf g_wkdh[65536], g_wkdl[65536];
__device__ __align__(16) hf g_wvdh[65536], g_wvdl[65536];
__device__ __align__(16) hf g_woh[1048576], g_wodh[1048576];
__device__ __align__(16) float g_sp[16777216];   // score partials [pb][sl][bh][256][256]
__device__ __align__(16) float g_s[2097152];
__device__ __align__(16) hf g_ph[2097152];
__device__ __align__(16) hf g_ch[33554432], g_cl[33554432];
__device__ float g_mv[64];

// ---------------- helpers ----------------
__device__ __forceinline__ uint32_t smem_u32(const void* p){
    uint32_t a;
    asm("{ .reg .u64 t; cvta.to.shared.u64 t, %1; cvt.u32.u64 %0, t; }" : "=r"(a) : "l"(p));
    return a;
}
__device__ __forceinline__ void cp16(uint32_t sa, const void* g){
    asm volatile("cp.async.cg.shared.global [%0], [%1], 16;" :: "r"(sa), "l"(g));
}
__device__ __forceinline__ void mma16816(float* d, const uint32_t* a, const uint32_t* b){
    asm volatile("mma.sync.aligned.m16n8k16.row.col.f32.f16.f16.f32 "
        "{%0,%1,%2,%3}, {%4,%5,%6,%7}, {%8,%9}, {%0,%1,%2,%3};"
        : "+f"(d[0]),"+f"(d[1]),"+f"(d[2]),"+f"(d[3])
        : "r"(a[0]),"r"(a[1]),"r"(a[2]),"r"(a[3]),"r"(b[0]),"r"(b[1]));
}
__device__ __forceinline__ uint32_t lds32(const char* p){ return *(const uint32_t*)p; }
__device__ __forceinline__ void split2h(float v, hf& h, hf& l){
    h = __float2half_rn(v);
    l = __float2half_rn(v - __half2float(h));
}

// shared mma inner body: tiles Ah@0 Al@10240 Bh@20480 Bl@30720, rows 80B
__device__ __forceinline__ void mma_tile(const char* tbase, const int* aob, const int* bob,
                                         float acc[4][4][4], int hasBl)
{
    const char* tA  = tbase;
    const char* tAl = tbase + 10240;
    const char* tB  = tbase + 20480;
    const char* tBl = tbase + 30720;
#pragma unroll
    for (int ks = 0; ks < 2; ++ks){
        const int kb = ks * 32;
        uint32_t aH[4][4], aT[4][4], bX[4][2];
#pragma unroll
        for (int mt = 0; mt < 4; ++mt){
            aH[mt][0] = lds32(tA + aob[mt] + kb);
            aH[mt][1] = lds32(tA + aob[mt] + kb + 640);
            aH[mt][2] = lds32(tA + aob[mt] + kb + 16);
            aH[mt][3] = lds32(tA + aob[mt] + kb + 656);
        }
#pragma unroll
        for (int nt = 0; nt < 4; ++nt){
            bX[nt][0] = lds32(tB + bob[nt] + kb);
            bX[nt][1] = lds32(tB + bob[nt] + kb + 16);
        }
#pragma unroll
        for (int mt = 0; mt < 4; ++mt)
#pragma unroll
            for (int nt = 0; nt < 4; ++nt) mma16816(acc[mt][nt], aH[mt], bX[nt]);
#pragma unroll
        for (int mt = 0; mt < 4; ++mt){
            aT[mt][0] = lds32(tAl + aob[mt] + kb);
            aT[mt][1] = lds32(tAl + aob[mt] + kb + 640);
            aT[mt][2] = lds32(tAl + aob[mt] + kb + 16);
            aT[mt][3] = lds32(tAl + aob[mt] + kb + 656);
        }
#pragma unroll
        for (int mt = 0; mt < 4; ++mt)
#pragma unroll
            for (int nt = 0; nt < 4; ++nt) mma16816(acc[mt][nt], aT[mt], bX[nt]);
        if (hasBl){
#pragma unroll
            for (int nt = 0; nt < 4; ++nt){
                bX[nt][0] = lds32(tBl + bob[nt] + kb);
                bX[nt][1] = lds32(tBl + bob[nt] + kb + 16);
            }
#pragma unroll
            for (int mt = 0; mt < 4; ++mt)
#pragma unroll
                for (int nt = 0; nt < 4; ++nt) mma16816(acc[mt][nt], aH[mt], bX[nt]);
        }
    }
}

// stage accumulators into smem [128][129] floats
__device__ __forceinline__ void stage_acc(char* dyn, float acc[4][4][4],
                                          int wm, int wn, int quad, int lane2)
{
    float* stg = reinterpret_cast<float*>(dyn);
#pragma unroll
    for (int mt = 0; mt < 4; ++mt){
        const int r = wm*64 + mt*16 + quad;
#pragma unroll
        for (int nt = 0; nt < 4; ++nt){
            const int cc = wn*32 + nt*8 + lane2;
            stg[r*129 + cc]       = acc[mt][nt][0];
            stg[r*129 + cc + 1]   = acc[mt][nt][1];
            stg[(r+8)*129 + cc]   = acc[mt][nt][2];
            stg[(r+8)*129 + cc+1] = acc[mt][nt][3];
        }
    }
}

// ---------------- generic fp16-pair GEMM ----------------
// C[m,n] = sum_k A[m,k]*B[n,k]; A hi/lo pairs; B hi (+lo if hasBl -> 3-pass).
// mode 0: fp32 -> oF ; mode 1: split hf pairs natural -> oH/oL
__global__ void __launch_bounds__(256, 1) k_gemm(
    const hf* __restrict__ Ah, const hf* __restrict__ Al,
    long sA1, long sA2, long sA3, int lda,
    const hf* __restrict__ Bh, const hf* __restrict__ Bl,
    long sB1, long sB2, long sB3, int ldb,
    int K, int zm1, int zm2, int hasBl, int mode,
    float* __restrict__ oF, hf* __restrict__ oH, hf* __restrict__ oL,
    long sO1, long sO2, long sO3, int ldo)
{
    extern __shared__ char dyn[];
    const uint32_t smb = smem_u32(dyn);
    const int bufB = 30720 + hasBl*10240;
    const int tid = threadIdx.x;
    const int l = tid & 31, wid = tid >> 5;
    const int wm = wid >> 2, wn = wid & 3;
    const int quad = l >> 2, lane2 = (l & 3) * 2;
    const int z = blockIdx.z;
    const int z1 = z / zm1, zr = z % zm1;
    const int z2 = zr / zm2, z3 = zr % zm2;
    const int m0 = blockIdx.x * 128, n0 = blockIdx.y * 128;
    const long offA = z1*sA1 + z2*sA2 + z3*sA3;
    const long offB = z1*sB1 + z2*sB2 + z3*sB3;
    const long offO = z1*sO1 + z2*sO2 + z3*sO3;

    const hf* pAh = Ah + offA + (size_t)m0*lda;
    const hf* pAl = Al + offA + (size_t)m0*lda;
    const hf* pBh = Bh + offB + (size_t)n0*ldb;
    const hf* pBl = hasBl ? (Bl + offB + (size_t)n0*ldb) : pBh;

    float acc[4][4][4];
#pragma unroll
    for (int a = 0; a < 4; ++a)
#pragma unroll
        for (int b = 0; b < 4; ++b)
#pragma unroll
            for (int c = 0; c < 4; ++c) acc[a][b][c] = 0.f;

    const int NC = K / 32;
    const int nt_tiles = 3 + hasBl;

    auto copy_chunk = [&](int c, int bufi){
        const hf* srcs[4] = {pAh + c*32, pAl + c*32, pBh + c*32, pBl + c*32};
#pragma unroll
        for (int t = 0; t < 4; ++t){
            if (t >= nt_tiles) break;
            const int ld = (t < 2) ? lda : ldb;
            const uint32_t sb = smb + bufi*bufB + t*10240;
#pragma unroll
            for (int i = 0; i < 2; ++i){
                int e = tid + i*256;
                int row = e >> 2, cc = e & 3;
                cp16(sb + row*80 + cc*16, srcs[t] + (size_t)row*ld + cc*8);
            }
        }
    };

    copy_chunk(0, 0);
    asm volatile("cp.async.commit_group;");

    int aob[4], bob[4];
#pragma unroll
    for (int mt = 0; mt < 4; ++mt) aob[mt] = (wm*64 + mt*16 + quad)*80 + lane2*2;
#pragma unroll
    for (int nt = 0; nt < 4; ++nt) bob[nt] = (wn*32 + nt*8 + quad)*80 + lane2*2;

    for (int c = 0; c < NC; ++c){
        if (c + 1 < NC){
            copy_chunk(c+1, (c+1)&1);
            asm volatile("cp.async.commit_group;");
            asm volatile("cp.async.wait_group 1;");
        } else {
            asm volatile("cp.async.wait_group 0;");
        }
        __syncthreads();
        mma_tile(dyn + (c&1)*bufB, aob, bob, acc, hasBl);
        __syncthreads();
    }

    stage_acc(dyn, acc, wm, wn, quad, lane2);
    __syncthreads();
    float* stg = reinterpret_cast<float*>(dyn);
    if (mode == 0){
        for (int idx = tid; idx < 16384; idx += 256){
            int r = idx >> 7, cc = idx & 127;
            oF[offO + (size_t)(m0+r)*ldo + n0 + cc] = stg[r*129 + cc];
        }
    } else {
        for (int idx = tid; idx < 16384; idx += 256){
            int r = idx >> 7, cc = idx & 127;
            hf h, lo; split2h(stg[r*129 + cc], h, lo);
            size_t o = offO + (size_t)(m0+r)*ldo + n0 + cc;
            oH[o] = h; oL[o] = lo;
        }
    }
}

// ---------------- projection GEMM: A fp32 (fused split), B fp16 pairs, 3-pass ----------------
// K fixed 256. mode 1: natural pairs; mode 2: transposed pairs.
__global__ void __launch_bounds__(256, 1) k_proj(
    const float* __restrict__ A, long sA2, long sA3, int lda,
    const hf* __restrict__ Bh, const hf* __restrict__ Bl, long sB3, int ldb,
    int mode,
    hf* __restrict__ oH, hf* __restrict__ oL, long sO2, long sO3, int ldo)
{
    extern __shared__ char dyn[];
    const uint32_t smb = smem_u32(dyn);
    const int tid = threadIdx.x;
    const int l = tid & 31, wid = tid >> 5;
    const int wm = wid >> 2, wn = wid & 3;
    const int quad = l >> 2, lane2 = (l & 3) * 2;
    const int z = blockIdx.z;
    const int z2 = z >> 2, z3 = z & 3;
    const int m0 = blockIdx.x * 128, n0 = blockIdx.y * 128;
    const long offA = z2*sA2 + z3*sA3;
    const long offB = z3*sB3;
    const long offO = z2*sO2 + z3*sO3;

    const float* pA = A + offA + (size_t)m0*lda;
    const hf* pBh = Bh + offB + (size_t)n0*ldb;
    const hf* pBl = Bl + offB + (size_t)n0*ldb;

    float acc[4][4][4];
#pragma unroll
    for (int a = 0; a < 4; ++a)
#pragma unroll
        for (int b = 0; b < 4; ++b)
#pragma unroll
            for (int c = 0; c < 4; ++c) acc[a][b][c] = 0.f;

    auto copyB = [&](int c, int bufi){
        const hf* srcs[2] = {pBh + c*32, pBl + c*32};
#pragma unroll
        for (int t = 0; t < 2; ++t){
            const uint32_t sb = smb + bufi*40960 + (2+t)*10240;
#pragma unroll
            for (int i = 0; i < 2; ++i){
                int e = tid + i*256;
                int row = e >> 2, cc = e & 3;
                cp16(sb + row*80 + cc*16, srcs[t] + (size_t)row*ldb + cc*8);
            }
        }
    };
    auto ldgA = [&](float4* r, int c){
        const float* base = pA + c*32;
#pragma unroll
        for (int i = 0; i < 4; ++i){
            int e = tid + 256*i;
            int row = e >> 3, cg = e & 7;
            r[i] = *reinterpret_cast<const float4*>(base + (size_t)row*lda + cg*4);
        }
    };
    auto stsA = [&](float4* r, int bufi){
        char* tA = dyn + bufi*40960;
#pragma unroll
        for (int i = 0; i < 4; ++i){
            int e = tid + 256*i;
            int row = e >> 3, cg = e & 7;
            float4 f = r[i];
            __half2 h0 = __floats2half2_rn(f.x, f.y);
            __half2 h1 = __floats2half2_rn(f.z, f.w);
            float2 c0 = __half22float2(h0), c1 = __half22float2(h1);
            __half2 l0 = __floats2half2_rn(f.x - c0.x, f.y - c0.y);
            __half2 l1 = __floats2half2_rn(f.z - c1.x, f.w - c1.y);
            char* p = tA + row*80 + cg*8;
            *reinterpret_cast<__half2*>(p)             = h0;
            *reinterpret_cast<__half2*>(p + 4)         = h1;
            *reinterpret_cast<__half2*>(p + 10240)     = l0;
            *reinterpret_cast<__half2*>(p + 10244)     = l1;
        }
    };

    int aob[4], bob[4];
#pragma unroll
    for (int mt = 0; mt < 4; ++mt) aob[mt] = (wm*64 + mt*16 + quad)*80 + lane2*2;
#pragma unroll
    for (int nt = 0; nt < 4; ++nt) bob[nt] = (wn*32 + nt*8 + quad)*80 + lane2*2;

    float4 rA[4], rA2[4];
    ldgA(rA, 0);
    copyB(0, 0);
    asm volatile("cp.async.commit_group;");

    const int NC = 8;  // K=256
    for (int c = 0; c < NC; ++c){
        stsA(rA, c & 1);
        if (c + 1 < NC){
            ldgA(rA2, c+1);
            copyB(c+1, (c+1)&1);
            asm volatile("cp.async.commit_group;");
            asm volatile("cp.async.wait_group 1;");
        } else {
            asm volatile("cp.async.wait_group 0;");
        }
        __syncthreads();
        mma_tile(dyn + (c&1)*40960, aob, bob, acc, 1);
        __syncthreads();
#pragma unroll
        for (int i = 0; i < 4; ++i) rA[i] = rA2[i];
    }

    stage_acc(dyn, acc, wm, wn, quad, lane2);
    __syncthreads();
    float* stg = reinterpret_cast<float*>(dyn);
    if (mode == 1){
        for (int idx = tid; idx < 16384; idx += 256){
            int r = idx >> 7, cc = idx & 127;
            hf h, lo; split2h(stg[r*129 + cc], h, lo);
            size_t o = offO + (size_t)(m0+r)*ldo + n0 + cc;
            oH[o] = h; oL[o] = lo;
        }
    } else {
        for (int idx = tid; idx < 16384; idx += 256){
            int cc = idx >> 7, r = idx & 127;
            hf h, lo; split2h(stg[r*129 + cc], h, lo);
            size_t o = offO + (size_t)(n0+cc)*ldo + m0 + r;
            oH[o] = h; oL[o] = lo;
        }
    }
}

// ---------------- elementwise ----------------
__global__ void __launch_bounds__(256) k_splitW(const float* __restrict__ s,
                                               hf* __restrict__ h, hf* __restrict__ l){
    size_t i = ((size_t)blockIdx.x*256 + threadIdx.x) * 4;
    float4 v = *reinterpret_cast<const float4*>(s + i);
    hf hh, ll;
    split2h(v.x, hh, ll); h[i]   = hh; l[i]   = ll;
    split2h(v.y, hh, ll); h[i+1] = hh; l[i+1] = ll;
    split2h(v.z, hh, ll); h[i+2] = hh; l[i+2] = ll;
    split2h(v.w, hh, ll); h[i+3] = hh; l[i+3] = ll;
}
__global__ void __launch_bounds__(256) k_splitWo(const float* __restrict__ s, hf* __restrict__ h){
    int idx = blockIdx.x*256 + threadIdx.x;
    int j = idx >> 10, t = idx & 1023;
    h[idx] = __float2half_rn(s[((size_t)j<<10) + ((t & 255)<<2) + (t>>8)]);
}
__global__ void __launch_bounds__(256) k_reduce(){
    int idx = blockIdx.x*256 + threadIdx.x;          // 0..2097151
    int pb = idx >> 20, r = idx & 1048575;
    const float* p = g_sp + (size_t)pb*8388608 + r;
    float s = 0.f;
#pragma unroll
    for (int sl = 0; sl < 8; ++sl) s += p[(size_t)sl*1048576];
    g_s[idx] = s * SCALEV;
}
__global__ void __launch_bounds__(256) k_moments(){
    const int idx = blockIdx.x;
    const float* s = g_s + (size_t)idx*65536;
    __shared__ float sh[256], sh2[256];
    float sum = 0.f, sq = 0.f;
    for (int i = threadIdx.x; i < 65536; i += 256){ float v = s[i]; sum += v; sq = fmaf(v,v,sq); }
    sh[threadIdx.x] = sum; sh2[threadIdx.x] = sq;
    __syncthreads();
    for (int o = 128; o; o >>= 1){
        if (threadIdx.x < o){ sh[threadIdx.x] += sh[threadIdx.x+o]; sh2[threadIdx.x] += sh2[threadIdx.x+o]; }
        __syncthreads();
    }
    if (threadIdx.x == 0){
        float m = sh[0]*(1.f/65536.f);
        g_mv[idx*2] = m;
        g_mv[idx*2+1] = sh2[0]*(1.f/65536.f) - m*m;
    }
}
__global__ void __launch_bounds__(256) k_softmax(){
    const int pb = blockIdx.z*16 + blockIdx.y;
    const size_t rb = ((size_t)pb*256 + blockIdx.x)*256;
    const float mean = g_mv[pb*2];
    const float inv  = rsqrtf(g_mv[pb*2+1] + EPSV);
    const int tid = threadIdx.x;
    float y = (g_s[rb + tid] - mean) * inv;
    __shared__ float red[8];
    float m = y;
#pragma unroll
    for (int o = 16; o; o >>= 1) m = fmaxf(m, __shfl_xor_sync(~0u, m, o));
    if ((tid & 31) == 0) red[tid>>5] = m;
    __syncthreads();
    if (tid == 0){ float mm = red[0]; for (int i=1;i<8;++i) mm = fmaxf(mm, red[i]); red[0] = mm; }
    __syncthreads();
    float e = expf(y - red[0]);
    __syncthreads();
    float ssum = e;
#pragma unroll
    for (int o = 16; o; o >>= 1) ssum += __shfl_xor_sync(~0u, ssum, o);
    if ((tid & 31) == 0) red[tid>>5] = ssum;
    __syncthreads();
    if (tid == 0){ float t = 0.f; for (int i=0;i<8;++i) t += red[i]; red[0] = t; }
    __syncthreads();
    g_ph[rb + tid] = __float2half_rn(e / red[0]);
}

// ---------------- launch ----------------
static void* dsym(const void* s){ void* p = 0; cudaGetSymbolAddress(&p, s); return p; }

extern "C" void kernel_launch(void* const* d_in, const int* in_sizes, int n_in,
                              void* d_out, int out_size)
{
    const float* emb1     = (const float*)d_in[0];
    const float* emb_all  = (const float*)d_in[1];
    const float* embd1    = (const float*)d_in[2];
    const float* emb_alld = (const float*)d_in[3];
    const float* Wq = (const float*)d_in[4];  const float* Wqd = (const float*)d_in[5];
    const float* Wk = (const float*)d_in[6];  const float* Wv  = (const float*)d_in[7];
    const float* Wkd= (const float*)d_in[8];  const float* Wvd = (const float*)d_in[9];
    const float* Wo = (const float*)d_in[10]; const float* Wod = (const float*)d_in[11];
    float* out = (float*)d_out;

    cudaFuncSetAttribute(k_gemm, cudaFuncAttributeMaxDynamicSharedMemorySize, 81920);
    cudaFuncSetAttribute(k_proj, cudaFuncAttributeMaxDynamicSharedMemorySize, 81920);

#define GH(x) ((hf*)dsym(x))
    hf *qAh = GH(g_qAh), *qAl = GH(g_qAl);
    hf *kBh = GH(g_kBh), *kBl = GH(g_kBl);
    hf *vh = GH(g_vh), *vl = GH(g_vl), *vdh = GH(g_vdh), *vdl = GH(g_vdl);
    hf *ch = GH(g_ch), *cl = GH(g_cl), *ph = GH(g_ph);
    float* sp = (float*)dsym(g_sp);

    // weight splits
    k_splitW<<<256,256>>>(Wq,  GH(g_wqh),  GH(g_wql));
    k_splitW<<<256,256>>>(Wqd, GH(g_wqdh), GH(g_wqdl));
    k_splitW<<<64,256>>>(Wk,  GH(g_wkh),  GH(g_wkl));
    k_splitW<<<64,256>>>(Wv,  GH(g_wvh),  GH(g_wvl));
    k_splitW<<<64,256>>>(Wkd, GH(g_wkdh), GH(g_wkdl));
    k_splitW<<<64,256>>>(Wvd, GH(g_wvdh), GH(g_wvdl));
    k_splitWo<<<4096,256>>>(Wo,  GH(g_woh));
    k_splitWo<<<4096,256>>>(Wod, GH(g_wodh));

    // projections (fused fp32-A split), grid (32,2,16)
    dim3 gp(32,2,16);
    // Q -> Qt (path0 A slot), Qd -> +16M; Kd -> kB slot0, K -> slot1 (score pairing)
    k_proj<<<gp,256,81920>>>(emb1,     4194304,256,1024, GH(g_wqh), GH(g_wql), 65536,256, 2, qAh,           qAl,           4194304,1048576, 4096);
    k_proj<<<gp,256,81920>>>(embd1,    4194304,256,1024, GH(g_wqdh),GH(g_wqdl),65536,256, 2, qAh+16777216,  qAl+16777216,  4194304,1048576, 4096);
    k_proj<<<gp,256,81920>>>(emb_alld, 4194304,256,1024, GH(g_wkdh),GH(g_wkdl),0,    256, 2, kBh,           kBl,           4194304,1048576, 4096);
    k_proj<<<gp,256,81920>>>(emb_all,  4194304,256,1024, GH(g_wkh), GH(g_wkl), 0,    256, 2, kBh+16777216,  kBl+16777216,  4194304,1048576, 4096);
    k_proj<<<gp,256,81920>>>(emb_all,  4194304,256,1024, GH(g_wvh), GH(g_wvl), 0,    256, 1, vh,            vl,            4194304,1048576, 256);
    k_proj<<<gp,256,81920>>>(emb_alld, 4194304,256,1024, GH(g_wvdh),GH(g_wvdl),0,    256, 1, vdh,           vdl,           4194304,1048576, 256);

    // scores: one launch, split-K x8, 3-pass, fp32 partials
    dim3 gsc(2,2,256);
    k_gemm<<<gsc,256,81920>>>(qAh,qAl, 16777216,1048576,512, 4096,
                              kBh,kBl, 16777216,1048576,512, 4096,
                              512, 128,8, 1, 0,
                              sp, 0,0, 8388608,65536,1048576, 256);
    k_reduce<<<8192,256>>>();
    k_moments<<<32,256>>>();
    k_softmax<<<dim3(256,16,2),256>>>();

    // ctx: 2-pass (B = probs hi only), grid (32,2,16)
    dim3 gc(32,2,16);
    k_gemm<<<gc,256,66048>>>(vdh,vdl, 0,4194304,1048576, 256,
                             ph, (hf*)0, 0,262144,65536, 256,
                             256, 64,4, 0, 1,
                             (float*)0, ch, cl, 0,4194304,256, 1024);
    k_gemm<<<gc,256,66048>>>(vh,vl, 0,4194304,1048576, 256,
                             ph+1048576, (hf*)0, 0,262144,65536, 256,
                             256, 64,4, 0, 1,
                             (float*)0, ch+16777216, cl+16777216, 0,4194304,256, 1024);

    // out projections: 2-pass (B = Wout hi only), grid (128,8)
    dim3 go(128,8,1);
    k_gemm<<<go,256,66048>>>(ch,cl, 0,0,0, 1024,
                             GH(g_woh), (hf*)0, 0,0,0, 1024,
                             1024, 64,4, 0, 0,
                             out, (hf*)0,(hf*)0, 0,0,0, 1024);
    k_gemm<<<go,256,66048>>>(ch+16777216,cl+16777216, 0,0,0, 1024,
                             GH(g_wodh), (hf*)0, 0,0,0, 1024,
                             1024, 64,4, 0, 0,
                             out+16777216, (hf*)0,(hf*)0, 0,0,0, 1024);
#undef GH
}

// round 8
// speedup vs baseline: 4.5929x; 1.4189x over previous
#include <cuda_runtime.h>
#include <cuda_fp16.h>
#include <stdint.h>
#include <math.h>

typedef __half hf;

#define EPSV 1e-5f
#define SCALEV 0.03125f

// ---------------- scratch ----------------
__device__ __align__(16) hf g_qAh[33554432], g_qAl[33554432];  // Qt pairs [path][bh][c][n]
__device__ __align__(16) hf g_kBh[33554432];                   // [Kdt; Kt] hi
__device__ __align__(16) hf g_vAh[33554432];                   // [Vd; V] hi [bh][n][k]
__device__ __align__(16) hf g_wqh[262144], g_wqdh[262144];
__device__ __align__(16) hf g_wkh[65536], g_wvh[65536], g_wkdh[65536], g_wvdh[65536];
__device__ __align__(16) hf g_woh[2097152];                    // blocked, both paths
__device__ __align__(16) float g_sp[16777216];                 // score partials
__device__ __align__(16) float g_s[2097152];
__device__ __align__(16) hf g_ph[2097152];
__device__ __align__(16) hf g_ch[33554432];                    // ctx fp16 blocked, both paths
__device__ float g_mv[64];

// ---------------- helpers ----------------
__device__ __forceinline__ uint32_t smem_u32(const void* p){
    uint32_t a;
    asm("{ .reg .u64 t; cvta.to.shared.u64 t, %1; cvt.u32.u64 %0, t; }" : "=r"(a) : "l"(p));
    return a;
}
__device__ __forceinline__ void cp16(uint32_t sa, const void* g){
    asm volatile("cp.async.cg.shared.global [%0], [%1], 16;" :: "r"(sa), "l"(g));
}
__device__ __forceinline__ void mma16816(float* d, const uint32_t* a, const uint32_t* b){
    asm volatile("mma.sync.aligned.m16n8k16.row.col.f32.f16.f16.f32 "
        "{%0,%1,%2,%3}, {%4,%5,%6,%7}, {%8,%9}, {%0,%1,%2,%3};"
        : "+f"(d[0]),"+f"(d[1]),"+f"(d[2]),"+f"(d[3])
        : "r"(a[0]),"r"(a[1]),"r"(a[2]),"r"(a[3]),"r"(b[0]),"r"(b[1]));
}
__device__ __forceinline__ uint32_t lds32(const char* p){ return *(const uint32_t*)p; }
__device__ __forceinline__ void split2h(float v, hf& h, hf& l){
    h = __float2half_rn(v);
    l = __float2half_rn(v - __half2float(h));
}

// inner mma over one 32-K chunk. slots: A@0 [, Al@10240], B@(1+HASAL)*10240
template<int HASAL>
__device__ __forceinline__ void mma_tile(const char* tbase, const int* aob, const int* bob,
                                         float acc[4][4][4])
{
    const char* tA  = tbase;
    const char* tAl = tbase + 10240;
    const char* tB  = tbase + (1+HASAL)*10240;
#pragma unroll
    for (int ks = 0; ks < 2; ++ks){
        const int kb = ks * 32;
        uint32_t aH[4][4], bX[4][2];
#pragma unroll
        for (int mt = 0; mt < 4; ++mt){
            aH[mt][0] = lds32(tA + aob[mt] + kb);
            aH[mt][1] = lds32(tA + aob[mt] + kb + 640);
            aH[mt][2] = lds32(tA + aob[mt] + kb + 16);
            aH[mt][3] = lds32(tA + aob[mt] + kb + 656);
        }
#pragma unroll
        for (int nt = 0; nt < 4; ++nt){
            bX[nt][0] = lds32(tB + bob[nt] + kb);
            bX[nt][1] = lds32(tB + bob[nt] + kb + 16);
        }
#pragma unroll
        for (int mt = 0; mt < 4; ++mt)
#pragma unroll
            for (int nt = 0; nt < 4; ++nt) mma16816(acc[mt][nt], aH[mt], bX[nt]);
        if (HASAL){
            uint32_t aT[4][4];
#pragma unroll
            for (int mt = 0; mt < 4; ++mt){
                aT[mt][0] = lds32(tAl + aob[mt] + kb);
                aT[mt][1] = lds32(tAl + aob[mt] + kb + 640);
                aT[mt][2] = lds32(tAl + aob[mt] + kb + 16);
                aT[mt][3] = lds32(tAl + aob[mt] + kb + 656);
            }
#pragma unroll
            for (int mt = 0; mt < 4; ++mt)
#pragma unroll
                for (int nt = 0; nt < 4; ++nt) mma16816(acc[mt][nt], aT[mt], bX[nt]);
        }
    }
}

__device__ __forceinline__ void stage_acc(char* dyn, float acc[4][4][4],
                                          int wm, int wn, int quad, int lane2)
{
    float* stg = reinterpret_cast<float*>(dyn);
#pragma unroll
    for (int mt = 0; mt < 4; ++mt){
        const int r = wm*64 + mt*16 + quad;
#pragma unroll
        for (int nt = 0; nt < 4; ++nt){
            const int cc = wn*32 + nt*8 + lane2;
            stg[r*129 + cc]       = acc[mt][nt][0];
            stg[r*129 + cc + 1]   = acc[mt][nt][1];
            stg[(r+8)*129 + cc]   = acc[mt][nt][2];
            stg[(r+8)*129 + cc+1] = acc[mt][nt][3];
        }
    }
}

// ---------------- generic GEMM: C[m,n] = sum_k A[m,k]*B[n,k] ----------------
// HASAL: add Al*Bh pass. mode 0: fp32 -> oF ; mode 1: fp16 hi -> oH
template<int HASAL>
__global__ void __launch_bounds__(256, 1) k_gemm(
    const hf* __restrict__ Ah, const hf* __restrict__ Al,
    long sA1, long sA2, long sA3, int lda,
    const hf* __restrict__ Bh, long sB1, long sB2, long sB3, int ldb,
    int K, int zm1, int zm2, int mode,
    float* __restrict__ oF, hf* __restrict__ oH,
    long sO1, long sO2, long sO3, int ldo)
{
    extern __shared__ char dyn[];
    const uint32_t smb = smem_u32(dyn);
    const int bufB = (2+HASAL)*10240;
    const int tid = threadIdx.x;
    const int l = tid & 31, wid = tid >> 5;
    const int wm = wid >> 2, wn = wid & 3;
    const int quad = l >> 2, lane2 = (l & 3) * 2;
    const int z = blockIdx.z;
    const int z1 = z / zm1, zr = z % zm1;
    const int z2 = zr / zm2, z3 = zr % zm2;
    const int m0 = blockIdx.x * 128, n0 = blockIdx.y * 128;
    const long offA = z1*sA1 + z2*sA2 + z3*sA3;
    const long offB = z1*sB1 + z2*sB2 + z3*sB3;
    const long offO = z1*sO1 + z2*sO2 + z3*sO3;

    const hf* pAh = Ah + offA + (size_t)m0*lda;
    const hf* pAl = HASAL ? (Al + offA + (size_t)m0*lda) : pAh;
    const hf* pBh = Bh + offB + (size_t)n0*ldb;

    float acc[4][4][4];
#pragma unroll
    for (int a = 0; a < 4; ++a)
#pragma unroll
        for (int b = 0; b < 4; ++b)
#pragma unroll
            for (int c = 0; c < 4; ++c) acc[a][b][c] = 0.f;

    const int NC = K / 32;

    auto copy_chunk = [&](int c, int bufi){
        const hf* srcs[3];
        int lds[3];
        int nt = 0;
        srcs[nt] = pAh + c*32; lds[nt] = lda; nt++;
        if (HASAL){ srcs[nt] = pAl + c*32; lds[nt] = lda; nt++; }
        srcs[nt] = pBh + c*32; lds[nt] = ldb; nt++;
#pragma unroll
        for (int t = 0; t < 2+HASAL; ++t){
            const uint32_t sb = smb + bufi*bufB + t*10240;
#pragma unroll
            for (int i = 0; i < 2; ++i){
                int e = tid + i*256;
                int row = e >> 2, cc = e & 3;
                cp16(sb + row*80 + cc*16, srcs[t] + (size_t)row*lds[t] + cc*8);
            }
        }
    };

    copy_chunk(0, 0);
    asm volatile("cp.async.commit_group;");

    int aob[4], bob[4];
#pragma unroll
    for (int mt = 0; mt < 4; ++mt) aob[mt] = (wm*64 + mt*16 + quad)*80 + lane2*2;
#pragma unroll
    for (int nt = 0; nt < 4; ++nt) bob[nt] = (wn*32 + nt*8 + quad)*80 + lane2*2;

    for (int c = 0; c < NC; ++c){
        if (c + 1 < NC){
            copy_chunk(c+1, (c+1)&1);
            asm volatile("cp.async.commit_group;");
            asm volatile("cp.async.wait_group 1;");
        } else {
            asm volatile("cp.async.wait_group 0;");
        }
        __syncthreads();
        mma_tile<HASAL>(dyn + (c&1)*bufB, aob, bob, acc);
        __syncthreads();
    }

    stage_acc(dyn, acc, wm, wn, quad, lane2);
    __syncthreads();
    float* stg = reinterpret_cast<float*>(dyn);
    if (mode == 0){
        for (int idx = tid; idx < 16384; idx += 256){
            int r = idx >> 7, cc = idx & 127;
            oF[offO + (size_t)(m0+r)*ldo + n0 + cc] = stg[r*129 + cc];
        }
    } else {
        for (int idx = tid; idx < 16384; idx += 256){
            int r = idx >> 7, cc = idx & 127;
            oH[offO + (size_t)(m0+r)*ldo + n0 + cc] = __float2half_rn(stg[r*129 + cc]);
        }
    }
}

// ---------------- projection GEMM: A fp32 fused-split (exact), B = W hi, 2-pass ----------------
// K fixed 256. mode 1: natural hi; mode 2: transposed pairs; mode 3: transposed hi.
__global__ void __launch_bounds__(256, 1) k_proj(
    const float* __restrict__ A, long sA2, long sA3, int lda,
    const hf* __restrict__ Bh, long sB3, int ldb,
    int mode,
    hf* __restrict__ oH, hf* __restrict__ oL, long sO2, long sO3, int ldo)
{
    extern __shared__ char dyn[];
    const uint32_t smb = smem_u32(dyn);
    const int tid = threadIdx.x;
    const int l = tid & 31, wid = tid >> 5;
    const int wm = wid >> 2, wn = wid & 3;
    const int quad = l >> 2, lane2 = (l & 3) * 2;
    const int z = blockIdx.z;
    const int z2 = z >> 2, z3 = z & 3;
    const int m0 = blockIdx.x * 128, n0 = blockIdx.y * 128;
    const long offA = z2*sA2 + z3*sA3;
    const long offO = z2*sO2 + z3*sO3;

    const float* pA = A + offA + (size_t)m0*lda;
    const hf* pBh = Bh + z3*sB3 + (size_t)n0*ldb;

    float acc[4][4][4];
#pragma unroll
    for (int a = 0; a < 4; ++a)
#pragma unroll
        for (int b = 0; b < 4; ++b)
#pragma unroll
            for (int c = 0; c < 4; ++c) acc[a][b][c] = 0.f;

    auto copyB = [&](int c, int bufi){
        const uint32_t sb = smb + bufi*30720 + 20480;
#pragma unroll
        for (int i = 0; i < 2; ++i){
            int e = tid + i*256;
            int row = e >> 2, cc = e & 3;
            cp16(sb + row*80 + cc*16, pBh + c*32 + (size_t)row*ldb + cc*8);
        }
    };
    auto ldgA = [&](float4* r, int c){
        const float* base = pA + c*32;
#pragma unroll
        for (int i = 0; i < 4; ++i){
            int e = tid + 256*i;
            int row = e >> 3, cg = e & 7;
            r[i] = *reinterpret_cast<const float4*>(base + (size_t)row*lda + cg*4);
        }
    };
    auto stsA = [&](float4* r, int bufi){
        char* tA = dyn + bufi*30720;
#pragma unroll
        for (int i = 0; i < 4; ++i){
            int e = tid + 256*i;
            int row = e >> 3, cg = e & 7;
            float4 f = r[i];
            __half2 h0 = __floats2half2_rn(f.x, f.y);
            __half2 h1 = __floats2half2_rn(f.z, f.w);
            float2 c0 = __half22float2(h0), c1 = __half22float2(h1);
            __half2 l0 = __floats2half2_rn(f.x - c0.x, f.y - c0.y);
            __half2 l1 = __floats2half2_rn(f.z - c1.x, f.w - c1.y);
            char* p = tA + row*80 + cg*8;
            *reinterpret_cast<__half2*>(p)         = h0;
            *reinterpret_cast<__half2*>(p + 4)     = h1;
            *reinterpret_cast<__half2*>(p + 10240) = l0;
            *reinterpret_cast<__half2*>(p + 10244) = l1;
        }
    };

    int aob[4], bob[4];
#pragma unroll
    for (int mt = 0; mt < 4; ++mt) aob[mt] = (wm*64 + mt*16 + quad)*80 + lane2*2;
#pragma unroll
    for (int nt = 0; nt < 4; ++nt) bob[nt] = (wn*32 + nt*8 + quad)*80 + lane2*2;

    float4 rA[4], rA2[4];
    ldgA(rA, 0);
    copyB(0, 0);
    asm volatile("cp.async.commit_group;");

    const int NC = 8;
    for (int c = 0; c < NC; ++c){
        stsA(rA, c & 1);
        if (c + 1 < NC){
            ldgA(rA2, c+1);
            copyB(c+1, (c+1)&1);
            asm volatile("cp.async.commit_group;");
            asm volatile("cp.async.wait_group 1;");
        } else {
            asm volatile("cp.async.wait_group 0;");
        }
        __syncthreads();
        mma_tile<1>(dyn + (c&1)*30720, aob, bob, acc);
        __syncthreads();
#pragma unroll
        for (int i = 0; i < 4; ++i) rA[i] = rA2[i];
    }

    stage_acc(dyn, acc, wm, wn, quad, lane2);
    __syncthreads();
    float* stg = reinterpret_cast<float*>(dyn);
    if (mode == 1){
        for (int idx = tid; idx < 16384; idx += 256){
            int r = idx >> 7, cc = idx & 127;
            oH[offO + (size_t)(m0+r)*ldo + n0 + cc] = __float2half_rn(stg[r*129 + cc]);
        }
    } else if (mode == 2){
        for (int idx = tid; idx < 16384; idx += 256){
            int cc = idx >> 7, r = idx & 127;
            hf h, lo; split2h(stg[r*129 + cc], h, lo);
            size_t o = offO + (size_t)(n0+cc)*ldo + m0 + r;
            oH[o] = h; oL[o] = lo;
        }
    } else {
        for (int idx = tid; idx < 16384; idx += 256){
            int cc = idx >> 7, r = idx & 127;
            oH[offO + (size_t)(n0+cc)*ldo + m0 + r] = __float2half_rn(stg[r*129 + cc]);
        }
    }
}

// ---------------- elementwise ----------------
__global__ void __launch_bounds__(256) k_splitWh(const float* __restrict__ s, hf* __restrict__ h){
    size_t i = ((size_t)blockIdx.x*256 + threadIdx.x) * 4;
    float4 v = *reinterpret_cast<const float4*>(s + i);
    h[i]   = __float2half_rn(v.x);
    h[i+1] = __float2half_rn(v.y);
    h[i+2] = __float2half_rn(v.z);
    h[i+3] = __float2half_rn(v.w);
}
__global__ void __launch_bounds__(256) k_splitWo(const float* __restrict__ s, hf* __restrict__ h){
    int idx = blockIdx.x*256 + threadIdx.x;
    int j = idx >> 10, t = idx & 1023;
    h[idx] = __float2half_rn(s[((size_t)j<<10) + ((t & 255)<<2) + (t>>8)]);
}
__global__ void __launch_bounds__(256) k_reduce(){
    int idx = blockIdx.x*256 + threadIdx.x;
    int pb = idx >> 20, r = idx & 1048575;
    const float* p = g_sp + (size_t)pb*8388608 + r;
    float s = 0.f;
#pragma unroll
    for (int sl = 0; sl < 8; ++sl) s += p[(size_t)sl*1048576];
    g_s[idx] = s * SCALEV;
}
__global__ void __launch_bounds__(256) k_moments(){
    const int idx = blockIdx.x;
    const float* s = g_s + (size_t)idx*65536;
    __shared__ float sh[256], sh2[256];
    float sum = 0.f, sq = 0.f;
    for (int i = threadIdx.x; i < 65536; i += 256){ float v = s[i]; sum += v; sq = fmaf(v,v,sq); }
    sh[threadIdx.x] = sum; sh2[threadIdx.x] = sq;
    __syncthreads();
    for (int o = 128; o; o >>= 1){
        if (threadIdx.x < o){ sh[threadIdx.x] += sh[threadIdx.x+o]; sh2[threadIdx.x] += sh2[threadIdx.x+o]; }
        __syncthreads();
    }
    if (threadIdx.x == 0){
        float m = sh[0]*(1.f/65536.f);
        g_mv[idx*2] = m;
        g_mv[idx*2+1] = sh2[0]*(1.f/65536.f) - m*m;
    }
}
__global__ void __launch_bounds__(256) k_softmax(){
    const int pb = blockIdx.z*16 + blockIdx.y;
    const size_t rb = ((size_t)pb*256 + blockIdx.x)*256;
    const float mean = g_mv[pb*2];
    const float inv  = rsqrtf(g_mv[pb*2+1] + EPSV);
    const int tid = threadIdx.x;
    float y = (g_s[rb + tid] - mean) * inv;
    __shared__ float red[8];
    float m = y;
#pragma unroll
    for (int o = 16; o; o >>= 1) m = fmaxf(m, __shfl_xor_sync(~0u, m, o));
    if ((tid & 31) == 0) red[tid>>5] = m;
    __syncthreads();
    if (tid == 0){ float mm = red[0]; for (int i=1;i<8;++i) mm = fmaxf(mm, red[i]); red[0] = mm; }
    __syncthreads();
    float e = expf(y - red[0]);
    __syncthreads();
    float ssum = e;
#pragma unroll
    for (int o = 16; o; o >>= 1) ssum += __shfl_xor_sync(~0u, ssum, o);
    if ((tid & 31) == 0) red[tid>>5] = ssum;
    __syncthreads();
    if (tid == 0){ float t = 0.f; for (int i=0;i<8;++i) t += red[i]; red[0] = t; }
    __syncthreads();
    g_ph[rb + tid] = __float2half_rn(e / red[0]);
}

// ---------------- launch ----------------
static void* dsym(const void* s){ void* p = 0; cudaGetSymbolAddress(&p, s); return p; }

extern "C" void kernel_launch(void* const* d_in, const int* in_sizes, int n_in,
                              void* d_out, int out_size)
{
    const float* emb1     = (const float*)d_in[0];
    const float* emb_all  = (const float*)d_in[1];
    const float* embd1    = (const float*)d_in[2];
    const float* emb_alld = (const float*)d_in[3];
    const float* Wq = (const float*)d_in[4];  const float* Wqd = (const float*)d_in[5];
    const float* Wk = (const float*)d_in[6];  const float* Wv  = (const float*)d_in[7];
    const float* Wkd= (const float*)d_in[8];  const float* Wvd = (const float*)d_in[9];
    const float* Wo = (const float*)d_in[10]; const float* Wod = (const float*)d_in[11];
    float* out = (float*)d_out;

    const int SM = 66048;
    cudaFuncSetAttribute(k_gemm<1>, cudaFuncAttributeMaxDynamicSharedMemorySize, SM);
    cudaFuncSetAttribute(k_gemm<0>, cudaFuncAttributeMaxDynamicSharedMemorySize, SM);
    cudaFuncSetAttribute(k_proj,    cudaFuncAttributeMaxDynamicSharedMemorySize, SM);

#define GH(x) ((hf*)dsym(x))
    hf *qAh = GH(g_qAh), *qAl = GH(g_qAl);
    hf *kBh = GH(g_kBh), *vAh = GH(g_vAh);
    hf *ch = GH(g_ch), *ph = GH(g_ph), *woh = GH(g_woh);
    float* sp = (float*)dsym(g_sp);

    // weight conversions (hi only)
    k_splitWh<<<256,256>>>(Wq,  GH(g_wqh));
    k_splitWh<<<256,256>>>(Wqd, GH(g_wqdh));
    k_splitWh<<<64,256>>>(Wk,  GH(g_wkh));
    k_splitWh<<<64,256>>>(Wv,  GH(g_wvh));
    k_splitWh<<<64,256>>>(Wkd, GH(g_wkdh));
    k_splitWh<<<64,256>>>(Wvd, GH(g_wvdh));
    k_splitWo<<<4096,256>>>(Wo,  woh);
    k_splitWo<<<4096,256>>>(Wod, woh + 1048576);

    // projections: 2-pass (exact emb split x W-hi)
    dim3 gp(32,2,16);
    k_proj<<<gp,256,SM>>>(emb1,     4194304,256,1024, GH(g_wqh),  65536,256, 2, qAh,          qAl,          4194304,1048576, 4096);
    k_proj<<<gp,256,SM>>>(embd1,    4194304,256,1024, GH(g_wqdh), 65536,256, 2, qAh+16777216, qAl+16777216, 4194304,1048576, 4096);
    k_proj<<<gp,256,SM>>>(emb_alld, 4194304,256,1024, GH(g_wkdh), 0,    256, 3, kBh,          (hf*)0,       4194304,1048576, 4096);
    k_proj<<<gp,256,SM>>>(emb_all,  4194304,256,1024, GH(g_wkh),  0,    256, 3, kBh+16777216, (hf*)0,       4194304,1048576, 4096);
    k_proj<<<gp,256,SM>>>(emb_alld, 4194304,256,1024, GH(g_wvdh), 0,    256, 1, vAh,          (hf*)0,       4194304,1048576, 256);
    k_proj<<<gp,256,SM>>>(emb_all,  4194304,256,1024, GH(g_wvh),  0,    256, 1, vAh+16777216, (hf*)0,       4194304,1048576, 256);

    // scores: 2-pass (Q pairs x K hi), split-K x8, one launch
    dim3 gsc(2,2,256);
    k_gemm<1><<<gsc,256,SM>>>(qAh,qAl, 16777216,1048576,512, 4096,
                              kBh, 16777216,1048576,512, 4096,
                              512, 128,8, 0,
                              sp, (hf*)0, 8388608,65536,1048576, 256);
    k_reduce<<<8192,256>>>();
    k_moments<<<32,256>>>();
    k_softmax<<<dim3(256,16,2),256>>>();

    // ctx: 1-pass (V hi x probs hi), both paths in one launch
    dim3 gc(32,2,32);
    k_gemm<0><<<gc,256,SM>>>(vAh,(hf*)0, 16777216,4194304,1048576, 256,
                             ph, 1048576,262144,65536, 256,
                             256, 16,4, 1,
                             (float*)0, ch, 16777216,4194304,256, 1024);

    // out: 1-pass (ctx hi x Wo hi), both paths in one launch
    dim3 go(128,8,2);
    k_gemm<0><<<go,256,SM>>>(ch,(hf*)0, 16777216,0,0, 1024,
                             woh, 1048576,0,0, 1024,
                             1024, 1,1, 0,
                             out, (hf*)0, 16777216,0,0, 1024);
#undef GH
}

// round 9
// speedup vs baseline: 5.0543x; 1.1005x over previous
#include <cuda_runtime.h>
#include <cuda_fp16.h>
#include <stdint.h>
#include <math.h>

typedef __half hf;

#define EPSV 1e-5f
#define SCALEV 0.03125f

// ---------------- scratch ----------------
__device__ __align__(16) hf g_qAh[33554432], g_qAl[33554432];  // Qt pairs [path][bh][c][n]
__device__ __align__(16) hf g_kBh[33554432];                   // [Kdt; Kt] hi
__device__ __align__(16) hf g_vAh[33554432];                   // [Vd; V] hi [bh][n][k]
__device__ __align__(16) hf g_wqh[262144], g_wqdh[262144];
__device__ __align__(16) hf g_wkh[65536], g_wvh[65536], g_wkdh[65536], g_wvdh[65536];
__device__ __align__(16) hf g_woh[2097152];                    // blocked, both paths
__device__ __align__(16) float g_sp[16777216];                 // score partials
__device__ __align__(16) float g_s[2097152];
__device__ __align__(16) hf g_ph[2097152];
__device__ __align__(16) hf g_ch[33554432];                    // ctx fp16 blocked, both paths
__device__ float g_mv[64];

// ---------------- helpers ----------------
__device__ __forceinline__ uint32_t smem_u32(const void* p){
    uint32_t a;
    asm("{ .reg .u64 t; cvta.to.shared.u64 t, %1; cvt.u32.u64 %0, t; }" : "=r"(a) : "l"(p));
    return a;
}
__device__ __forceinline__ void cp16(uint32_t sa, const void* g){
    asm volatile("cp.async.cg.shared.global [%0], [%1], 16;" :: "r"(sa), "l"(g));
}
__device__ __forceinline__ void mma16816(float* d, const uint32_t* a, const uint32_t* b){
    asm volatile("mma.sync.aligned.m16n8k16.row.col.f32.f16.f16.f32 "
        "{%0,%1,%2,%3}, {%4,%5,%6,%7}, {%8,%9}, {%0,%1,%2,%3};"
        : "+f"(d[0]),"+f"(d[1]),"+f"(d[2]),"+f"(d[3])
        : "r"(a[0]),"r"(a[1]),"r"(a[2]),"r"(a[3]),"r"(b[0]),"r"(b[1]));
}
__device__ __forceinline__ uint32_t lds32(const char* p){ return *(const uint32_t*)p; }
__device__ __forceinline__ void split2h(float v, hf& h, hf& l){
    h = __float2half_rn(v);
    l = __float2half_rn(v - __half2float(h));
}

// inner mma over one 32-K chunk. slots: A@0 [, Al@10240], B@(1+HASAL)*10240
template<int HASAL>
__device__ __forceinline__ void mma_tile(const char* tbase, const int* aob, const int* bob,
                                         float acc[4][4][4])
{
    const char* tA  = tbase;
    const char* tAl = tbase + 10240;
    const char* tB  = tbase + (1+HASAL)*10240;
#pragma unroll
    for (int ks = 0; ks < 2; ++ks){
        const int kb = ks * 32;
        uint32_t aH[4][4], bX[4][2];
#pragma unroll
        for (int mt = 0; mt < 4; ++mt){
            aH[mt][0] = lds32(tA + aob[mt] + kb);
            aH[mt][1] = lds32(tA + aob[mt] + kb + 640);
            aH[mt][2] = lds32(tA + aob[mt] + kb + 16);
            aH[mt][3] = lds32(tA + aob[mt] + kb + 656);
        }
#pragma unroll
        for (int nt = 0; nt < 4; ++nt){
            bX[nt][0] = lds32(tB + bob[nt] + kb);
            bX[nt][1] = lds32(tB + bob[nt] + kb + 16);
        }
#pragma unroll
        for (int mt = 0; mt < 4; ++mt)
#pragma unroll
            for (int nt = 0; nt < 4; ++nt) mma16816(acc[mt][nt], aH[mt], bX[nt]);
        if (HASAL){
            uint32_t aT[4][4];
#pragma unroll
            for (int mt = 0; mt < 4; ++mt){
                aT[mt][0] = lds32(tAl + aob[mt] + kb);
                aT[mt][1] = lds32(tAl + aob[mt] + kb + 640);
                aT[mt][2] = lds32(tAl + aob[mt] + kb + 16);
                aT[mt][3] = lds32(tAl + aob[mt] + kb + 656);
            }
#pragma unroll
            for (int mt = 0; mt < 4; ++mt)
#pragma unroll
                for (int nt = 0; nt < 4; ++nt) mma16816(acc[mt][nt], aT[mt], bX[nt]);
        }
    }
}

__device__ __forceinline__ void stage_acc(char* dyn, float acc[4][4][4],
                                          int wm, int wn, int quad, int lane2)
{
    float* stg = reinterpret_cast<float*>(dyn);
#pragma unroll
    for (int mt = 0; mt < 4; ++mt){
        const int r = wm*64 + mt*16 + quad;
#pragma unroll
        for (int nt = 0; nt < 4; ++nt){
            const int cc = wn*32 + nt*8 + lane2;
            stg[r*129 + cc]       = acc[mt][nt][0];
            stg[r*129 + cc + 1]   = acc[mt][nt][1];
            stg[(r+8)*129 + cc]   = acc[mt][nt][2];
            stg[(r+8)*129 + cc+1] = acc[mt][nt][3];
        }
    }
}

// ---------------- generic GEMM: C[m,n] = sum_k A[m,k]*B[n,k] ----------------
// HASAL: add Al*Bh pass. mode 0: fp32 -> oF ; mode 1: fp16 hi -> oH
template<int HASAL>
__global__ void __launch_bounds__(256, 1) k_gemm(
    const hf* __restrict__ Ah, const hf* __restrict__ Al,
    long sA1, long sA2, long sA3, int lda,
    const hf* __restrict__ Bh, long sB1, long sB2, long sB3, int ldb,
    int K, int zm1, int zm2, int mode,
    float* __restrict__ oF, hf* __restrict__ oH,
    long sO1, long sO2, long sO3, int ldo)
{
    extern __shared__ char dyn[];
    const uint32_t smb = smem_u32(dyn);
    const int bufB = (2+HASAL)*10240;
    const int tid = threadIdx.x;
    const int l = tid & 31, wid = tid >> 5;
    const int wm = wid >> 2, wn = wid & 3;
    const int quad = l >> 2, lane2 = (l & 3) * 2;
    const int z = blockIdx.z;
    const int z1 = z / zm1, zr = z % zm1;
    const int z2 = zr / zm2, z3 = zr % zm2;
    const int m0 = blockIdx.x * 128, n0 = blockIdx.y * 128;
    const long offA = z1*sA1 + z2*sA2 + z3*sA3;
    const long offB = z1*sB1 + z2*sB2 + z3*sB3;
    const long offO = z1*sO1 + z2*sO2 + z3*sO3;

    const hf* pAh = Ah + offA + (size_t)m0*lda;
    const hf* pAl = HASAL ? (Al + offA + (size_t)m0*lda) : pAh;
    const hf* pBh = Bh + offB + (size_t)n0*ldb;

    float acc[4][4][4];
#pragma unroll
    for (int a = 0; a < 4; ++a)
#pragma unroll
        for (int b = 0; b < 4; ++b)
#pragma unroll
            for (int c = 0; c < 4; ++c) acc[a][b][c] = 0.f;

    const int NC = K / 32;

    auto copy_chunk = [&](int c, int bufi){
        const hf* srcs[3];
        int lds[3];
        int nt = 0;
        srcs[nt] = pAh + c*32; lds[nt] = lda; nt++;
        if (HASAL){ srcs[nt] = pAl + c*32; lds[nt] = lda; nt++; }
        srcs[nt] = pBh + c*32; lds[nt] = ldb; nt++;
#pragma unroll
        for (int t = 0; t < 2+HASAL; ++t){
            const uint32_t sb = smb + bufi*bufB + t*10240;
#pragma unroll
            for (int i = 0; i < 2; ++i){
                int e = tid + i*256;
                int row = e >> 2, cc = e & 3;
                cp16(sb + row*80 + cc*16, srcs[t] + (size_t)row*lds[t] + cc*8);
            }
        }
    };

    copy_chunk(0, 0);
    asm volatile("cp.async.commit_group;");

    int aob[4], bob[4];
#pragma unroll
    for (int mt = 0; mt < 4; ++mt) aob[mt] = (wm*64 + mt*16 + quad)*80 + lane2*2;
#pragma unroll
    for (int nt = 0; nt < 4; ++nt) bob[nt] = (wn*32 + nt*8 + quad)*80 + lane2*2;

    for (int c = 0; c < NC; ++c){
        if (c + 1 < NC){
            copy_chunk(c+1, (c+1)&1);
            asm volatile("cp.async.commit_group;");
            asm volatile("cp.async.wait_group 1;");
        } else {
            asm volatile("cp.async.wait_group 0;");
        }
        __syncthreads();
        mma_tile<HASAL>(dyn + (c&1)*bufB, aob, bob, acc);
        __syncthreads();
    }

    stage_acc(dyn, acc, wm, wn, quad, lane2);
    __syncthreads();
    float* stg = reinterpret_cast<float*>(dyn);
    if (mode == 0){
        for (int idx = tid; idx < 16384; idx += 256){
            int r = idx >> 7, cc = idx & 127;
            oF[offO + (size_t)(m0+r)*ldo + n0 + cc] = stg[r*129 + cc];
        }
    } else {
        for (int idx = tid; idx < 16384; idx += 256){
            int r = idx >> 7, cc = idx & 127;
            oH[offO + (size_t)(m0+r)*ldo + n0 + cc] = __float2half_rn(stg[r*129 + cc]);
        }
    }
}

// ---------------- merged projection GEMM: 1-pass, all 6 stages in one launch ----------------
// z = stage*16 + (batch*4 + head). K fixed 256.
// stage 0: Q (mode2 pairs-T)  1: Qd (mode2)  2: Kd (mode3 hi-T)  3: K (mode3)
// stage 4: Vd (mode1 hi-nat)  5: V (mode1)
__global__ void __launch_bounds__(256, 1) k_proj(
    const float* __restrict__ e1, const float* __restrict__ ea,
    const float* __restrict__ ed, const float* __restrict__ eb,
    const hf* __restrict__ wq, const hf* __restrict__ wqd,
    const hf* __restrict__ wk, const hf* __restrict__ wkd,
    const hf* __restrict__ wv, const hf* __restrict__ wvd,
    hf* __restrict__ qAh, hf* __restrict__ qAl,
    hf* __restrict__ kBh, hf* __restrict__ vAh)
{
    extern __shared__ char dyn[];
    const uint32_t smb = smem_u32(dyn);
    const int tid = threadIdx.x;
    const int l = tid & 31, wid = tid >> 5;
    const int wm = wid >> 2, wn = wid & 3;
    const int quad = l >> 2, lane2 = (l & 3) * 2;
    const int z = blockIdx.z;
    const int s = z >> 4, zz = z & 15;
    const int z2 = zz >> 2, z3 = zz & 3;
    const int m0 = blockIdx.x * 128, n0 = blockIdx.y * 128;

    const float* A; const hf* W; hf* oH; hf* oL = 0; long sB3; int mode; int ldo;
    switch (s){
        case 0:  A = e1; W = wq;  sB3 = 65536; mode = 2; oH = qAh;            oL = qAl;            ldo = 4096; break;
        case 1:  A = ed; W = wqd; sB3 = 65536; mode = 2; oH = qAh + 16777216; oL = qAl + 16777216; ldo = 4096; break;
        case 2:  A = eb; W = wkd; sB3 = 0;     mode = 3; oH = kBh;                                 ldo = 4096; break;
        case 3:  A = ea; W = wk;  sB3 = 0;     mode = 3; oH = kBh + 16777216;                      ldo = 4096; break;
        case 4:  A = eb; W = wvd; sB3 = 0;     mode = 1; oH = vAh;                                 ldo = 256;  break;
        default: A = ea; W = wv;  sB3 = 0;     mode = 1; oH = vAh + 16777216;                      ldo = 256;  break;
    }
    const long offA = (long)z2*4194304 + (long)z3*256;
    const long offO = (long)z2*4194304 + (long)z3*1048576;
    const float* pA = A + offA + (size_t)m0*1024;
    const hf* pBh = W + z3*sB3 + (size_t)n0*256;

    float acc[4][4][4];
#pragma unroll
    for (int a = 0; a < 4; ++a)
#pragma unroll
        for (int b = 0; b < 4; ++b)
#pragma unroll
            for (int c = 0; c < 4; ++c) acc[a][b][c] = 0.f;

    auto copyB = [&](int c, int bufi){
        const uint32_t sb = smb + bufi*20480 + 10240;
#pragma unroll
        for (int i = 0; i < 2; ++i){
            int e = tid + i*256;
            int row = e >> 2, cc = e & 3;
            cp16(sb + row*80 + cc*16, pBh + c*32 + (size_t)row*256 + cc*8);
        }
    };
    auto ldgA = [&](float4* r, int c){
        const float* base = pA + c*32;
#pragma unroll
        for (int i = 0; i < 4; ++i){
            int e = tid + 256*i;
            int row = e >> 3, cg = e & 7;
            r[i] = *reinterpret_cast<const float4*>(base + (size_t)row*1024 + cg*4);
        }
    };
    auto stsA = [&](float4* r, int bufi){
        char* tA = dyn + bufi*20480;
#pragma unroll
        for (int i = 0; i < 4; ++i){
            int e = tid + 256*i;
            int row = e >> 3, cg = e & 7;
            float4 f = r[i];
            __half2 h0 = __floats2half2_rn(f.x, f.y);
            __half2 h1 = __floats2half2_rn(f.z, f.w);
            char* p = tA + row*80 + cg*8;
            *reinterpret_cast<__half2*>(p)     = h0;
            *reinterpret_cast<__half2*>(p + 4) = h1;
        }
    };

    int aob[4], bob[4];
#pragma unroll
    for (int mt = 0; mt < 4; ++mt) aob[mt] = (wm*64 + mt*16 + quad)*80 + lane2*2;
#pragma unroll
    for (int nt = 0; nt < 4; ++nt) bob[nt] = (wn*32 + nt*8 + quad)*80 + lane2*2;

    float4 rA[4], rA2[4];
    ldgA(rA, 0);
    copyB(0, 0);
    asm volatile("cp.async.commit_group;");

    const int NC = 8;
    for (int c = 0; c < NC; ++c){
        stsA(rA, c & 1);
        if (c + 1 < NC){
            ldgA(rA2, c+1);
            copyB(c+1, (c+1)&1);
            asm volatile("cp.async.commit_group;");
            asm volatile("cp.async.wait_group 1;");
        } else {
            asm volatile("cp.async.wait_group 0;");
        }
        __syncthreads();
        mma_tile<0>(dyn + (c&1)*20480, aob, bob, acc);
        __syncthreads();
#pragma unroll
        for (int i = 0; i < 4; ++i) rA[i] = rA2[i];
    }

    stage_acc(dyn, acc, wm, wn, quad, lane2);
    __syncthreads();
    float* stg = reinterpret_cast<float*>(dyn);
    if (mode == 1){
        for (int idx = tid; idx < 16384; idx += 256){
            int r = idx >> 7, cc = idx & 127;
            oH[offO + (size_t)(m0+r)*ldo + n0 + cc] = __float2half_rn(stg[r*129 + cc]);
        }
    } else if (mode == 2){
        for (int idx = tid; idx < 16384; idx += 256){
            int cc = idx >> 7, r = idx & 127;
            hf h, lo; split2h(stg[r*129 + cc], h, lo);
            size_t o = offO + (size_t)(n0+cc)*ldo + m0 + r;
            oH[o] = h; oL[o] = lo;
        }
    } else {
        for (int idx = tid; idx < 16384; idx += 256){
            int cc = idx >> 7, r = idx & 127;
            oH[offO + (size_t)(n0+cc)*ldo + m0 + r] = __float2half_rn(stg[r*129 + cc]);
        }
    }
}

// ---------------- elementwise ----------------
// 6 QKV weights in one launch: y selects tensor; sizes 262144 (s<2) / 65536
__global__ void __launch_bounds__(256) k_splitW6(
    const float* __restrict__ Wq, const float* __restrict__ Wqd,
    const float* __restrict__ Wk, const float* __restrict__ Wkd,
    const float* __restrict__ Wv, const float* __restrict__ Wvd,
    hf* __restrict__ wqh, hf* __restrict__ wqdh,
    hf* __restrict__ wkh, hf* __restrict__ wkdh,
    hf* __restrict__ wvh, hf* __restrict__ wvdh)
{
    const int s = blockIdx.y;
    const float* src; hf* dst; int n;
    switch (s){
        case 0:  src = Wq;  dst = wqh;  n = 262144; break;
        case 1:  src = Wqd; dst = wqdh; n = 262144; break;
        case 2:  src = Wk;  dst = wkh;  n = 65536;  break;
        case 3:  src = Wkd; dst = wkdh; n = 65536;  break;
        case 4:  src = Wv;  dst = wvh;  n = 65536;  break;
        default: src = Wvd; dst = wvdh; n = 65536;  break;
    }
    int i = (blockIdx.x*256 + threadIdx.x) * 4;
    if (i >= n) return;
    float4 v = *reinterpret_cast<const float4*>(src + i);
    dst[i]   = __float2half_rn(v.x);
    dst[i+1] = __float2half_rn(v.y);
    dst[i+2] = __float2half_rn(v.z);
    dst[i+3] = __float2half_rn(v.w);
}
// Wout gather-block, both paths via y
__global__ void __launch_bounds__(256) k_splitWo(const float* __restrict__ Wo,
                                                 const float* __restrict__ Wod,
                                                 hf* __restrict__ h){
    const float* s = blockIdx.y ? Wod : Wo;
    int idx = blockIdx.x*256 + threadIdx.x;
    int j = idx >> 10, t = idx & 1023;
    h[(size_t)blockIdx.y*1048576 + idx] =
        __float2half_rn(s[((size_t)j<<10) + ((t & 255)<<2) + (t>>8)]);
}
__global__ void __launch_bounds__(256) k_reduce(){
    int idx = blockIdx.x*256 + threadIdx.x;
    int pb = idx >> 20, r = idx & 1048575;
    const float* p = g_sp + (size_t)pb*8388608 + r;
    float s = 0.f;
#pragma unroll
    for (int sl = 0; sl < 8; ++sl) s += p[(size_t)sl*1048576];
    g_s[idx] = s * SCALEV;
}
__global__ void __launch_bounds__(256) k_moments(){
    const int idx = blockIdx.x;
    const float* s = g_s + (size_t)idx*65536;
    __shared__ float sh[256], sh2[256];
    float sum = 0.f, sq = 0.f;
    for (int i = threadIdx.x; i < 65536; i += 256){ float v = s[i]; sum += v; sq = fmaf(v,v,sq); }
    sh[threadIdx.x] = sum; sh2[threadIdx.x] = sq;
    __syncthreads();
    for (int o = 128; o; o >>= 1){
        if (threadIdx.x < o){ sh[threadIdx.x] += sh[threadIdx.x+o]; sh2[threadIdx.x] += sh2[threadIdx.x+o]; }
        __syncthreads();
    }
    if (threadIdx.x == 0){
        float m = sh[0]*(1.f/65536.f);
        g_mv[idx*2] = m;
        g_mv[idx*2+1] = sh2[0]*(1.f/65536.f) - m*m;
    }
}
__global__ void __launch_bounds__(256) k_softmax(){
    const int pb = blockIdx.z*16 + blockIdx.y;
    const size_t rb = ((size_t)pb*256 + blockIdx.x)*256;
    const float mean = g_mv[pb*2];
    const float inv  = rsqrtf(g_mv[pb*2+1] + EPSV);
    const int tid = threadIdx.x;
    float y = (g_s[rb + tid] - mean) * inv;
    __shared__ float red[8];
    float m = y;
#pragma unroll
    for (int o = 16; o; o >>= 1) m = fmaxf(m, __shfl_xor_sync(~0u, m, o));
    if ((tid & 31) == 0) red[tid>>5] = m;
    __syncthreads();
    if (tid == 0){ float mm = red[0]; for (int i=1;i<8;++i) mm = fmaxf(mm, red[i]); red[0] = mm; }
    __syncthreads();
    float e = expf(y - red[0]);
    __syncthreads();
    float ssum = e;
#pragma unroll
    for (int o = 16; o; o >>= 1) ssum += __shfl_xor_sync(~0u, ssum, o);
    if ((tid & 31) == 0) red[tid>>5] = ssum;
    __syncthreads();
    if (tid == 0){ float t = 0.f; for (int i=0;i<8;++i) t += red[i]; red[0] = t; }
    __syncthreads();
    g_ph[rb + tid] = __float2half_rn(e / red[0]);
}

// ---------------- launch ----------------
static void* dsym(const void* s){ void* p = 0; cudaGetSymbolAddress(&p, s); return p; }

extern "C" void kernel_launch(void* const* d_in, const int* in_sizes, int n_in,
                              void* d_out, int out_size)
{
    const float* emb1     = (const float*)d_in[0];
    const float* emb_all  = (const float*)d_in[1];
    const float* embd1    = (const float*)d_in[2];
    const float* emb_alld = (const float*)d_in[3];
    const float* Wq = (const float*)d_in[4];  const float* Wqd = (const float*)d_in[5];
    const float* Wk = (const float*)d_in[6];  const float* Wv  = (const float*)d_in[7];
    const float* Wkd= (const float*)d_in[8];  const float* Wvd = (const float*)d_in[9];
    const float* Wo = (const float*)d_in[10]; const float* Wod = (const float*)d_in[11];
    float* out = (float*)d_out;

    const int SM = 66048;
    cudaFuncSetAttribute(k_gemm<1>, cudaFuncAttributeMaxDynamicSharedMemorySize, SM);
    cudaFuncSetAttribute(k_gemm<0>, cudaFuncAttributeMaxDynamicSharedMemorySize, SM);
    cudaFuncSetAttribute(k_proj,    cudaFuncAttributeMaxDynamicSharedMemorySize, SM);

#define GH(x) ((hf*)dsym(x))
    hf *qAh = GH(g_qAh), *qAl = GH(g_qAl);
    hf *kBh = GH(g_kBh), *vAh = GH(g_vAh);
    hf *ch = GH(g_ch), *ph = GH(g_ph), *woh = GH(g_woh);
    float* sp = (float*)dsym(g_sp);

    // weight conversions (merged)
    k_splitW6<<<dim3(256,6),256>>>(Wq,Wqd,Wk,Wkd,Wv,Wvd,
                                   GH(g_wqh),GH(g_wqdh),GH(g_wkh),GH(g_wkdh),GH(g_wvh),GH(g_wvdh));
    k_splitWo<<<dim3(4096,2),256>>>(Wo, Wod, woh);

    // projections: 1-pass, all 6 stages in one launch
    k_proj<<<dim3(32,2,96),256,SM>>>(emb1, emb_all, embd1, emb_alld,
                                     GH(g_wqh),GH(g_wqdh),GH(g_wkh),GH(g_wkdh),GH(g_wvh),GH(g_wvdh),
                                     qAh, qAl, kBh, vAh);

    // scores: 2-pass (Q pairs x K hi), split-K x8, one launch
    dim3 gsc(2,2,256);
    k_gemm<1><<<gsc,256,SM>>>(qAh,qAl, 16777216,1048576,512, 4096,
                              kBh, 16777216,1048576,512, 4096,
                              512, 128,8, 0,
                              sp, (hf*)0, 8388608,65536,1048576, 256);
    k_reduce<<<8192,256>>>();
    k_moments<<<32,256>>>();
    k_softmax<<<dim3(256,16,2),256>>>();

    // ctx: 1-pass (V hi x probs hi), both paths in one launch
    dim3 gc(32,2,32);
    k_gemm<0><<<gc,256,SM>>>(vAh,(hf*)0, 16777216,4194304,1048576, 256,
                             ph, 1048576,262144,65536, 256,
                             256, 16,4, 1,
                             (float*)0, ch, 16777216,4194304,256, 1024);

    // out: 1-pass (ctx hi x Wo hi), both paths in one launch
    dim3 go(128,8,2);
    k_gemm<0><<<go,256,SM>>>(ch,(hf*)0, 16777216,0,0, 1024,
                             woh, 1048576,0,0, 1024,
                             1024, 1,1, 0,
                             out, (hf*)0, 16777216,0,0, 1024);
#undef GH
}

// round 10
// speedup vs baseline: 6.2938x; 1.2452x over previous
#include <cuda_runtime.h>
#include <cuda_fp16.h>
#include <stdint.h>
#include <math.h>

typedef __half hf;

#define EPSV 1e-5f
#define SCALEV 0.03125f

// ---------------- scratch ----------------
__device__ __align__(16) hf g_qAh[33554432], g_qAl[33554432];  // Qt pairs [path][bh][c][n]
__device__ __align__(16) hf g_kBh[33554432];                   // [Kdt; Kt] hi
__device__ __align__(16) hf g_vAh[33554432];                   // [Vd; V] hi [bh][n][k]
__device__ __align__(16) hf g_wqh[262144], g_wqdh[262144];
__device__ __align__(16) hf g_wkh[65536], g_wvh[65536], g_wkdh[65536], g_wvdh[65536];
__device__ __align__(16) hf g_woh[2097152];                    // blocked, both paths
__device__ __align__(16) float g_sp[16777216];                 // score partials
__device__ __align__(16) float g_s[2097152];
__device__ __align__(16) hf g_ph[2097152];
__device__ __align__(16) hf g_ch[33554432];                    // ctx fp16 blocked, both paths
__device__ float g_mv[64];

// ---------------- helpers ----------------
__device__ __forceinline__ uint32_t smem_u32(const void* p){
    uint32_t a;
    asm("{ .reg .u64 t; cvta.to.shared.u64 t, %1; cvt.u32.u64 %0, t; }" : "=r"(a) : "l"(p));
    return a;
}
__device__ __forceinline__ void cp16(uint32_t sa, const void* g){
    asm volatile("cp.async.cg.shared.global [%0], [%1], 16;" :: "r"(sa), "l"(g));
}
__device__ __forceinline__ void mma16816(float* d, const uint32_t* a, const uint32_t* b){
    asm volatile("mma.sync.aligned.m16n8k16.row.col.f32.f16.f16.f32 "
        "{%0,%1,%2,%3}, {%4,%5,%6,%7}, {%8,%9}, {%0,%1,%2,%3};"
        : "+f"(d[0]),"+f"(d[1]),"+f"(d[2]),"+f"(d[3])
        : "r"(a[0]),"r"(a[1]),"r"(a[2]),"r"(a[3]),"r"(b[0]),"r"(b[1]));
}
__device__ __forceinline__ uint32_t lds32(const char* p){ return *(const uint32_t*)p; }
__device__ __forceinline__ void split2h(float v, hf& h, hf& l){
    h = __float2half_rn(v);
    l = __float2half_rn(v - __half2float(h));
}

// inner mma over one 32-K chunk. slots: A@0 [, Al@10240], B@(1+HASAL)*10240
// register-lean: ONE A-fragment array reused across passes; B loaded once per ks.
template<int HASAL>
__device__ __forceinline__ void mma_tile(const char* tbase, const int* aob, const int* bob,
                                         float acc[4][4][4])
{
    const char* tB = tbase + (1+HASAL)*10240;
#pragma unroll
    for (int ks = 0; ks < 2; ++ks){
        const int kb = ks * 32;
        uint32_t bX[4][2];
#pragma unroll
        for (int nt = 0; nt < 4; ++nt){
            bX[nt][0] = lds32(tB + bob[nt] + kb);
            bX[nt][1] = lds32(tB + bob[nt] + kb + 16);
        }
#pragma unroll
        for (int pass = 0; pass <= HASAL; ++pass){
            const char* tAp = tbase + pass*10240;
            uint32_t aH[4][4];
#pragma unroll
            for (int mt = 0; mt < 4; ++mt){
                aH[mt][0] = lds32(tAp + aob[mt] + kb);
                aH[mt][1] = lds32(tAp + aob[mt] + kb + 640);
                aH[mt][2] = lds32(tAp + aob[mt] + kb + 16);
                aH[mt][3] = lds32(tAp + aob[mt] + kb + 656);
            }
#pragma unroll
            for (int mt = 0; mt < 4; ++mt)
#pragma unroll
                for (int nt = 0; nt < 4; ++nt) mma16816(acc[mt][nt], aH[mt], bX[nt]);
        }
    }
}

__device__ __forceinline__ void stage_acc(char* dyn, float acc[4][4][4],
                                          int wm, int wn, int quad, int lane2)
{
    float* stg = reinterpret_cast<float*>(dyn);
#pragma unroll
    for (int mt = 0; mt < 4; ++mt){
        const int r = wm*64 + mt*16 + quad;
#pragma unroll
        for (int nt = 0; nt < 4; ++nt){
            const int cc = wn*32 + nt*8 + lane2;
            stg[r*129 + cc]       = acc[mt][nt][0];
            stg[r*129 + cc + 1]   = acc[mt][nt][1];
            stg[(r+8)*129 + cc]   = acc[mt][nt][2];
            stg[(r+8)*129 + cc+1] = acc[mt][nt][3];
        }
    }
}

// ---------------- generic GEMM: C[m,n] = sum_k A[m,k]*B[n,k] ----------------
// HASAL: add Al*Bh pass. mode 0: fp32 -> oF ; mode 1: fp16 hi -> oH
template<int HASAL>
__global__ void __launch_bounds__(256, 2) k_gemm(
    const hf* __restrict__ Ah, const hf* __restrict__ Al,
    long sA1, long sA2, long sA3, int lda,
    const hf* __restrict__ Bh, long sB1, long sB2, long sB3, int ldb,
    int K, int zm1, int zm2, int mode,
    float* __restrict__ oF, hf* __restrict__ oH,
    long sO1, long sO2, long sO3, int ldo)
{
    extern __shared__ char dyn[];
    const uint32_t smb = smem_u32(dyn);
    const int bufB = (2+HASAL)*10240;
    const int tid = threadIdx.x;
    const int l = tid & 31, wid = tid >> 5;
    const int wm = wid >> 2, wn = wid & 3;
    const int quad = l >> 2, lane2 = (l & 3) * 2;
    const int z = blockIdx.z;
    const int z1 = z / zm1, zr = z % zm1;
    const int z2 = zr / zm2, z3 = zr % zm2;
    const int m0 = blockIdx.x * 128, n0 = blockIdx.y * 128;
    const long offA = z1*sA1 + z2*sA2 + z3*sA3;
    const long offB = z1*sB1 + z2*sB2 + z3*sB3;
    const long offO = z1*sO1 + z2*sO2 + z3*sO3;

    const hf* pAh = Ah + offA + (size_t)m0*lda;
    const hf* pAl = HASAL ? (Al + offA + (size_t)m0*lda) : pAh;
    const hf* pBh = Bh + offB + (size_t)n0*ldb;

    float acc[4][4][4];
#pragma unroll
    for (int a = 0; a < 4; ++a)
#pragma unroll
        for (int b = 0; b < 4; ++b)
#pragma unroll
            for (int c = 0; c < 4; ++c) acc[a][b][c] = 0.f;

    const int NC = K / 32;

    auto copy_chunk = [&](int c, int bufi){
        const hf* srcs[3];
        int lds[3];
        int nt = 0;
        srcs[nt] = pAh + c*32; lds[nt] = lda; nt++;
        if (HASAL){ srcs[nt] = pAl + c*32; lds[nt] = lda; nt++; }
        srcs[nt] = pBh + c*32; lds[nt] = ldb; nt++;
#pragma unroll
        for (int t = 0; t < 2+HASAL; ++t){
            const uint32_t sb = smb + bufi*bufB + t*10240;
#pragma unroll
            for (int i = 0; i < 2; ++i){
                int e = tid + i*256;
                int row = e >> 2, cc = e & 3;
                cp16(sb + row*80 + cc*16, srcs[t] + (size_t)row*lds[t] + cc*8);
            }
        }
    };

    copy_chunk(0, 0);
    asm volatile("cp.async.commit_group;");

    int aob[4], bob[4];
#pragma unroll
    for (int mt = 0; mt < 4; ++mt) aob[mt] = (wm*64 + mt*16 + quad)*80 + lane2*2;
#pragma unroll
    for (int nt = 0; nt < 4; ++nt) bob[nt] = (wn*32 + nt*8 + quad)*80 + lane2*2;

    for (int c = 0; c < NC; ++c){
        if (c + 1 < NC){
            copy_chunk(c+1, (c+1)&1);
            asm volatile("cp.async.commit_group;");
            asm volatile("cp.async.wait_group 1;");
        } else {
            asm volatile("cp.async.wait_group 0;");
        }
        __syncthreads();
        mma_tile<HASAL>(dyn + (c&1)*bufB, aob, bob, acc);
        __syncthreads();
    }

    stage_acc(dyn, acc, wm, wn, quad, lane2);
    __syncthreads();
    float* stg = reinterpret_cast<float*>(dyn);
    if (mode == 0){
        for (int idx = tid; idx < 16384; idx += 256){
            int r = idx >> 7, cc = idx & 127;
            oF[offO + (size_t)(m0+r)*ldo + n0 + cc] = stg[r*129 + cc];
        }
    } else {
        for (int idx = tid; idx < 16384; idx += 256){
            int r = idx >> 7, cc = idx & 127;
            oH[offO + (size_t)(m0+r)*ldo + n0 + cc] = __float2half_rn(stg[r*129 + cc]);
        }
    }
}

// ---------------- merged projection GEMM: 1-pass, all 6 stages in one launch ----------------
// z = stage*16 + (batch*4 + head). K fixed 256.
__global__ void __launch_bounds__(256, 2) k_proj(
    const float* __restrict__ e1, const float* __restrict__ ea,
    const float* __restrict__ ed, const float* __restrict__ eb,
    const hf* __restrict__ wq, const hf* __restrict__ wqd,
    const hf* __restrict__ wk, const hf* __restrict__ wkd,
    const hf* __restrict__ wv, const hf* __restrict__ wvd,
    hf* __restrict__ qAh, hf* __restrict__ qAl,
    hf* __restrict__ kBh, hf* __restrict__ vAh)
{
    extern __shared__ char dyn[];
    const uint32_t smb = smem_u32(dyn);
    const int tid = threadIdx.x;
    const int l = tid & 31, wid = tid >> 5;
    const int wm = wid >> 2, wn = wid & 3;
    const int quad = l >> 2, lane2 = (l & 3) * 2;
    const int z = blockIdx.z;
    const int s = z >> 4, zz = z & 15;
    const int z2 = zz >> 2, z3 = zz & 3;
    const int m0 = blockIdx.x * 128, n0 = blockIdx.y * 128;

    const float* A; const hf* W; hf* oH; hf* oL = 0; long sB3; int mode; int ldo;
    switch (s){
        case 0:  A = e1; W = wq;  sB3 = 65536; mode = 2; oH = qAh;            oL = qAl;            ldo = 4096; break;
        case 1:  A = ed; W = wqd; sB3 = 65536; mode = 2; oH = qAh + 16777216; oL = qAl + 16777216; ldo = 4096; break;
        case 2:  A = eb; W = wkd; sB3 = 0;     mode = 3; oH = kBh;                                 ldo = 4096; break;
        case 3:  A = ea; W = wk;  sB3 = 0;     mode = 3; oH = kBh + 16777216;                      ldo = 4096; break;
        case 4:  A = eb; W = wvd; sB3 = 0;     mode = 1; oH = vAh;                                 ldo = 256;  break;
        default: A = ea; W = wv;  sB3 = 0;     mode = 1; oH = vAh + 16777216;                      ldo = 256;  break;
    }
    const long offA = (long)z2*4194304 + (long)z3*256;
    const long offO = (long)z2*4194304 + (long)z3*1048576;
    const float* pA = A + offA + (size_t)m0*1024;
    const hf* pBh = W + z3*sB3 + (size_t)n0*256;

    float acc[4][4][4];
#pragma unroll
    for (int a = 0; a < 4; ++a)
#pragma unroll
        for (int b = 0; b < 4; ++b)
#pragma unroll
            for (int c = 0; c < 4; ++c) acc[a][b][c] = 0.f;

    auto copyB = [&](int c, int bufi){
        const uint32_t sb = smb + bufi*20480 + 10240;
#pragma unroll
        for (int i = 0; i < 2; ++i){
            int e = tid + i*256;
            int row = e >> 2, cc = e & 3;
            cp16(sb + row*80 + cc*16, pBh + c*32 + (size_t)row*256 + cc*8);
        }
    };
    auto ldgA = [&](float4* r, int c){
        const float* base = pA + c*32;
#pragma unroll
        for (int i = 0; i < 4; ++i){
            int e = tid + 256*i;
            int row = e >> 3, cg = e & 7;
            r[i] = *reinterpret_cast<const float4*>(base + (size_t)row*1024 + cg*4);
        }
    };
    auto stsA = [&](float4* r, int bufi){
        char* tA = dyn + bufi*20480;
#pragma unroll
        for (int i = 0; i < 4; ++i){
            int e = tid + 256*i;
            int row = e >> 3, cg = e & 7;
            float4 f = r[i];
            __half2 h0 = __floats2half2_rn(f.x, f.y);
            __half2 h1 = __floats2half2_rn(f.z, f.w);
            char* p = tA + row*80 + cg*8;
            *reinterpret_cast<__half2*>(p)     = h0;
            *reinterpret_cast<__half2*>(p + 4) = h1;
        }
    };

    int aob[4], bob[4];
#pragma unroll
    for (int mt = 0; mt < 4; ++mt) aob[mt] = (wm*64 + mt*16 + quad)*80 + lane2*2;
#pragma unroll
    for (int nt = 0; nt < 4; ++nt) bob[nt] = (wn*32 + nt*8 + quad)*80 + lane2*2;

    float4 rA[4], rA2[4];
    ldgA(rA, 0);
    copyB(0, 0);
    asm volatile("cp.async.commit_group;");

    const int NC = 8;
    for (int c = 0; c < NC; ++c){
        stsA(rA, c & 1);
        if (c + 1 < NC){
            ldgA(rA2, c+1);
            copyB(c+1, (c+1)&1);
            asm volatile("cp.async.commit_group;");
            asm volatile("cp.async.wait_group 1;");
        } else {
            asm volatile("cp.async.wait_group 0;");
        }
        __syncthreads();
        mma_tile<0>(dyn + (c&1)*20480, aob, bob, acc);
        __syncthreads();
#pragma unroll
        for (int i = 0; i < 4; ++i) rA[i] = rA2[i];
    }

    stage_acc(dyn, acc, wm, wn, quad, lane2);
    __syncthreads();
    float* stg = reinterpret_cast<float*>(dyn);
    if (mode == 1){
        for (int idx = tid; idx < 16384; idx += 256){
            int r = idx >> 7, cc = idx & 127;
            oH[offO + (size_t)(m0+r)*ldo + n0 + cc] = __float2half_rn(stg[r*129 + cc]);
        }
    } else if (mode == 2){
        for (int idx = tid; idx < 16384; idx += 256){
            int cc = idx >> 7, r = idx & 127;
            hf h, lo; split2h(stg[r*129 + cc], h, lo);
            size_t o = offO + (size_t)(n0+cc)*ldo + m0 + r;
            oH[o] = h; oL[o] = lo;
        }
    } else {
        for (int idx = tid; idx < 16384; idx += 256){
            int cc = idx >> 7, r = idx & 127;
            oH[offO + (size_t)(n0+cc)*ldo + m0 + r] = __float2half_rn(stg[r*129 + cc]);
        }
    }
}

// ---------------- elementwise ----------------
__global__ void __launch_bounds__(256) k_splitW6(
    const float* __restrict__ Wq, const float* __restrict__ Wqd,
    const float* __restrict__ Wk, const float* __restrict__ Wkd,
    const float* __restrict__ Wv, const float* __restrict__ Wvd,
    hf* __restrict__ wqh, hf* __restrict__ wqdh,
    hf* __restrict__ wkh, hf* __restrict__ wkdh,
    hf* __restrict__ wvh, hf* __restrict__ wvdh)
{
    const int s = blockIdx.y;
    const float* src; hf* dst; int n;
    switch (s){
        case 0:  src = Wq;  dst = wqh;  n = 262144; break;
        case 1:  src = Wqd; dst = wqdh; n = 262144; break;
        case 2:  src = Wk;  dst = wkh;  n = 65536;  break;
        case 3:  src = Wkd; dst = wkdh; n = 65536;  break;
        case 4:  src = Wv;  dst = wvh;  n = 65536;  break;
        default: src = Wvd; dst = wvdh; n = 65536;  break;
    }
    int i = (blockIdx.x*256 + threadIdx.x) * 4;
    if (i >= n) return;
    float4 v = *reinterpret_cast<const float4*>(src + i);
    dst[i]   = __float2half_rn(v.x);
    dst[i+1] = __float2half_rn(v.y);
    dst[i+2] = __float2half_rn(v.z);
    dst[i+3] = __float2half_rn(v.w);
}
__global__ void __launch_bounds__(256) k_splitWo(const float* __restrict__ Wo,
                                                 const float* __restrict__ Wod,
                                                 hf* __restrict__ h){
    const float* s = blockIdx.y ? Wod : Wo;
    int idx = blockIdx.x*256 + threadIdx.x;
    int j = idx >> 10, t = idx & 1023;
    h[(size_t)blockIdx.y*1048576 + idx] =
        __float2half_rn(s[((size_t)j<<10) + ((t & 255)<<2) + (t>>8)]);
}
__global__ void __launch_bounds__(256) k_reduce(){
    int idx = blockIdx.x*256 + threadIdx.x;
    int pb = idx >> 20, r = idx & 1048575;
    const float* p = g_sp + (size_t)pb*8388608 + r;
    float s = 0.f;
#pragma unroll
    for (int sl = 0; sl < 8; ++sl) s += p[(size_t)sl*1048576];
    g_s[idx] = s * SCALEV;
}
__global__ void __launch_bounds__(256) k_moments(){
    const int idx = blockIdx.x;
    const float* s = g_s + (size_t)idx*65536;
    __shared__ float sh[256], sh2[256];
    float sum = 0.f, sq = 0.f;
    for (int i = threadIdx.x; i < 65536; i += 256){ float v = s[i]; sum += v; sq = fmaf(v,v,sq); }
    sh[threadIdx.x] = sum; sh2[threadIdx.x] = sq;
    __syncthreads();
    for (int o = 128; o; o >>= 1){
        if (threadIdx.x < o){ sh[threadIdx.x] += sh[threadIdx.x+o]; sh2[threadIdx.x] += sh2[threadIdx.x+o]; }
        __syncthreads();
    }
    if (threadIdx.x == 0){
        float m = sh[0]*(1.f/65536.f);
        g_mv[idx*2] = m;
        g_mv[idx*2+1] = sh2[0]*(1.f/65536.f) - m*m;
    }
}
__global__ void __launch_bounds__(256) k_softmax(){
    const int pb = blockIdx.z*16 + blockIdx.y;
    const size_t rb = ((size_t)pb*256 + blockIdx.x)*256;
    const float mean = g_mv[pb*2];
    const float inv  = rsqrtf(g_mv[pb*2+1] + EPSV);
    const int tid = threadIdx.x;
    float y = (g_s[rb + tid] - mean) * inv;
    __shared__ float red[8];
    float m = y;
#pragma unroll
    for (int o = 16; o; o >>= 1) m = fmaxf(m, __shfl_xor_sync(~0u, m, o));
    if ((tid & 31) == 0) red[tid>>5] = m;
    __syncthreads();
    if (tid == 0){ float mm = red[0]; for (int i=1;i<8;++i) mm = fmaxf(mm, red[i]); red[0] = mm; }
    __syncthreads();
    float e = expf(y - red[0]);
    __syncthreads();
    float ssum = e;
#pragma unroll
    for (int o = 16; o; o >>= 1) ssum += __shfl_xor_sync(~0u, ssum, o);
    if ((tid & 31) == 0) red[tid>>5] = ssum;
    __syncthreads();
    if (tid == 0){ float t = 0.f; for (int i=0;i<8;++i) t += red[i]; red[0] = t; }
    __syncthreads();
    g_ph[rb + tid] = __float2half_rn(e / red[0]);
}

// ---------------- launch ----------------
static void* dsym(const void* s){ void* p = 0; cudaGetSymbolAddress(&p, s); return p; }

extern "C" void kernel_launch(void* const* d_in, const int* in_sizes, int n_in,
                              void* d_out, int out_size)
{
    const float* emb1     = (const float*)d_in[0];
    const float* emb_all  = (const float*)d_in[1];
    const float* embd1    = (const float*)d_in[2];
    const float* emb_alld = (const float*)d_in[3];
    const float* Wq = (const float*)d_in[4];  const float* Wqd = (const float*)d_in[5];
    const float* Wk = (const float*)d_in[6];  const float* Wv  = (const float*)d_in[7];
    const float* Wkd= (const float*)d_in[8];  const float* Wvd = (const float*)d_in[9];
    const float* Wo = (const float*)d_in[10]; const float* Wod = (const float*)d_in[11];
    float* out = (float*)d_out;

    const int SM = 66048;
    cudaFuncSetAttribute(k_gemm<1>, cudaFuncAttributeMaxDynamicSharedMemorySize, SM);
    cudaFuncSetAttribute(k_gemm<0>, cudaFuncAttributeMaxDynamicSharedMemorySize, SM);
    cudaFuncSetAttribute(k_proj,    cudaFuncAttributeMaxDynamicSharedMemorySize, SM);

#define GH(x) ((hf*)dsym(x))
    hf *qAh = GH(g_qAh), *qAl = GH(g_qAl);
    hf *kBh = GH(g_kBh), *vAh = GH(g_vAh);
    hf *ch = GH(g_ch), *ph = GH(g_ph), *woh = GH(g_woh);
    float* sp = (float*)dsym(g_sp);

    // weight conversions (merged)
    k_splitW6<<<dim3(256,6),256>>>(Wq,Wqd,Wk,Wkd,Wv,Wvd,
                                   GH(g_wqh),GH(g_wqdh),GH(g_wkh),GH(g_wkdh),GH(g_wvh),GH(g_wvdh));
    k_splitWo<<<dim3(4096,2),256>>>(Wo, Wod, woh);

    // projections: 1-pass, all 6 stages in one launch
    k_proj<<<dim3(32,2,96),256,SM>>>(emb1, emb_all, embd1, emb_alld,
                                     GH(g_wqh),GH(g_wqdh),GH(g_wkh),GH(g_wkdh),GH(g_wvh),GH(g_wvdh),
                                     qAh, qAl, kBh, vAh);

    // scores: 2-pass (Q pairs x K hi), split-K x8, one launch
    dim3 gsc(2,2,256);
    k_gemm<1><<<gsc,256,SM>>>(qAh,qAl, 16777216,1048576,512, 4096,
                              kBh, 16777216,1048576,512, 4096,
                              512, 128,8, 0,
                              sp, (hf*)0, 8388608,65536,1048576, 256);
    k_reduce<<<8192,256>>>();
    k_moments<<<32,256>>>();
    k_softmax<<<dim3(256,16,2),256>>>();

    // ctx: 1-pass (V hi x probs hi), both paths in one launch
    dim3 gc(32,2,32);
    k_gemm<0><<<gc,256,SM>>>(vAh,(hf*)0, 16777216,4194304,1048576, 256,
                             ph, 1048576,262144,65536, 256,
                             256, 16,4, 1,
                             (float*)0, ch, 16777216,4194304,256, 1024);

    // out: 1-pass (ctx hi x Wo hi), both paths in one launch
    dim3 go(128,8,2);
    k_gemm<0><<<go,256,SM>>>(ch,(hf*)0, 16777216,0,0, 1024,
                             woh, 1048576,0,0, 1024,
                             1024, 1,1, 0,
                             out, (hf*)0, 16777216,0,0, 1024);
#undef GH
}

// round 11
// speedup vs baseline: 6.6733x; 1.0603x over previous
#include <cuda_runtime.h>
#include <cuda_fp16.h>
#include <stdint.h>
#include <math.h>

typedef __half hf;

#define EPSV 1e-5f
#define SCALEV 0.03125f

// ---------------- scratch ----------------
__device__ __align__(16) hf g_qAh[33554432], g_qAl[33554432];  // Qt pairs [path][bh][c][n]
__device__ __align__(16) hf g_kBh[33554432];                   // [Kdt; Kt] hi
__device__ __align__(16) hf g_vAh[33554432];                   // [Vd; V] hi [bh][n][k]
__device__ __align__(16) hf g_wqh[262144], g_wqdh[262144];
__device__ __align__(16) hf g_wkh[65536], g_wvh[65536], g_wkdh[65536], g_wvdh[65536];
__device__ __align__(16) hf g_woh[2097152];                    // blocked, both paths
__device__ __align__(16) float g_sp[16777216];                 // score partials
__device__ __align__(16) float g_s[2097152];
__device__ __align__(16) hf g_ph[2097152];
__device__ __align__(16) hf g_ch[33554432];                    // ctx fp16 blocked, both paths
__device__ float g_mv[64];

// ---------------- helpers ----------------
__device__ __forceinline__ uint32_t smem_u32(const void* p){
    uint32_t a;
    asm("{ .reg .u64 t; cvta.to.shared.u64 t, %1; cvt.u32.u64 %0, t; }" : "=r"(a) : "l"(p));
    return a;
}
__device__ __forceinline__ void cp16(uint32_t sa, const void* g){
    asm volatile("cp.async.cg.shared.global [%0], [%1], 16;" :: "r"(sa), "l"(g));
}
__device__ __forceinline__ void mma16816(float* d, const uint32_t* a, const uint32_t* b){
    asm volatile("mma.sync.aligned.m16n8k16.row.col.f32.f16.f16.f32 "
        "{%0,%1,%2,%3}, {%4,%5,%6,%7}, {%8,%9}, {%0,%1,%2,%3};"
        : "+f"(d[0]),"+f"(d[1]),"+f"(d[2]),"+f"(d[3])
        : "r"(a[0]),"r"(a[1]),"r"(a[2]),"r"(a[3]),"r"(b[0]),"r"(b[1]));
}
__device__ __forceinline__ void ldsm4(uint32_t* r, uint32_t addr){
    asm volatile("ldmatrix.sync.aligned.m8n8.x4.shared.b16 {%0,%1,%2,%3}, [%4];"
        : "=r"(r[0]),"=r"(r[1]),"=r"(r[2]),"=r"(r[3]) : "r"(addr));
}
__device__ __forceinline__ void ldsm2(uint32_t* r, uint32_t addr){
    asm volatile("ldmatrix.sync.aligned.m8n8.x2.shared.b16 {%0,%1}, [%2];"
        : "=r"(r[0]),"=r"(r[1]) : "r"(addr));
}
__device__ __forceinline__ void split2h(float v, hf& h, hf& l){
    h = __float2half_rn(v);
    l = __float2half_rn(v - __half2float(h));
}

// inner mma over one 32-K chunk via ldmatrix. slots: A@0 [, Al@10240], B@(1+HASAL)*10240
// aoff/boff: per-lane ldmatrix base byte offsets within a tile.
template<int HASAL>
__device__ __forceinline__ void mma_tile(uint32_t tbase, const uint32_t* aoff, const uint32_t* boff,
                                         float acc[4][4][4])
{
    const uint32_t tB = tbase + (1+HASAL)*10240;
#pragma unroll
    for (int ks = 0; ks < 2; ++ks){
        const int kb = ks * 32;
        uint32_t bX[4][2];
#pragma unroll
        for (int nt = 0; nt < 4; ++nt) ldsm2(bX[nt], tB + boff[nt] + kb);
#pragma unroll
        for (int pass = 0; pass <= HASAL; ++pass){
            const uint32_t tAp = tbase + pass*10240;
            uint32_t aH[4][4];
#pragma unroll
            for (int mt = 0; mt < 4; ++mt) ldsm4(aH[mt], tAp + aoff[mt] + kb);
#pragma unroll
            for (int mt = 0; mt < 4; ++mt)
#pragma unroll
                for (int nt = 0; nt < 4; ++nt) mma16816(acc[mt][nt], aH[mt], bX[nt]);
        }
    }
}

__device__ __forceinline__ void stage_acc(char* dyn, float acc[4][4][4],
                                          int wm, int wn, int quad, int lane2)
{
    float* stg = reinterpret_cast<float*>(dyn);
#pragma unroll
    for (int mt = 0; mt < 4; ++mt){
        const int r = wm*64 + mt*16 + quad;
#pragma unroll
        for (int nt = 0; nt < 4; ++nt){
            const int cc = wn*32 + nt*8 + lane2;
            stg[r*129 + cc]       = acc[mt][nt][0];
            stg[r*129 + cc + 1]   = acc[mt][nt][1];
            stg[(r+8)*129 + cc]   = acc[mt][nt][2];
            stg[(r+8)*129 + cc+1] = acc[mt][nt][3];
        }
    }
}

// per-lane ldmatrix offsets
__device__ __forceinline__ void frag_offsets(int l, int wm, int wn, uint32_t* aoff, uint32_t* boff){
    const int li8 = l & 7, lq = (l >> 3) & 1, lh = (l >> 4) & 1;
#pragma unroll
    for (int mt = 0; mt < 4; ++mt)
        aoff[mt] = (uint32_t)((wm*64 + mt*16 + li8 + lq*8)*80 + lh*16);
#pragma unroll
    for (int nt = 0; nt < 4; ++nt)
        boff[nt] = (uint32_t)((wn*32 + nt*8 + li8)*80 + lq*16);
}

// ---------------- generic GEMM: C[m,n] = sum_k A[m,k]*B[n,k] ----------------
// HASAL: add Al*Bh pass. mode 0: fp32 -> oF ; mode 1: fp16 hi -> oH
template<int HASAL>
__global__ void __launch_bounds__(256, 2) k_gemm(
    const hf* __restrict__ Ah, const hf* __restrict__ Al,
    long sA1, long sA2, long sA3, int lda,
    const hf* __restrict__ Bh, long sB1, long sB2, long sB3, int ldb,
    int K, int zm1, int zm2, int mode,
    float* __restrict__ oF, hf* __restrict__ oH,
    long sO1, long sO2, long sO3, int ldo)
{
    extern __shared__ char dyn[];
    const uint32_t smb = smem_u32(dyn);
    const int bufB = (2+HASAL)*10240;
    const int tid = threadIdx.x;
    const int l = tid & 31, wid = tid >> 5;
    const int wm = wid >> 2, wn = wid & 3;
    const int quad = l >> 2, lane2 = (l & 3) * 2;
    const int z = blockIdx.z;
    const int z1 = z / zm1, zr = z % zm1;
    const int z2 = zr / zm2, z3 = zr % zm2;
    const int m0 = blockIdx.x * 128, n0 = blockIdx.y * 128;
    const long offA = z1*sA1 + z2*sA2 + z3*sA3;
    const long offB = z1*sB1 + z2*sB2 + z3*sB3;
    const long offO = z1*sO1 + z2*sO2 + z3*sO3;

    const hf* pAh = Ah + offA + (size_t)m0*lda;
    const hf* pAl = HASAL ? (Al + offA + (size_t)m0*lda) : pAh;
    const hf* pBh = Bh + offB + (size_t)n0*ldb;

    float acc[4][4][4];
#pragma unroll
    for (int a = 0; a < 4; ++a)
#pragma unroll
        for (int b = 0; b < 4; ++b)
#pragma unroll
            for (int c = 0; c < 4; ++c) acc[a][b][c] = 0.f;

    const int NC = K / 32;

    auto copy_chunk = [&](int c, int bufi){
        const hf* srcs[3];
        int lds[3];
        int nt = 0;
        srcs[nt] = pAh + c*32; lds[nt] = lda; nt++;
        if (HASAL){ srcs[nt] = pAl + c*32; lds[nt] = lda; nt++; }
        srcs[nt] = pBh + c*32; lds[nt] = ldb; nt++;
#pragma unroll
        for (int t = 0; t < 2+HASAL; ++t){
            const uint32_t sb = smb + bufi*bufB + t*10240;
#pragma unroll
            for (int i = 0; i < 2; ++i){
                int e = tid + i*256;
                int row = e >> 2, cc = e & 3;
                cp16(sb + row*80 + cc*16, srcs[t] + (size_t)row*lds[t] + cc*8);
            }
        }
    };

    copy_chunk(0, 0);
    asm volatile("cp.async.commit_group;");

    uint32_t aoff[4], boff[4];
    frag_offsets(l, wm, wn, aoff, boff);

    for (int c = 0; c < NC; ++c){
        if (c + 1 < NC){
            copy_chunk(c+1, (c+1)&1);
            asm volatile("cp.async.commit_group;");
            asm volatile("cp.async.wait_group 1;");
        } else {
            asm volatile("cp.async.wait_group 0;");
        }
        __syncthreads();
        mma_tile<HASAL>(smb + (c&1)*bufB, aoff, boff, acc);
        __syncthreads();
    }

    stage_acc(dyn, acc, wm, wn, quad, lane2);
    __syncthreads();
    float* stg = reinterpret_cast<float*>(dyn);
    if (mode == 0){
        for (int idx = tid; idx < 16384; idx += 256){
            int r = idx >> 7, cc = idx & 127;
            oF[offO + (size_t)(m0+r)*ldo + n0 + cc] = stg[r*129 + cc];
        }
    } else {
        for (int idx = tid; idx < 16384; idx += 256){
            int r = idx >> 7, cc = idx & 127;
            oH[offO + (size_t)(m0+r)*ldo + n0 + cc] = __float2half_rn(stg[r*129 + cc]);
        }
    }
}

// ---------------- merged projection GEMM: 1-pass, all 6 stages in one launch ----------------
// z = stage*16 + (batch*4 + head). K fixed 256.
__global__ void __launch_bounds__(256, 2) k_proj(
    const float* __restrict__ e1, const float* __restrict__ ea,
    const float* __restrict__ ed, const float* __restrict__ eb,
    const hf* __restrict__ wq, const hf* __restrict__ wqd,
    const hf* __restrict__ wk, const hf* __restrict__ wkd,
    const hf* __restrict__ wv, const hf* __restrict__ wvd,
    hf* __restrict__ qAh, hf* __restrict__ qAl,
    hf* __restrict__ kBh, hf* __restrict__ vAh)
{
    extern __shared__ char dyn[];
    const uint32_t smb = smem_u32(dyn);
    const int tid = threadIdx.x;
    const int l = tid & 31, wid = tid >> 5;
    const int wm = wid >> 2, wn = wid & 3;
    const int quad = l >> 2, lane2 = (l & 3) * 2;
    const int z = blockIdx.z;
    const int s = z >> 4, zz = z & 15;
    const int z2 = zz >> 2, z3 = zz & 3;
    const int m0 = blockIdx.x * 128, n0 = blockIdx.y * 128;

    const float* A; const hf* W; hf* oH; hf* oL = 0; long sB3; int mode; int ldo;
    switch (s){
        case 0:  A = e1; W = wq;  sB3 = 65536; mode = 2; oH = qAh;            oL = qAl;            ldo = 4096; break;
        case 1:  A = ed; W = wqd; sB3 = 65536; mode = 2; oH = qAh + 16777216; oL = qAl + 16777216; ldo = 4096; break;
        case 2:  A = eb; W = wkd; sB3 = 0;     mode = 3; oH = kBh;                                 ldo = 4096; break;
        case 3:  A = ea; W = wk;  sB3 = 0;     mode = 3; oH = kBh + 16777216;                      ldo = 4096; break;
        case 4:  A = eb; W = wvd; sB3 = 0;     mode = 1; oH = vAh;                                 ldo = 256;  break;
        default: A = ea; W = wv;  sB3 = 0;     mode = 1; oH = vAh + 16777216;                      ldo = 256;  break;
    }
    const long offA = (long)z2*4194304 + (long)z3*256;
    const long offO = (long)z2*4194304 + (long)z3*1048576;
    const float* pA = A + offA + (size_t)m0*1024;
    const hf* pBh = W + z3*sB3 + (size_t)n0*256;

    float acc[4][4][4];
#pragma unroll
    for (int a = 0; a < 4; ++a)
#pragma unroll
        for (int b = 0; b < 4; ++b)
#pragma unroll
            for (int c = 0; c < 4; ++c) acc[a][b][c] = 0.f;

    auto copyB = [&](int c, int bufi){
        const uint32_t sb = smb + bufi*20480 + 10240;
#pragma unroll
        for (int i = 0; i < 2; ++i){
            int e = tid + i*256;
            int row = e >> 2, cc = e & 3;
            cp16(sb + row*80 + cc*16, pBh + c*32 + (size_t)row*256 + cc*8);
        }
    };
    auto ldgA = [&](float4* r, int c){
        const float* base = pA + c*32;
#pragma unroll
        for (int i = 0; i < 4; ++i){
            int e = tid + 256*i;
            int row = e >> 3, cg = e & 7;
            r[i] = *reinterpret_cast<const float4*>(base + (size_t)row*1024 + cg*4);
        }
    };
    auto stsA = [&](float4* r, int bufi){
        char* tA = dyn + bufi*20480;
#pragma unroll
        for (int i = 0; i < 4; ++i){
            int e = tid + 256*i;
            int row = e >> 3, cg = e & 7;
            float4 f = r[i];
            __half2 h0 = __floats2half2_rn(f.x, f.y);
            __half2 h1 = __floats2half2_rn(f.z, f.w);
            char* p = tA + row*80 + cg*8;
            *reinterpret_cast<__half2*>(p)     = h0;
            *reinterpret_cast<__half2*>(p + 4) = h1;
        }
    };

    uint32_t aoff[4], boff[4];
    frag_offsets(l, wm, wn, aoff, boff);

    float4 rA[4], rA2[4];
    ldgA(rA, 0);
    copyB(0, 0);
    asm volatile("cp.async.commit_group;");

    const int NC = 8;
    for (int c = 0; c < NC; ++c){
        stsA(rA, c & 1);
        if (c + 1 < NC){
            ldgA(rA2, c+1);
            copyB(c+1, (c+1)&1);
            asm volatile("cp.async.commit_group;");
            asm volatile("cp.async.wait_group 1;");
        } else {
            asm volatile("cp.async.wait_group 0;");
        }
        __syncthreads();
        mma_tile<0>(smb + (c&1)*20480, aoff, boff, acc);
        __syncthreads();
#pragma unroll
        for (int i = 0; i < 4; ++i) rA[i] = rA2[i];
    }

    stage_acc(dyn, acc, wm, wn, quad, lane2);
    __syncthreads();
    float* stg = reinterpret_cast<float*>(dyn);
    if (mode == 1){
        for (int idx = tid; idx < 16384; idx += 256){
            int r = idx >> 7, cc = idx & 127;
            oH[offO + (size_t)(m0+r)*ldo + n0 + cc] = __float2half_rn(stg[r*129 + cc]);
        }
    } else if (mode == 2){
        for (int idx = tid; idx < 16384; idx += 256){
            int cc = idx >> 7, r = idx & 127;
            hf h, lo; split2h(stg[r*129 + cc], h, lo);
            size_t o = offO + (size_t)(n0+cc)*ldo + m0 + r;
            oH[o] = h; oL[o] = lo;
        }
    } else {
        for (int idx = tid; idx < 16384; idx += 256){
            int cc = idx >> 7, r = idx & 127;
            oH[offO + (size_t)(n0+cc)*ldo + m0 + r] = __float2half_rn(stg[r*129 + cc]);
        }
    }
}

// ---------------- elementwise ----------------
__global__ void __launch_bounds__(256) k_splitW6(
    const float* __restrict__ Wq, const float* __restrict__ Wqd,
    const float* __restrict__ Wk, const float* __restrict__ Wkd,
    const float* __restrict__ Wv, const float* __restrict__ Wvd,
    hf* __restrict__ wqh, hf* __restrict__ wqdh,
    hf* __restrict__ wkh, hf* __restrict__ wkdh,
    hf* __restrict__ wvh, hf* __restrict__ wvdh)
{
    const int s = blockIdx.y;
    const float* src; hf* dst; int n;
    switch (s){
        case 0:  src = Wq;  dst = wqh;  n = 262144; break;
        case 1:  src = Wqd; dst = wqdh; n = 262144; break;
        case 2:  src = Wk;  dst = wkh;  n = 65536;  break;
        case 3:  src = Wkd; dst = wkdh; n = 65536;  break;
        case 4:  src = Wv;  dst = wvh;  n = 65536;  break;
        default: src = Wvd; dst = wvdh; n = 65536;  break;
    }
    int i = (blockIdx.x*256 + threadIdx.x) * 4;
    if (i >= n) return;
    float4 v = *reinterpret_cast<const float4*>(src + i);
    dst[i]   = __float2half_rn(v.x);
    dst[i+1] = __float2half_rn(v.y);
    dst[i+2] = __float2half_rn(v.z);
    dst[i+3] = __float2half_rn(v.w);
}
__global__ void __launch_bounds__(256) k_splitWo(const float* __restrict__ Wo,
                                                 const float* __restrict__ Wod,
                                                 hf* __restrict__ h){
    const float* s = blockIdx.y ? Wod : Wo;
    int idx = blockIdx.x*256 + threadIdx.x;
    int j = idx >> 10, t = idx & 1023;
    h[(size_t)blockIdx.y*1048576 + idx] =
        __float2half_rn(s[((size_t)j<<10) + ((t & 255)<<2) + (t>>8)]);
}
__global__ void __launch_bounds__(256) k_reduce(){
    int idx = blockIdx.x*256 + threadIdx.x;
    int pb = idx >> 20, r = idx & 1048575;
    const float* p = g_sp + (size_t)pb*8388608 + r;
    float s = 0.f;
#pragma unroll
    for (int sl = 0; sl < 8; ++sl) s += p[(size_t)sl*1048576];
    g_s[idx] = s * SCALEV;
}
__global__ void __launch_bounds__(256) k_moments(){
    const int idx = blockIdx.x;
    const float* s = g_s + (size_t)idx*65536;
    __shared__ float sh[256], sh2[256];
    float sum = 0.f, sq = 0.f;
    for (int i = threadIdx.x; i < 65536; i += 256){ float v = s[i]; sum += v; sq = fmaf(v,v,sq); }
    sh[threadIdx.x] = sum; sh2[threadIdx.x] = sq;
    __syncthreads();
    for (int o = 128; o; o >>= 1){
        if (threadIdx.x < o){ sh[threadIdx.x] += sh[threadIdx.x+o]; sh2[threadIdx.x] += sh2[threadIdx.x+o]; }
        __syncthreads();
    }
    if (threadIdx.x == 0){
        float m = sh[0]*(1.f/65536.f);
        g_mv[idx*2] = m;
        g_mv[idx*2+1] = sh2[0]*(1.f/65536.f) - m*m;
    }
}
__global__ void __launch_bounds__(256) k_softmax(){
    const int pb = blockIdx.z*16 + blockIdx.y;
    const size_t rb = ((size_t)pb*256 + blockIdx.x)*256;
    const float mean = g_mv[pb*2];
    const float inv  = rsqrtf(g_mv[pb*2+1] + EPSV);
    const int tid = threadIdx.x;
    float y = (g_s[rb + tid] - mean) * inv;
    __shared__ float red[8];
    float m = y;
#pragma unroll
    for (int o = 16; o; o >>= 1) m = fmaxf(m, __shfl_xor_sync(~0u, m, o));
    if ((tid & 31) == 0) red[tid>>5] = m;
    __syncthreads();
    if (tid == 0){ float mm = red[0]; for (int i=1;i<8;++i) mm = fmaxf(mm, red[i]); red[0] = mm; }
    __syncthreads();
    float e = expf(y - red[0]);
    __syncthreads();
    float ssum = e;
#pragma unroll
    for (int o = 16; o; o >>= 1) ssum += __shfl_xor_sync(~0u, ssum, o);
    if ((tid & 31) == 0) red[tid>>5] = ssum;
    __syncthreads();
    if (tid == 0){ float t = 0.f; for (int i=0;i<8;++i) t += red[i]; red[0] = t; }
    __syncthreads();
    g_ph[rb + tid] = __float2half_rn(e / red[0]);
}

// ---------------- launch ----------------
static void* dsym(const void* s){ void* p = 0; cudaGetSymbolAddress(&p, s); return p; }

extern "C" void kernel_launch(void* const* d_in, const int* in_sizes, int n_in,
                              void* d_out, int out_size)
{
    const float* emb1     = (const float*)d_in[0];
    const float* emb_all  = (const float*)d_in[1];
    const float* embd1    = (const float*)d_in[2];
    const float* emb_alld = (const float*)d_in[3];
    const float* Wq = (const float*)d_in[4];  const float* Wqd = (const float*)d_in[5];
    const float* Wk = (const float*)d_in[6];  const float* Wv  = (const float*)d_in[7];
    const float* Wkd= (const float*)d_in[8];  const float* Wvd = (const float*)d_in[9];
    const float* Wo = (const float*)d_in[10]; const float* Wod = (const float*)d_in[11];
    float* out = (float*)d_out;

    const int SM = 66048;
    cudaFuncSetAttribute(k_gemm<1>, cudaFuncAttributeMaxDynamicSharedMemorySize, SM);
    cudaFuncSetAttribute(k_gemm<0>, cudaFuncAttributeMaxDynamicSharedMemorySize, SM);
    cudaFuncSetAttribute(k_proj,    cudaFuncAttributeMaxDynamicSharedMemorySize, SM);

#define GH(x) ((hf*)dsym(x))
    hf *qAh = GH(g_qAh), *qAl = GH(g_qAl);
    hf *kBh = GH(g_kBh), *vAh = GH(g_vAh);
    hf *ch = GH(g_ch), *ph = GH(g_ph), *woh = GH(g_woh);
    float* sp = (float*)dsym(g_sp);

    // weight conversions (merged)
    k_splitW6<<<dim3(256,6),256>>>(Wq,Wqd,Wk,Wkd,Wv,Wvd,
                                   GH(g_wqh),GH(g_wqdh),GH(g_wkh),GH(g_wkdh),GH(g_wvh),GH(g_wvdh));
    k_splitWo<<<dim3(4096,2),256>>>(Wo, Wod, woh);

    // projections: 1-pass, all 6 stages in one launch
    k_proj<<<dim3(32,2,96),256,SM>>>(emb1, emb_all, embd1, emb_alld,
                                     GH(g_wqh),GH(g_wqdh),GH(g_wkh),GH(g_wkdh),GH(g_wvh),GH(g_wvdh),
                                     qAh, qAl, kBh, vAh);

    // scores: 2-pass (Q pairs x K hi), split-K x8, one launch
    dim3 gsc(2,2,256);
    k_gemm<1><<<gsc,256,SM>>>(qAh,qAl, 16777216,1048576,512, 4096,
                              kBh, 16777216,1048576,512, 4096,
                              512, 128,8, 0,
                              sp, (hf*)0, 8388608,65536,1048576, 256);
    k_reduce<<<8192,256>>>();
    k_moments<<<32,256>>>();
    k_softmax<<<dim3(256,16,2),256>>>();

    // ctx: 1-pass (V hi x probs hi), both paths in one launch
    dim3 gc(32,2,32);
    k_gemm<0><<<gc,256,SM>>>(vAh,(hf*)0, 16777216,4194304,1048576, 256,
                             ph, 1048576,262144,65536, 256,
                             256, 16,4, 1,
                             (float*)0, ch, 16777216,4194304,256, 1024);

    // out: 1-pass (ctx hi x Wo hi), both paths in one launch
    dim3 go(128,8,2);
    k_gemm<0><<<go,256,SM>>>(ch,(hf*)0, 16777216,0,0, 1024,
                             woh, 1048576,0,0, 1024,
                             1024, 1,1, 0,
                             out, (hf*)0, 16777216,0,0, 1024);
#undef GH
}

// round 12
// speedup vs baseline: 7.0053x; 1.0497x over previous
#include <cuda_runtime.h>
#include <cuda_fp16.h>
#include <stdint.h>
#include <math.h>

typedef __half hf;

#define EPSV 1e-5f
#define SCALEV 0.03125f

// ---------------- scratch ----------------
__device__ __align__(16) hf g_qAh[33554432], g_qAl[33554432];  // Qt pairs [path][bh][c][n]
__device__ __align__(16) hf g_kBh[33554432];                   // [Kdt; Kt] hi
__device__ __align__(16) hf g_vAh[33554432];                   // [Vd; V] hi [bh][n][k]
__device__ __align__(16) hf g_wqh[262144], g_wqdh[262144];
__device__ __align__(16) hf g_wkh[65536], g_wvh[65536], g_wkdh[65536], g_wvdh[65536];
__device__ __align__(16) hf g_woh[2097152];                    // blocked, both paths
__device__ __align__(16) float g_sp[16777216];                 // score partials
__device__ __align__(16) float g_s[2097152];
__device__ __align__(16) hf g_ph[2097152];
__device__ __align__(16) hf g_ch[33554432];                    // ctx fp16 blocked, both paths
__device__ float g_mv[64];

// ---------------- helpers ----------------
__device__ __forceinline__ uint32_t smem_u32(const void* p){
    uint32_t a;
    asm("{ .reg .u64 t; cvta.to.shared.u64 t, %1; cvt.u32.u64 %0, t; }" : "=r"(a) : "l"(p));
    return a;
}
__device__ __forceinline__ void cp16(uint32_t sa, const void* g){
    asm volatile("cp.async.cg.shared.global [%0], [%1], 16;" :: "r"(sa), "l"(g));
}
__device__ __forceinline__ void mma16816(float* d, const uint32_t* a, const uint32_t* b){
    asm volatile("mma.sync.aligned.m16n8k16.row.col.f32.f16.f16.f32 "
        "{%0,%1,%2,%3}, {%4,%5,%6,%7}, {%8,%9}, {%0,%1,%2,%3};"
        : "+f"(d[0]),"+f"(d[1]),"+f"(d[2]),"+f"(d[3])
        : "r"(a[0]),"r"(a[1]),"r"(a[2]),"r"(a[3]),"r"(b[0]),"r"(b[1]));
}
__device__ __forceinline__ void ldsm4(uint32_t* r, uint32_t addr){
    asm volatile("ldmatrix.sync.aligned.m8n8.x4.shared.b16 {%0,%1,%2,%3}, [%4];"
        : "=r"(r[0]),"=r"(r[1]),"=r"(r[2]),"=r"(r[3]) : "r"(addr));
}
__device__ __forceinline__ void ldsm2(uint32_t* r, uint32_t addr){
    asm volatile("ldmatrix.sync.aligned.m8n8.x2.shared.b16 {%0,%1}, [%2];"
        : "=r"(r[0]),"=r"(r[1]) : "r"(addr));
}
__device__ __forceinline__ void split2h(float v, hf& h, hf& l){
    h = __float2half_rn(v);
    l = __float2half_rn(v - __half2float(h));
}

// inner mma over one chunk via ldmatrix.
// PITCH: tile row pitch bytes; TILEB: tile bytes; NKS: k16 steps per chunk.
template<int HASAL, int PITCH, int TILEB, int NKS>
__device__ __forceinline__ void mma_tile(uint32_t tbase, const uint32_t* aoff, const uint32_t* boff,
                                         float acc[4][4][4])
{
    const uint32_t tB = tbase + (1+HASAL)*TILEB;
#pragma unroll
    for (int ks = 0; ks < NKS; ++ks){
        const int kb = ks * 32;
        uint32_t bX[4][2];
#pragma unroll
        for (int nt = 0; nt < 4; ++nt) ldsm2(bX[nt], tB + boff[nt] + kb);
#pragma unroll
        for (int pass = 0; pass <= HASAL; ++pass){
            const uint32_t tAp = tbase + pass*TILEB;
            uint32_t aH[4][4];
#pragma unroll
            for (int mt = 0; mt < 4; ++mt) ldsm4(aH[mt], tAp + aoff[mt] + kb);
#pragma unroll
            for (int mt = 0; mt < 4; ++mt)
#pragma unroll
                for (int nt = 0; nt < 4; ++nt) mma16816(acc[mt][nt], aH[mt], bX[nt]);
        }
    }
}

__device__ __forceinline__ void stage_acc(char* dyn, float acc[4][4][4],
                                          int wm, int wn, int quad, int lane2)
{
    float* stg = reinterpret_cast<float*>(dyn);
#pragma unroll
    for (int mt = 0; mt < 4; ++mt){
        const int r = wm*64 + mt*16 + quad;
#pragma unroll
        for (int nt = 0; nt < 4; ++nt){
            const int cc = wn*32 + nt*8 + lane2;
            stg[r*129 + cc]       = acc[mt][nt][0];
            stg[r*129 + cc + 1]   = acc[mt][nt][1];
            stg[(r+8)*129 + cc]   = acc[mt][nt][2];
            stg[(r+8)*129 + cc+1] = acc[mt][nt][3];
        }
    }
}

// per-lane ldmatrix offsets, parametric pitch
template<int PITCH>
__device__ __forceinline__ void frag_offsets(int l, int wm, int wn, uint32_t* aoff, uint32_t* boff){
    const int li8 = l & 7, lq = (l >> 3) & 1, lh = (l >> 4) & 1;
#pragma unroll
    for (int mt = 0; mt < 4; ++mt)
        aoff[mt] = (uint32_t)((wm*64 + mt*16 + li8 + lq*8)*PITCH + lh*16);
#pragma unroll
    for (int nt = 0; nt < 4; ++nt)
        boff[nt] = (uint32_t)((wn*32 + nt*8 + li8)*PITCH + lq*16);
}

// ---------------- generic GEMM, BK=64: C[m,n] = sum_k A[m,k]*B[n,k] ----------------
// HASAL: add Al*Bh pass. mode 0: fp32 -> oF ; mode 1: fp16 hi -> oH
template<int HASAL>
__global__ void __launch_bounds__(256, 2) k_gemm(
    const hf* __restrict__ Ah, const hf* __restrict__ Al,
    long sA1, long sA2, long sA3, int lda,
    const hf* __restrict__ Bh, long sB1, long sB2, long sB3, int ldb,
    int K, int zm1, int zm2, int mode,
    float* __restrict__ oF, hf* __restrict__ oH,
    long sO1, long sO2, long sO3, int ldo)
{
    const int PITCH = 144, TILEB = 18432;
    extern __shared__ char dyn[];
    const uint32_t smb = smem_u32(dyn);
    const int bufB = (2+HASAL)*TILEB;
    const int tid = threadIdx.x;
    const int l = tid & 31, wid = tid >> 5;
    const int wm = wid >> 2, wn = wid & 3;
    const int quad = l >> 2, lane2 = (l & 3) * 2;
    const int z = blockIdx.z;
    const int z1 = z / zm1, zr = z % zm1;
    const int z2 = zr / zm2, z3 = zr % zm2;
    const int m0 = blockIdx.x * 128, n0 = blockIdx.y * 128;
    const long offA = z1*sA1 + z2*sA2 + z3*sA3;
    const long offB = z1*sB1 + z2*sB2 + z3*sB3;
    const long offO = z1*sO1 + z2*sO2 + z3*sO3;

    const hf* pAh = Ah + offA + (size_t)m0*lda;
    const hf* pAl = HASAL ? (Al + offA + (size_t)m0*lda) : pAh;
    const hf* pBh = Bh + offB + (size_t)n0*ldb;

    float acc[4][4][4];
#pragma unroll
    for (int a = 0; a < 4; ++a)
#pragma unroll
        for (int b = 0; b < 4; ++b)
#pragma unroll
            for (int c = 0; c < 4; ++c) acc[a][b][c] = 0.f;

    const int NC = K / 64;

    // copy one 128x64 hf tile set (BK=64 -> 128 rows x 8 x 16B per tile)
    auto copy_chunk = [&](int c, int bufi){
        const hf* srcs[3];
        int lds[3];
        int nt = 0;
        srcs[nt] = pAh + c*64; lds[nt] = lda; nt++;
        if (HASAL){ srcs[nt] = pAl + c*64; lds[nt] = lda; nt++; }
        srcs[nt] = pBh + c*64; lds[nt] = ldb; nt++;
#pragma unroll
        for (int t = 0; t < 2+HASAL; ++t){
            const uint32_t sb = smb + bufi*bufB + t*TILEB;
#pragma unroll
            for (int i = 0; i < 4; ++i){
                int e = tid + i*256;            // 0..1023
                int row = e >> 3, cc = e & 7;
                cp16(sb + row*PITCH + cc*16, srcs[t] + (size_t)row*lds[t] + cc*8);
            }
        }
    };

    copy_chunk(0, 0);
    asm volatile("cp.async.commit_group;");

    uint32_t aoff[4], boff[4];
    frag_offsets<PITCH>(l, wm, wn, aoff, boff);

    for (int c = 0; c < NC; ++c){
        if (c + 1 < NC){
            copy_chunk(c+1, (c+1)&1);
            asm volatile("cp.async.commit_group;");
            asm volatile("cp.async.wait_group 1;");
        } else {
            asm volatile("cp.async.wait_group 0;");
        }
        __syncthreads();
        mma_tile<HASAL, PITCH, TILEB, 4>(smb + (c&1)*bufB, aoff, boff, acc);
        __syncthreads();
    }

    stage_acc(dyn, acc, wm, wn, quad, lane2);
    __syncthreads();
    float* stg = reinterpret_cast<float*>(dyn);
    if (mode == 0){
        for (int idx = tid; idx < 16384; idx += 256){
            int r = idx >> 7, cc = idx & 127;
            oF[offO + (size_t)(m0+r)*ldo + n0 + cc] = stg[r*129 + cc];
        }
    } else {
        for (int idx = tid; idx < 16384; idx += 256){
            int r = idx >> 7, cc = idx & 127;
            oH[offO + (size_t)(m0+r)*ldo + n0 + cc] = __float2half_rn(stg[r*129 + cc]);
        }
    }
}

// ---------------- merged projection GEMM: 1-pass, all 6 stages, BK=32 ----------------
// z = stage*16 + (batch*4 + head). K fixed 256.
__global__ void __launch_bounds__(256, 2) k_proj(
    const float* __restrict__ e1, const float* __restrict__ ea,
    const float* __restrict__ ed, const float* __restrict__ eb,
    const hf* __restrict__ wq, const hf* __restrict__ wqd,
    const hf* __restrict__ wk, const hf* __restrict__ wkd,
    const hf* __restrict__ wv, const hf* __restrict__ wvd,
    hf* __restrict__ qAh, hf* __restrict__ qAl,
    hf* __restrict__ kBh, hf* __restrict__ vAh)
{
    extern __shared__ char dyn[];
    const uint32_t smb = smem_u32(dyn);
    const int tid = threadIdx.x;
    const int l = tid & 31, wid = tid >> 5;
    const int wm = wid >> 2, wn = wid & 3;
    const int quad = l >> 2, lane2 = (l & 3) * 2;
    const int z = blockIdx.z;
    const int s = z >> 4, zz = z & 15;
    const int z2 = zz >> 2, z3 = zz & 3;
    const int m0 = blockIdx.x * 128, n0 = blockIdx.y * 128;

    const float* A; const hf* W; hf* oH; hf* oL = 0; long sB3; int mode; int ldo;
    switch (s){
        case 0:  A = e1; W = wq;  sB3 = 65536; mode = 2; oH = qAh;            oL = qAl;            ldo = 4096; break;
        case 1:  A = ed; W = wqd; sB3 = 65536; mode = 2; oH = qAh + 16777216; oL = qAl + 16777216; ldo = 4096; break;
        case 2:  A = eb; W = wkd; sB3 = 0;     mode = 3; oH = kBh;                                 ldo = 4096; break;
        case 3:  A = ea; W = wk;  sB3 = 0;     mode = 3; oH = kBh + 16777216;                      ldo = 4096; break;
        case 4:  A = eb; W = wvd; sB3 = 0;     mode = 1; oH = vAh;                                 ldo = 256;  break;
        default: A = ea; W = wv;  sB3 = 0;     mode = 1; oH = vAh + 16777216;                      ldo = 256;  break;
    }
    const long offA = (long)z2*4194304 + (long)z3*256;
    const long offO = (long)z2*4194304 + (long)z3*1048576;
    const float* pA = A + offA + (size_t)m0*1024;
    const hf* pBh = W + z3*sB3 + (size_t)n0*256;

    float acc[4][4][4];
#pragma unroll
    for (int a = 0; a < 4; ++a)
#pragma unroll
        for (int b = 0; b < 4; ++b)
#pragma unroll
            for (int c = 0; c < 4; ++c) acc[a][b][c] = 0.f;

    auto copyB = [&](int c, int bufi){
        const uint32_t sb = smb + bufi*20480 + 10240;
#pragma unroll
        for (int i = 0; i < 2; ++i){
            int e = tid + i*256;
            int row = e >> 2, cc = e & 3;
            cp16(sb + row*80 + cc*16, pBh + c*32 + (size_t)row*256 + cc*8);
        }
    };
    auto ldgA = [&](float4* r, int c){
        const float* base = pA + c*32;
#pragma unroll
        for (int i = 0; i < 4; ++i){
            int e = tid + 256*i;
            int row = e >> 3, cg = e & 7;
            r[i] = *reinterpret_cast<const float4*>(base + (size_t)row*1024 + cg*4);
        }
    };
    auto stsA = [&](float4* r, int bufi){
        char* tA = dyn + bufi*20480;
#pragma unroll
        for (int i = 0; i < 4; ++i){
            int e = tid + 256*i;
            int row = e >> 3, cg = e & 7;
            float4 f = r[i];
            __half2 h0 = __floats2half2_rn(f.x, f.y);
            __half2 h1 = __floats2half2_rn(f.z, f.w);
            char* p = tA + row*80 + cg*8;
            *reinterpret_cast<__half2*>(p)     = h0;
            *reinterpret_cast<__half2*>(p + 4) = h1;
        }
    };

    uint32_t aoff[4], boff[4];
    frag_offsets<80>(l, wm, wn, aoff, boff);

    float4 rA[4], rA2[4];
    ldgA(rA, 0);
    copyB(0, 0);
    asm volatile("cp.async.commit_group;");

    const int NC = 8;
    for (int c = 0; c < NC; ++c){
        stsA(rA, c & 1);
        if (c + 1 < NC){
            ldgA(rA2, c+1);
            copyB(c+1, (c+1)&1);
            asm volatile("cp.async.commit_group;");
            asm volatile("cp.async.wait_group 1;");
        } else {
            asm volatile("cp.async.wait_group 0;");
        }
        __syncthreads();
        mma_tile<0, 80, 10240, 2>(smb + (c&1)*20480, aoff, boff, acc);
        __syncthreads();
#pragma unroll
        for (int i = 0; i < 4; ++i) rA[i] = rA2[i];
    }

    stage_acc(dyn, acc, wm, wn, quad, lane2);
    __syncthreads();
    float* stg = reinterpret_cast<float*>(dyn);
    if (mode == 1){
        for (int idx = tid; idx < 16384; idx += 256){
            int r = idx >> 7, cc = idx & 127;
            oH[offO + (size_t)(m0+r)*ldo + n0 + cc] = __float2half_rn(stg[r*129 + cc]);
        }
    } else if (mode == 2){
        for (int idx = tid; idx < 16384; idx += 256){
            int cc = idx >> 7, r = idx & 127;
            hf h, lo; split2h(stg[r*129 + cc], h, lo);
            size_t o = offO + (size_t)(n0+cc)*ldo + m0 + r;
            oH[o] = h; oL[o] = lo;
        }
    } else {
        for (int idx = tid; idx < 16384; idx += 256){
            int cc = idx >> 7, r = idx & 127;
            oH[offO + (size_t)(n0+cc)*ldo + m0 + r] = __float2half_rn(stg[r*129 + cc]);
        }
    }
}

// ---------------- elementwise ----------------
__global__ void __launch_bounds__(256) k_splitW6(
    const float* __restrict__ Wq, const float* __restrict__ Wqd,
    const float* __restrict__ Wk, const float* __restrict__ Wkd,
    const float* __restrict__ Wv, const float* __restrict__ Wvd,
    hf* __restrict__ wqh, hf* __restrict__ wqdh,
    hf* __restrict__ wkh, hf* __restrict__ wkdh,
    hf* __restrict__ wvh, hf* __restrict__ wvdh)
{
    const int s = blockIdx.y;
    const float* src; hf* dst; int n;
    switch (s){
        case 0:  src = Wq;  dst = wqh;  n = 262144; break;
        case 1:  src = Wqd; dst = wqdh; n = 262144; break;
        case 2:  src = Wk;  dst = wkh;  n = 65536;  break;
        case 3:  src = Wkd; dst = wkdh; n = 65536;  break;
        case 4:  src = Wv;  dst = wvh;  n = 65536;  break;
        default: src = Wvd; dst = wvdh; n = 65536;  break;
    }
    int i = (blockIdx.x*256 + threadIdx.x) * 4;
    if (i >= n) return;
    float4 v = *reinterpret_cast<const float4*>(src + i);
    dst[i]   = __float2half_rn(v.x);
    dst[i+1] = __float2half_rn(v.y);
    dst[i+2] = __float2half_rn(v.z);
    dst[i+3] = __float2half_rn(v.w);
}
__global__ void __launch_bounds__(256) k_splitWo(const float* __restrict__ Wo,
                                                 const float* __restrict__ Wod,
                                                 hf* __restrict__ h){
    const float* s = blockIdx.y ? Wod : Wo;
    int idx = blockIdx.x*256 + threadIdx.x;
    int j = idx >> 10, t = idx & 1023;
    h[(size_t)blockIdx.y*1048576 + idx] =
        __float2half_rn(s[((size_t)j<<10) + ((t & 255)<<2) + (t>>8)]);
}
__global__ void __launch_bounds__(256) k_reduce(){
    int idx = blockIdx.x*256 + threadIdx.x;
    int pb = idx >> 20, r = idx & 1048575;
    const float* p = g_sp + (size_t)pb*8388608 + r;
    float s = 0.f;
#pragma unroll
    for (int sl = 0; sl < 8; ++sl) s += p[(size_t)sl*1048576];
    g_s[idx] = s * SCALEV;
}
__global__ void __launch_bounds__(256) k_moments(){
    const int idx = blockIdx.x;
    const float* s = g_s + (size_t)idx*65536;
    __shared__ float sh[256], sh2[256];
    float sum = 0.f, sq = 0.f;
    for (int i = threadIdx.x; i < 65536; i += 256){ float v = s[i]; sum += v; sq = fmaf(v,v,sq); }
    sh[threadIdx.x] = sum; sh2[threadIdx.x] = sq;
    __syncthreads();
    for (int o = 128; o; o >>= 1){
        if (threadIdx.x < o){ sh[threadIdx.x] += sh[threadIdx.x+o]; sh2[threadIdx.x] += sh2[threadIdx.x+o]; }
        __syncthreads();
    }
    if (threadIdx.x == 0){
        float m = sh[0]*(1.f/65536.f);
        g_mv[idx*2] = m;
        g_mv[idx*2+1] = sh2[0]*(1.f/65536.f) - m*m;
    }
}
__global__ void __launch_bounds__(256) k_softmax(){
    const int pb = blockIdx.z*16 + blockIdx.y;
    const size_t rb = ((size_t)pb*256 + blockIdx.x)*256;
    const float mean = g_mv[pb*2];
    const float inv  = rsqrtf(g_mv[pb*2+1] + EPSV);
    const int tid = threadIdx.x;
    float y = (g_s[rb + tid] - mean) * inv;
    __shared__ float red[8];
    float m = y;
#pragma unroll
    for (int o = 16; o; o >>= 1) m = fmaxf(m, __shfl_xor_sync(~0u, m, o));
    if ((tid & 31) == 0) red[tid>>5] = m;
    __syncthreads();
    if (tid == 0){ float mm = red[0]; for (int i=1;i<8;++i) mm = fmaxf(mm, red[i]); red[0] = mm; }
    __syncthreads();
    float e = expf(y - red[0]);
    __syncthreads();
    float ssum = e;
#pragma unroll
    for (int o = 16; o; o >>= 1) ssum += __shfl_xor_sync(~0u, ssum, o);
    if ((tid & 31) == 0) red[tid>>5] = ssum;
    __syncthreads();
    if (tid == 0){ float t = 0.f; for (int i=0;i<8;++i) t += red[i]; red[0] = t; }
    __syncthreads();
    g_ph[rb + tid] = __float2half_rn(e / red[0]);
}

// ---------------- launch ----------------
static void* dsym(const void* s){ void* p = 0; cudaGetSymbolAddress(&p, s); return p; }

extern "C" void kernel_launch(void* const* d_in, const int* in_sizes, int n_in,
                              void* d_out, int out_size)
{
    const float* emb1     = (const float*)d_in[0];
    const float* emb_all  = (const float*)d_in[1];
    const float* embd1    = (const float*)d_in[2];
    const float* emb_alld = (const float*)d_in[3];
    const float* Wq = (const float*)d_in[4];  const float* Wqd = (const float*)d_in[5];
    const float* Wk = (const float*)d_in[6];  const float* Wv  = (const float*)d_in[7];
    const float* Wkd= (const float*)d_in[8];  const float* Wvd = (const float*)d_in[9];
    const float* Wo = (const float*)d_in[10]; const float* Wod = (const float*)d_in[11];
    float* out = (float*)d_out;

    const int SM1 = 110592;   // k_gemm<1>: 2 buf x 3 tiles x 18432
    const int SM0 = 73728;    // k_gemm<0>: 2 buf x 2 tiles x 18432 (>= 66048 epilogue)
    const int SMP = 66048;    // k_proj (2 x 20480 buffers, 66KB epilogue)
    cudaFuncSetAttribute(k_gemm<1>, cudaFuncAttributeMaxDynamicSharedMemorySize, SM1);
    cudaFuncSetAttribute(k_gemm<0>, cudaFuncAttributeMaxDynamicSharedMemorySize, SM0);
    cudaFuncSetAttribute(k_proj,    cudaFuncAttributeMaxDynamicSharedMemorySize, SMP);

#define GH(x) ((hf*)dsym(x))
    hf *qAh = GH(g_qAh), *qAl = GH(g_qAl);
    hf *kBh = GH(g_kBh), *vAh = GH(g_vAh);
    hf *ch = GH(g_ch), *ph = GH(g_ph), *woh = GH(g_woh);
    float* sp = (float*)dsym(g_sp);

    // weight conversions (merged)
    k_splitW6<<<dim3(256,6),256>>>(Wq,Wqd,Wk,Wkd,Wv,Wvd,
                                   GH(g_wqh),GH(g_wqdh),GH(g_wkh),GH(g_wkdh),GH(g_wvh),GH(g_wvdh));
    k_splitWo<<<dim3(4096,2),256>>>(Wo, Wod, woh);

    // projections: 1-pass, all 6 stages in one launch
    k_proj<<<dim3(32,2,96),256,SMP>>>(emb1, emb_all, embd1, emb_alld,
                                      GH(g_wqh),GH(g_wqdh),GH(g_wkh),GH(g_wkdh),GH(g_wvh),GH(g_wvdh),
                                      qAh, qAl, kBh, vAh);

    // scores: 2-pass (Q pairs x K hi), split-K x8, one launch
    dim3 gsc(2,2,256);
    k_gemm<1><<<gsc,256,SM1>>>(qAh,qAl, 16777216,1048576,512, 4096,
                               kBh, 16777216,1048576,512, 4096,
                               512, 128,8, 0,
                               sp, (hf*)0, 8388608,65536,1048576, 256);
    k_reduce<<<8192,256>>>();
    k_moments<<<32,256>>>();
    k_softmax<<<dim3(256,16,2),256>>>();

    // ctx: 1-pass (V hi x probs hi), both paths in one launch
    dim3 gc(32,2,32);
    k_gemm<0><<<gc,256,SM0>>>(vAh,(hf*)0, 16777216,4194304,1048576, 256,
                              ph, 1048576,262144,65536, 256,
                              256, 16,4, 1,
                              (float*)0, ch, 16777216,4194304,256, 1024);

    // out: 1-pass (ctx hi x Wo hi), both paths in one launch
    dim3 go(128,8,2);
    k_gemm<0><<<go,256,SM0>>>(ch,(hf*)0, 16777216,0,0, 1024,
                              woh, 1048576,0,0, 1024,
                              1024, 1,1, 0,
                              out, (hf*)0, 16777216,0,0, 1024);
#undef GH
}

// round 13
// speedup vs baseline: 7.4950x; 1.0699x over previous
#include <cuda_runtime.h>
#include <cuda_fp16.h>
#include <stdint.h>
#include <math.h>

typedef __half hf;

#define EPSV 1e-5f
#define SCALEV 0.03125f

// ---------------- scratch ----------------
__device__ __align__(16) hf g_qAh[33554432];                   // Qt hi [path][bh][c][n]
__device__ __align__(16) hf g_kBh[33554432];                   // [Kdt; Kt] hi
__device__ __align__(16) hf g_vAh[33554432];                   // [Vd; V] hi [bh][n][k]
__device__ __align__(16) hf g_wqh[262144], g_wqdh[262144];
__device__ __align__(16) hf g_wkh[65536], g_wvh[65536], g_wkdh[65536], g_wvdh[65536];
__device__ __align__(16) hf g_woh[2097152];                    // blocked, both paths
__device__ __align__(16) float g_sp[16777216];                 // score partials
__device__ __align__(16) float g_s[2097152];
__device__ __align__(16) hf g_ph[2097152];
__device__ __align__(16) hf g_ch[33554432];                    // ctx fp16 blocked, both paths
__device__ float g_mv[64];

// ---------------- helpers ----------------
__device__ __forceinline__ uint32_t smem_u32(const void* p){
    uint32_t a;
    asm("{ .reg .u64 t; cvta.to.shared.u64 t, %1; cvt.u32.u64 %0, t; }" : "=r"(a) : "l"(p));
    return a;
}
__device__ __forceinline__ void cp16(uint32_t sa, const void* g){
    asm volatile("cp.async.cg.shared.global [%0], [%1], 16;" :: "r"(sa), "l"(g));
}
__device__ __forceinline__ void mma16816(float* d, const uint32_t* a, const uint32_t* b){
    asm volatile("mma.sync.aligned.m16n8k16.row.col.f32.f16.f16.f32 "
        "{%0,%1,%2,%3}, {%4,%5,%6,%7}, {%8,%9}, {%0,%1,%2,%3};"
        : "+f"(d[0]),"+f"(d[1]),"+f"(d[2]),"+f"(d[3])
        : "r"(a[0]),"r"(a[1]),"r"(a[2]),"r"(a[3]),"r"(b[0]),"r"(b[1]));
}
__device__ __forceinline__ void ldsm4(uint32_t* r, uint32_t addr){
    asm volatile("ldmatrix.sync.aligned.m8n8.x4.shared.b16 {%0,%1,%2,%3}, [%4];"
        : "=r"(r[0]),"=r"(r[1]),"=r"(r[2]),"=r"(r[3]) : "r"(addr));
}
__device__ __forceinline__ void ldsm2(uint32_t* r, uint32_t addr){
    asm volatile("ldmatrix.sync.aligned.m8n8.x2.shared.b16 {%0,%1}, [%2];"
        : "=r"(r[0]),"=r"(r[1]) : "r"(addr));
}

// inner mma over one chunk via ldmatrix.
// PITCH: tile row pitch bytes; TILEB: tile bytes; NKS: k16 steps per chunk.
template<int HASAL, int PITCH, int TILEB, int NKS>
__device__ __forceinline__ void mma_tile(uint32_t tbase, const uint32_t* aoff, const uint32_t* boff,
                                         float acc[4][4][4])
{
    const uint32_t tB = tbase + (1+HASAL)*TILEB;
#pragma unroll
    for (int ks = 0; ks < NKS; ++ks){
        const int kb = ks * 32;
        uint32_t bX[4][2];
#pragma unroll
        for (int nt = 0; nt < 4; ++nt) ldsm2(bX[nt], tB + boff[nt] + kb);
#pragma unroll
        for (int pass = 0; pass <= HASAL; ++pass){
            const uint32_t tAp = tbase + pass*TILEB;
            uint32_t aH[4][4];
#pragma unroll
            for (int mt = 0; mt < 4; ++mt) ldsm4(aH[mt], tAp + aoff[mt] + kb);
#pragma unroll
            for (int mt = 0; mt < 4; ++mt)
#pragma unroll
                for (int nt = 0; nt < 4; ++nt) mma16816(acc[mt][nt], aH[mt], bX[nt]);
        }
    }
}

__device__ __forceinline__ void stage_acc(char* dyn, float acc[4][4][4],
                                          int wm, int wn, int quad, int lane2)
{
    float* stg = reinterpret_cast<float*>(dyn);
#pragma unroll
    for (int mt = 0; mt < 4; ++mt){
        const int r = wm*64 + mt*16 + quad;
#pragma unroll
        for (int nt = 0; nt < 4; ++nt){
            const int cc = wn*32 + nt*8 + lane2;
            stg[r*129 + cc]       = acc[mt][nt][0];
            stg[r*129 + cc + 1]   = acc[mt][nt][1];
            stg[(r+8)*129 + cc]   = acc[mt][nt][2];
            stg[(r+8)*129 + cc+1] = acc[mt][nt][3];
        }
    }
}

// per-lane ldmatrix offsets, parametric pitch
template<int PITCH>
__device__ __forceinline__ void frag_offsets(int l, int wm, int wn, uint32_t* aoff, uint32_t* boff){
    const int li8 = l & 7, lq = (l >> 3) & 1, lh = (l >> 4) & 1;
#pragma unroll
    for (int mt = 0; mt < 4; ++mt)
        aoff[mt] = (uint32_t)((wm*64 + mt*16 + li8 + lq*8)*PITCH + lh*16);
#pragma unroll
    for (int nt = 0; nt < 4; ++nt)
        boff[nt] = (uint32_t)((wn*32 + nt*8 + li8)*PITCH + lq*16);
}

// ---------------- generic GEMM, BK=64: C[m,n] = sum_k A[m,k]*B[n,k] ----------------
// HASAL: add Al*Bh pass. mode 0: fp32 -> oF ; mode 1: fp16 hi -> oH
template<int HASAL>
__global__ void __launch_bounds__(256, 2) k_gemm(
    const hf* __restrict__ Ah, const hf* __restrict__ Al,
    long sA1, long sA2, long sA3, int lda,
    const hf* __restrict__ Bh, long sB1, long sB2, long sB3, int ldb,
    int K, int zm1, int zm2, int mode,
    float* __restrict__ oF, hf* __restrict__ oH,
    long sO1, long sO2, long sO3, int ldo)
{
    const int PITCH = 144, TILEB = 18432;
    extern __shared__ char dyn[];
    const uint32_t smb = smem_u32(dyn);
    const int bufB = (2+HASAL)*TILEB;
    const int tid = threadIdx.x;
    const int l = tid & 31, wid = tid >> 5;
    const int wm = wid >> 2, wn = wid & 3;
    const int quad = l >> 2, lane2 = (l & 3) * 2;
    const int z = blockIdx.z;
    const int z1 = z / zm1, zr = z % zm1;
    const int z2 = zr / zm2, z3 = zr % zm2;
    const int m0 = blockIdx.x * 128, n0 = blockIdx.y * 128;
    const long offA = z1*sA1 + z2*sA2 + z3*sA3;
    const long offB = z1*sB1 + z2*sB2 + z3*sB3;
    const long offO = z1*sO1 + z2*sO2 + z3*sO3;

    const hf* pAh = Ah + offA + (size_t)m0*lda;
    const hf* pAl = HASAL ? (Al + offA + (size_t)m0*lda) : pAh;
    const hf* pBh = Bh + offB + (size_t)n0*ldb;

    float acc[4][4][4];
#pragma unroll
    for (int a = 0; a < 4; ++a)
#pragma unroll
        for (int b = 0; b < 4; ++b)
#pragma unroll
            for (int c = 0; c < 4; ++c) acc[a][b][c] = 0.f;

    const int NC = K / 64;

    auto copy_chunk = [&](int c, int bufi){
        const hf* srcs[3];
        int lds[3];
        int nt = 0;
        srcs[nt] = pAh + c*64; lds[nt] = lda; nt++;
        if (HASAL){ srcs[nt] = pAl + c*64; lds[nt] = lda; nt++; }
        srcs[nt] = pBh + c*64; lds[nt] = ldb; nt++;
#pragma unroll
        for (int t = 0; t < 2+HASAL; ++t){
            const uint32_t sb = smb + bufi*bufB + t*TILEB;
#pragma unroll
            for (int i = 0; i < 4; ++i){
                int e = tid + i*256;
                int row = e >> 3, cc = e & 7;
                cp16(sb + row*PITCH + cc*16, srcs[t] + (size_t)row*lds[t] + cc*8);
            }
        }
    };

    copy_chunk(0, 0);
    asm volatile("cp.async.commit_group;");

    uint32_t aoff[4], boff[4];
    frag_offsets<PITCH>(l, wm, wn, aoff, boff);

    for (int c = 0; c < NC; ++c){
        if (c + 1 < NC){
            copy_chunk(c+1, (c+1)&1);
            asm volatile("cp.async.commit_group;");
            asm volatile("cp.async.wait_group 1;");
        } else {
            asm volatile("cp.async.wait_group 0;");
        }
        __syncthreads();
        mma_tile<HASAL, PITCH, TILEB, 4>(smb + (c&1)*bufB, aoff, boff, acc);
        __syncthreads();
    }

    stage_acc(dyn, acc, wm, wn, quad, lane2);
    __syncthreads();
    float* stg = reinterpret_cast<float*>(dyn);
    if (mode == 0){
        for (int idx = tid; idx < 16384; idx += 256){
            int r = idx >> 7, cc = idx & 127;
            oF[offO + (size_t)(m0+r)*ldo + n0 + cc] = stg[r*129 + cc];
        }
    } else {
        for (int idx = tid; idx < 16384; idx += 256){
            int r = idx >> 7, cc = idx & 127;
            oH[offO + (size_t)(m0+r)*ldo + n0 + cc] = __float2half_rn(stg[r*129 + cc]);
        }
    }
}

// ---------------- merged projection GEMM: 1-pass, all 6 stages, BK=32 ----------------
// z = stage*16 + (batch*4 + head). K fixed 256.
// stage 0: Q (hi-T) 1: Qd (hi-T) 2: Kd (hi-T) 3: K (hi-T) 4: Vd (hi-nat) 5: V (hi-nat)
__global__ void __launch_bounds__(256, 2) k_proj(
    const float* __restrict__ e1, const float* __restrict__ ea,
    const float* __restrict__ ed, const float* __restrict__ eb,
    const hf* __restrict__ wq, const hf* __restrict__ wqd,
    const hf* __restrict__ wk, const hf* __restrict__ wkd,
    const hf* __restrict__ wv, const hf* __restrict__ wvd,
    hf* __restrict__ qAh, hf* __restrict__ kBh, hf* __restrict__ vAh)
{
    extern __shared__ char dyn[];
    const uint32_t smb = smem_u32(dyn);
    const int tid = threadIdx.x;
    const int l = tid & 31, wid = tid >> 5;
    const int wm = wid >> 2, wn = wid & 3;
    const int quad = l >> 2, lane2 = (l & 3) * 2;
    const int z = blockIdx.z;
    const int s = z >> 4, zz = z & 15;
    const int z2 = zz >> 2, z3 = zz & 3;
    const int m0 = blockIdx.x * 128, n0 = blockIdx.y * 128;

    const float* A; const hf* W; hf* oH; long sB3; int mode; int ldo;
    switch (s){
        case 0:  A = e1; W = wq;  sB3 = 65536; mode = 3; oH = qAh;            ldo = 4096; break;
        case 1:  A = ed; W = wqd; sB3 = 65536; mode = 3; oH = qAh + 16777216; ldo = 4096; break;
        case 2:  A = eb; W = wkd; sB3 = 0;     mode = 3; oH = kBh;            ldo = 4096; break;
        case 3:  A = ea; W = wk;  sB3 = 0;     mode = 3; oH = kBh + 16777216; ldo = 4096; break;
        case 4:  A = eb; W = wvd; sB3 = 0;     mode = 1; oH = vAh;            ldo = 256;  break;
        default: A = ea; W = wv;  sB3 = 0;     mode = 1; oH = vAh + 16777216; ldo = 256;  break;
    }
    const long offA = (long)z2*4194304 + (long)z3*256;
    const long offO = (long)z2*4194304 + (long)z3*1048576;
    const float* pA = A + offA + (size_t)m0*1024;
    const hf* pBh = W + z3*sB3 + (size_t)n0*256;

    float acc[4][4][4];
#pragma unroll
    for (int a = 0; a < 4; ++a)
#pragma unroll
        for (int b = 0; b < 4; ++b)
#pragma unroll
            for (int c = 0; c < 4; ++c) acc[a][b][c] = 0.f;

    auto copyB = [&](int c, int bufi){
        const uint32_t sb = smb + bufi*20480 + 10240;
#pragma unroll
        for (int i = 0; i < 2; ++i){
            int e = tid + i*256;
            int row = e >> 2, cc = e & 3;
            cp16(sb + row*80 + cc*16, pBh + c*32 + (size_t)row*256 + cc*8);
        }
    };
    auto ldgA = [&](float4* r, int c){
        const float* base = pA + c*32;
#pragma unroll
        for (int i = 0; i < 4; ++i){
            int e = tid + 256*i;
            int row = e >> 3, cg = e & 7;
            r[i] = *reinterpret_cast<const float4*>(base + (size_t)row*1024 + cg*4);
        }
    };
    auto stsA = [&](float4* r, int bufi){
        char* tA = dyn + bufi*20480;
#pragma unroll
        for (int i = 0; i < 4; ++i){
            int e = tid + 256*i;
            int row = e >> 3, cg = e & 7;
            float4 f = r[i];
            __half2 h0 = __floats2half2_rn(f.x, f.y);
            __half2 h1 = __floats2half2_rn(f.z, f.w);
            char* p = tA + row*80 + cg*8;
            *reinterpret_cast<__half2*>(p)     = h0;
            *reinterpret_cast<__half2*>(p + 4) = h1;
        }
    };

    uint32_t aoff[4], boff[4];
    frag_offsets<80>(l, wm, wn, aoff, boff);

    float4 rA[4], rA2[4];
    ldgA(rA, 0);
    copyB(0, 0);
    asm volatile("cp.async.commit_group;");

    const int NC = 8;
    for (int c = 0; c < NC; ++c){
        stsA(rA, c & 1);
        if (c + 1 < NC){
            ldgA(rA2, c+1);
            copyB(c+1, (c+1)&1);
            asm volatile("cp.async.commit_group;");
            asm volatile("cp.async.wait_group 1;");
        } else {
            asm volatile("cp.async.wait_group 0;");
        }
        __syncthreads();
        mma_tile<0, 80, 10240, 2>(smb + (c&1)*20480, aoff, boff, acc);
        __syncthreads();
#pragma unroll
        for (int i = 0; i < 4; ++i) rA[i] = rA2[i];
    }

    stage_acc(dyn, acc, wm, wn, quad, lane2);
    __syncthreads();
    float* stg = reinterpret_cast<float*>(dyn);
    if (mode == 1){
        for (int idx = tid; idx < 16384; idx += 256){
            int r = idx >> 7, cc = idx & 127;
            oH[offO + (size_t)(m0+r)*ldo + n0 + cc] = __float2half_rn(stg[r*129 + cc]);
        }
    } else {
        for (int idx = tid; idx < 16384; idx += 256){
            int cc = idx >> 7, r = idx & 127;
            oH[offO + (size_t)(n0+cc)*ldo + m0 + r] = __float2half_rn(stg[r*129 + cc]);
        }
    }
}

// ---------------- elementwise ----------------
__global__ void __launch_bounds__(256) k_splitW6(
    const float* __restrict__ Wq, const float* __restrict__ Wqd,
    const float* __restrict__ Wk, const float* __restrict__ Wkd,
    const float* __restrict__ Wv, const float* __restrict__ Wvd,
    hf* __restrict__ wqh, hf* __restrict__ wqdh,
    hf* __restrict__ wkh, hf* __restrict__ wkdh,
    hf* __restrict__ wvh, hf* __restrict__ wvdh)
{
    const int s = blockIdx.y;
    const float* src; hf* dst; int n;
    switch (s){
        case 0:  src = Wq;  dst = wqh;  n = 262144; break;
        case 1:  src = Wqd; dst = wqdh; n = 262144; break;
        case 2:  src = Wk;  dst = wkh;  n = 65536;  break;
        case 3:  src = Wkd; dst = wkdh; n = 65536;  break;
        case 4:  src = Wv;  dst = wvh;  n = 65536;  break;
        default: src = Wvd; dst = wvdh; n = 65536;  break;
    }
    int i = (blockIdx.x*256 + threadIdx.x) * 4;
    if (i >= n) return;
    float4 v = *reinterpret_cast<const float4*>(src + i);
    dst[i]   = __float2half_rn(v.x);
    dst[i+1] = __float2half_rn(v.y);
    dst[i+2] = __float2half_rn(v.z);
    dst[i+3] = __float2half_rn(v.w);
}
__global__ void __launch_bounds__(256) k_splitWo(const float* __restrict__ Wo,
                                                 const float* __restrict__ Wod,
                                                 hf* __restrict__ h){
    const float* s = blockIdx.y ? Wod : Wo;
    int idx = blockIdx.x*256 + threadIdx.x;
    int j = idx >> 10, t = idx & 1023;
    h[(size_t)blockIdx.y*1048576 + idx] =
        __float2half_rn(s[((size_t)j<<10) + ((t & 255)<<2) + (t>>8)]);
}
__global__ void __launch_bounds__(256) k_reduce(){
    int idx = blockIdx.x*256 + threadIdx.x;
    int pb = idx >> 20, r = idx & 1048575;
    const float* p = g_sp + (size_t)pb*8388608 + r;
    float s = 0.f;
#pragma unroll
    for (int sl = 0; sl < 8; ++sl) s += p[(size_t)sl*1048576];
    g_s[idx] = s * SCALEV;
}
__global__ void __launch_bounds__(256) k_moments(){
    const int idx = blockIdx.x;
    const float* s = g_s + (size_t)idx*65536;
    __shared__ float sh[256], sh2[256];
    float sum = 0.f, sq = 0.f;
    for (int i = threadIdx.x; i < 65536; i += 256){ float v = s[i]; sum += v; sq = fmaf(v,v,sq); }
    sh[threadIdx.x] = sum; sh2[threadIdx.x] = sq;
    __syncthreads();
    for (int o = 128; o; o >>= 1){
        if (threadIdx.x < o){ sh[threadIdx.x] += sh[threadIdx.x+o]; sh2[threadIdx.x] += sh2[threadIdx.x+o]; }
        __syncthreads();
    }
    if (threadIdx.x == 0){
        float m = sh[0]*(1.f/65536.f);
        g_mv[idx*2] = m;
        g_mv[idx*2+1] = sh2[0]*(1.f/65536.f) - m*m;
    }
}
__global__ void __launch_bounds__(256) k_softmax(){
    const int pb = blockIdx.z*16 + blockIdx.y;
    const size_t rb = ((size_t)pb*256 + blockIdx.x)*256;
    const float mean = g_mv[pb*2];
    const float inv  = rsqrtf(g_mv[pb*2+1] + EPSV);
    const int tid = threadIdx.x;
    float y = (g_s[rb + tid] - mean) * inv;
    __shared__ float red[8];
    float m = y;
#pragma unroll
    for (int o = 16; o; o >>= 1) m = fmaxf(m, __shfl_xor_sync(~0u, m, o));
    if ((tid & 31) == 0) red[tid>>5] = m;
    __syncthreads();
    if (tid == 0){ float mm = red[0]; for (int i=1;i<8;++i) mm = fmaxf(mm, red[i]); red[0] = mm; }
    __syncthreads();
    float e = expf(y - red[0]);
    __syncthreads();
    float ssum = e;
#pragma unroll
    for (int o = 16; o; o >>= 1) ssum += __shfl_xor_sync(~0u, ssum, o);
    if ((tid & 31) == 0) red[tid>>5] = ssum;
    __syncthreads();
    if (tid == 0){ float t = 0.f; for (int i=0;i<8;++i) t += red[i]; red[0] = t; }
    __syncthreads();
    g_ph[rb + tid] = __float2half_rn(e / red[0]);
}

// ---------------- launch ----------------
static void* dsym(const void* s){ void* p = 0; cudaGetSymbolAddress(&p, s); return p; }

extern "C" void kernel_launch(void* const* d_in, const int* in_sizes, int n_in,
                              void* d_out, int out_size)
{
    const float* emb1     = (const float*)d_in[0];
    const float* emb_all  = (const float*)d_in[1];
    const float* embd1    = (const float*)d_in[2];
    const float* emb_alld = (const float*)d_in[3];
    const float* Wq = (const float*)d_in[4];  const float* Wqd = (const float*)d_in[5];
    const float* Wk = (const float*)d_in[6];  const float* Wv  = (const float*)d_in[7];
    const float* Wkd= (const float*)d_in[8];  const float* Wvd = (const float*)d_in[9];
    const float* Wo = (const float*)d_in[10]; const float* Wod = (const float*)d_in[11];
    float* out = (float*)d_out;

    const int SM0 = 73728;    // k_gemm<0>: 2 buf x 2 tiles x 18432 (>= 66048 epilogue)
    const int SMP = 66048;    // k_proj
    cudaFuncSetAttribute(k_gemm<0>, cudaFuncAttributeMaxDynamicSharedMemorySize, SM0);
    cudaFuncSetAttribute(k_proj,    cudaFuncAttributeMaxDynamicSharedMemorySize, SMP);

#define GH(x) ((hf*)dsym(x))
    hf *qAh = GH(g_qAh);
    hf *kBh = GH(g_kBh), *vAh = GH(g_vAh);
    hf *ch = GH(g_ch), *ph = GH(g_ph), *woh = GH(g_woh);
    float* sp = (float*)dsym(g_sp);

    // weight conversions (merged)
    k_splitW6<<<dim3(256,6),256>>>(Wq,Wqd,Wk,Wkd,Wv,Wvd,
                                   GH(g_wqh),GH(g_wqdh),GH(g_wkh),GH(g_wkdh),GH(g_wvh),GH(g_wvdh));
    k_splitWo<<<dim3(4096,2),256>>>(Wo, Wod, woh);

    // projections: 1-pass, all 6 stages in one launch
    k_proj<<<dim3(32,2,96),256,SMP>>>(emb1, emb_all, embd1, emb_alld,
                                      GH(g_wqh),GH(g_wqdh),GH(g_wkh),GH(g_wkdh),GH(g_wvh),GH(g_wvdh),
                                      qAh, kBh, vAh);

    // scores: 1-pass (Q hi x K hi), split-K x8, one launch
    dim3 gsc(2,2,256);
    k_gemm<0><<<gsc,256,SM0>>>(qAh,(hf*)0, 16777216,1048576,512, 4096,
                               kBh, 16777216,1048576,512, 4096,
                               512, 128,8, 0,
                               sp, (hf*)0, 8388608,65536,1048576, 256);
    k_reduce<<<8192,256>>>();
    k_moments<<<32,256>>>();
    k_softmax<<<dim3(256,16,2),256>>>();

    // ctx: 1-pass (V hi x probs hi), both paths in one launch
    dim3 gc(32,2,32);
    k_gemm<0><<<gc,256,SM0>>>(vAh,(hf*)0, 16777216,4194304,1048576, 256,
                              ph, 1048576,262144,65536, 256,
                              256, 16,4, 1,
                              (float*)0, ch, 16777216,4194304,256, 1024);

    // out: 1-pass (ctx hi x Wo hi), both paths in one launch
    dim3 go(128,8,2);
    k_gemm<0><<<go,256,SM0>>>(ch,(hf*)0, 16777216,0,0, 1024,
                              woh, 1048576,0,0, 1024,
                              1024, 1,1, 0,
                              out, (hf*)0, 16777216,0,0, 1024);
#undef GH
}

// round 14
// speedup vs baseline: 7.8949x; 1.0534x over previous
#include <cuda_runtime.h>
#include <cuda_fp16.h>
#include <stdint.h>
#include <math.h>

typedef __half hf;

#define EPSV 1e-5f
#define SCALEV 0.03125f

// ---------------- scratch ----------------
__device__ __align__(16) hf g_qAh[33554432];                   // Qt hi [path][bh][c][n]
__device__ __align__(16) hf g_kBh[33554432];                   // [Kdt; Kt] hi
__device__ __align__(16) hf g_vAh[33554432];                   // [Vd; V] hi [bh][n][k]
__device__ __align__(16) hf g_wqh[262144], g_wqdh[262144];
__device__ __align__(16) hf g_wkh[65536], g_wvh[65536], g_wkdh[65536], g_wvdh[65536];
__device__ __align__(16) hf g_woh[2097152];                    // blocked, both paths
__device__ __align__(16) float g_sp[16777216];                 // score partials
__device__ __align__(16) float g_s[2097152];
__device__ __align__(16) hf g_ph[2097152];
__device__ __align__(16) hf g_ch[33554432];                    // ctx fp16 blocked, both paths
__device__ float g_mv[64];

// ---------------- helpers ----------------
__device__ __forceinline__ uint32_t smem_u32(const void* p){
    uint32_t a;
    asm("{ .reg .u64 t; cvta.to.shared.u64 t, %1; cvt.u32.u64 %0, t; }" : "=r"(a) : "l"(p));
    return a;
}
__device__ __forceinline__ void cp16(uint32_t sa, const void* g){
    asm volatile("cp.async.cg.shared.global [%0], [%1], 16;" :: "r"(sa), "l"(g));
}
__device__ __forceinline__ void mma16816(float* d, const uint32_t* a, const uint32_t* b){
    asm volatile("mma.sync.aligned.m16n8k16.row.col.f32.f16.f16.f32 "
        "{%0,%1,%2,%3}, {%4,%5,%6,%7}, {%8,%9}, {%0,%1,%2,%3};"
        : "+f"(d[0]),"+f"(d[1]),"+f"(d[2]),"+f"(d[3])
        : "r"(a[0]),"r"(a[1]),"r"(a[2]),"r"(a[3]),"r"(b[0]),"r"(b[1]));
}
__device__ __forceinline__ void ldsm4(uint32_t* r, uint32_t addr){
    asm volatile("ldmatrix.sync.aligned.m8n8.x4.shared.b16 {%0,%1,%2,%3}, [%4];"
        : "=r"(r[0]),"=r"(r[1]),"=r"(r[2]),"=r"(r[3]) : "r"(addr));
}
__device__ __forceinline__ void ldsm2(uint32_t* r, uint32_t addr){
    asm volatile("ldmatrix.sync.aligned.m8n8.x2.shared.b16 {%0,%1}, [%2];"
        : "=r"(r[0]),"=r"(r[1]) : "r"(addr));
}

// inner mma over one chunk via ldmatrix.
template<int HASAL, int PITCH, int TILEB, int NKS>
__device__ __forceinline__ void mma_tile(uint32_t tbase, const uint32_t* aoff, const uint32_t* boff,
                                         float acc[4][4][4])
{
    const uint32_t tB = tbase + (1+HASAL)*TILEB;
#pragma unroll
    for (int ks = 0; ks < NKS; ++ks){
        const int kb = ks * 32;
        uint32_t bX[4][2];
#pragma unroll
        for (int nt = 0; nt < 4; ++nt) ldsm2(bX[nt], tB + boff[nt] + kb);
#pragma unroll
        for (int pass = 0; pass <= HASAL; ++pass){
            const uint32_t tAp = tbase + pass*TILEB;
            uint32_t aH[4][4];
#pragma unroll
            for (int mt = 0; mt < 4; ++mt) ldsm4(aH[mt], tAp + aoff[mt] + kb);
#pragma unroll
            for (int mt = 0; mt < 4; ++mt)
#pragma unroll
                for (int nt = 0; nt < 4; ++nt) mma16816(acc[mt][nt], aH[mt], bX[nt]);
        }
    }
}

__device__ __forceinline__ void stage_acc(char* dyn, float acc[4][4][4],
                                          int wm, int wn, int quad, int lane2)
{
    float* stg = reinterpret_cast<float*>(dyn);
#pragma unroll
    for (int mt = 0; mt < 4; ++mt){
        const int r = wm*64 + mt*16 + quad;
#pragma unroll
        for (int nt = 0; nt < 4; ++nt){
            const int cc = wn*32 + nt*8 + lane2;
            stg[r*129 + cc]       = acc[mt][nt][0];
            stg[r*129 + cc + 1]   = acc[mt][nt][1];
            stg[(r+8)*129 + cc]   = acc[mt][nt][2];
            stg[(r+8)*129 + cc+1] = acc[mt][nt][3];
        }
    }
}

template<int PITCH>
__device__ __forceinline__ void frag_offsets(int l, int wm, int wn, uint32_t* aoff, uint32_t* boff){
    const int li8 = l & 7, lq = (l >> 3) & 1, lh = (l >> 4) & 1;
#pragma unroll
    for (int mt = 0; mt < 4; ++mt)
        aoff[mt] = (uint32_t)((wm*64 + mt*16 + li8 + lq*8)*PITCH + lh*16);
#pragma unroll
    for (int nt = 0; nt < 4; ++nt)
        boff[nt] = (uint32_t)((wn*32 + nt*8 + li8)*PITCH + lq*16);
}

// ---------------- generic GEMM, BK=64, 3-stage single-sync pipeline ----------------
// mode 0: fp32 -> oF ; mode 1: fp16 hi -> oH
template<int HASAL>
__global__ void __launch_bounds__(256, 2) k_gemm(
    const hf* __restrict__ Ah, const hf* __restrict__ Al,
    long sA1, long sA2, long sA3, int lda,
    const hf* __restrict__ Bh, long sB1, long sB2, long sB3, int ldb,
    int K, int zm1, int zm2, int mode,
    float* __restrict__ oF, hf* __restrict__ oH,
    long sO1, long sO2, long sO3, int ldo)
{
    const int PITCH = 144, TILEB = 18432;
    extern __shared__ char dyn[];
    const uint32_t smb = smem_u32(dyn);
    const int bufB = (2+HASAL)*TILEB;
    const int tid = threadIdx.x;
    const int l = tid & 31, wid = tid >> 5;
    const int wm = wid >> 2, wn = wid & 3;
    const int quad = l >> 2, lane2 = (l & 3) * 2;
    const int z = blockIdx.z;
    const int z1 = z / zm1, zr = z % zm1;
    const int z2 = zr / zm2, z3 = zr % zm2;
    const int m0 = blockIdx.x * 128, n0 = blockIdx.y * 128;
    const long offA = z1*sA1 + z2*sA2 + z3*sA3;
    const long offB = z1*sB1 + z2*sB2 + z3*sB3;
    const long offO = z1*sO1 + z2*sO2 + z3*sO3;

    const hf* pAh = Ah + offA + (size_t)m0*lda;
    const hf* pAl = HASAL ? (Al + offA + (size_t)m0*lda) : pAh;
    const hf* pBh = Bh + offB + (size_t)n0*ldb;

    float acc[4][4][4];
#pragma unroll
    for (int a = 0; a < 4; ++a)
#pragma unroll
        for (int b = 0; b < 4; ++b)
#pragma unroll
            for (int c = 0; c < 4; ++c) acc[a][b][c] = 0.f;

    const int NC = K / 64;

    auto copy_chunk = [&](int c, int bufi){
        const hf* srcs[3];
        int lds[3];
        int nt = 0;
        srcs[nt] = pAh + c*64; lds[nt] = lda; nt++;
        if (HASAL){ srcs[nt] = pAl + c*64; lds[nt] = lda; nt++; }
        srcs[nt] = pBh + c*64; lds[nt] = ldb; nt++;
#pragma unroll
        for (int t = 0; t < 2+HASAL; ++t){
            const uint32_t sb = smb + bufi*bufB + t*TILEB;
#pragma unroll
            for (int i = 0; i < 4; ++i){
                int e = tid + i*256;
                int row = e >> 3, cc = e & 7;
                cp16(sb + row*PITCH + cc*16, srcs[t] + (size_t)row*lds[t] + cc*8);
            }
        }
    };

    copy_chunk(0, 0);
    asm volatile("cp.async.commit_group;");
    copy_chunk(1, 1);
    asm volatile("cp.async.commit_group;");

    uint32_t aoff[4], boff[4];
    frag_offsets<PITCH>(l, wm, wn, aoff, boff);

    int bufc = 0;
    for (int c = 0; c < NC; ++c){
        if (c + 1 < NC) asm volatile("cp.async.wait_group 1;");
        else            asm volatile("cp.async.wait_group 0;");
        __syncthreads();
        if (c + 2 < NC){
            int b2 = bufc + 2; if (b2 >= 3) b2 -= 3;
            copy_chunk(c+2, b2);
            asm volatile("cp.async.commit_group;");
        }
        mma_tile<HASAL, PITCH, TILEB, 4>(smb + bufc*bufB, aoff, boff, acc);
        if (++bufc == 3) bufc = 0;
    }
    __syncthreads();

    stage_acc(dyn, acc, wm, wn, quad, lane2);
    __syncthreads();
    float* stg = reinterpret_cast<float*>(dyn);
    if (mode == 0){
        for (int idx = tid; idx < 16384; idx += 256){
            int r = idx >> 7, cc = idx & 127;
            oF[offO + (size_t)(m0+r)*ldo + n0 + cc] = stg[r*129 + cc];
        }
    } else {
        for (int idx = tid; idx < 16384; idx += 256){
            int r = idx >> 7, cc = idx & 127;
            oH[offO + (size_t)(m0+r)*ldo + n0 + cc] = __float2half_rn(stg[r*129 + cc]);
        }
    }
}

// ---------------- merged projection GEMM: 1-pass, all 6 stages, BK=32 ----------------
__global__ void __launch_bounds__(256, 2) k_proj(
    const float* __restrict__ e1, const float* __restrict__ ea,
    const float* __restrict__ ed, const float* __restrict__ eb,
    const hf* __restrict__ wq, const hf* __restrict__ wqd,
    const hf* __restrict__ wk, const hf* __restrict__ wkd,
    const hf* __restrict__ wv, const hf* __restrict__ wvd,
    hf* __restrict__ qAh, hf* __restrict__ kBh, hf* __restrict__ vAh)
{
    extern __shared__ char dyn[];
    const uint32_t smb = smem_u32(dyn);
    const int tid = threadIdx.x;
    const int l = tid & 31, wid = tid >> 5;
    const int wm = wid >> 2, wn = wid & 3;
    const int quad = l >> 2, lane2 = (l & 3) * 2;
    const int z = blockIdx.z;
    const int s = z >> 4, zz = z & 15;
    const int z2 = zz >> 2, z3 = zz & 3;
    const int m0 = blockIdx.x * 128, n0 = blockIdx.y * 128;

    const float* A; const hf* W; hf* oH; long sB3; int mode; int ldo;
    switch (s){
        case 0:  A = e1; W = wq;  sB3 = 65536; mode = 3; oH = qAh;            ldo = 4096; break;
        case 1:  A = ed; W = wqd; sB3 = 65536; mode = 3; oH = qAh + 16777216; ldo = 4096; break;
        case 2:  A = eb; W = wkd; sB3 = 0;     mode = 3; oH = kBh;            ldo = 4096; break;
        case 3:  A = ea; W = wk;  sB3 = 0;     mode = 3; oH = kBh + 16777216; ldo = 4096; break;
        case 4:  A = eb; W = wvd; sB3 = 0;     mode = 1; oH = vAh;            ldo = 256;  break;
        default: A = ea; W = wv;  sB3 = 0;     mode = 1; oH = vAh + 16777216; ldo = 256;  break;
    }
    const long offA = (long)z2*4194304 + (long)z3*256;
    const long offO = (long)z2*4194304 + (long)z3*1048576;
    const float* pA = A + offA + (size_t)m0*1024;
    const hf* pBh = W + z3*sB3 + (size_t)n0*256;

    float acc[4][4][4];
#pragma unroll
    for (int a = 0; a < 4; ++a)
#pragma unroll
        for (int b = 0; b < 4; ++b)
#pragma unroll
            for (int c = 0; c < 4; ++c) acc[a][b][c] = 0.f;

    auto copyB = [&](int c, int bufi){
        const uint32_t sb = smb + bufi*20480 + 10240;
#pragma unroll
        for (int i = 0; i < 2; ++i){
            int e = tid + i*256;
            int row = e >> 2, cc = e & 3;
            cp16(sb + row*80 + cc*16, pBh + c*32 + (size_t)row*256 + cc*8);
        }
    };
    auto ldgA = [&](float4* r, int c){
        const float* base = pA + c*32;
#pragma unroll
        for (int i = 0; i < 4; ++i){
            int e = tid + 256*i;
            int row = e >> 3, cg = e & 7;
            r[i] = *reinterpret_cast<const float4*>(base + (size_t)row*1024 + cg*4);
        }
    };
    auto stsA = [&](float4* r, int bufi){
        char* tA = dyn + bufi*20480;
#pragma unroll
        for (int i = 0; i < 4; ++i){
            int e = tid + 256*i;
            int row = e >> 3, cg = e & 7;
            float4 f = r[i];
            __half2 h0 = __floats2half2_rn(f.x, f.y);
            __half2 h1 = __floats2half2_rn(f.z, f.w);
            char* p = tA + row*80 + cg*8;
            *reinterpret_cast<__half2*>(p)     = h0;
            *reinterpret_cast<__half2*>(p + 4) = h1;
        }
    };

    uint32_t aoff[4], boff[4];
    frag_offsets<80>(l, wm, wn, aoff, boff);

    float4 rA[4], rA2[4];
    ldgA(rA, 0);
    copyB(0, 0);
    asm volatile("cp.async.commit_group;");

    const int NC = 8;
    for (int c = 0; c < NC; ++c){
        stsA(rA, c & 1);
        if (c + 1 < NC){
            ldgA(rA2, c+1);
            copyB(c+1, (c+1)&1);
            asm volatile("cp.async.commit_group;");
            asm volatile("cp.async.wait_group 1;");
        } else {
            asm volatile("cp.async.wait_group 0;");
        }
        __syncthreads();
        mma_tile<0, 80, 10240, 2>(smb + (c&1)*20480, aoff, boff, acc);
        __syncthreads();
#pragma unroll
        for (int i = 0; i < 4; ++i) rA[i] = rA2[i];
    }

    stage_acc(dyn, acc, wm, wn, quad, lane2);
    __syncthreads();
    float* stg = reinterpret_cast<float*>(dyn);
    if (mode == 1){
        for (int idx = tid; idx < 16384; idx += 256){
            int r = idx >> 7, cc = idx & 127;
            oH[offO + (size_t)(m0+r)*ldo + n0 + cc] = __float2half_rn(stg[r*129 + cc]);
        }
    } else {
        for (int idx = tid; idx < 16384; idx += 256){
            int cc = idx >> 7, r = idx & 127;
            oH[offO + (size_t)(n0+cc)*ldo + m0 + r] = __float2half_rn(stg[r*129 + cc]);
        }
    }
}

// ---------------- elementwise ----------------
__global__ void __launch_bounds__(256) k_splitW6(
    const float* __restrict__ Wq, const float* __restrict__ Wqd,
    const float* __restrict__ Wk, const float* __restrict__ Wkd,
    const float* __restrict__ Wv, const float* __restrict__ Wvd,
    hf* __restrict__ wqh, hf* __restrict__ wqdh,
    hf* __restrict__ wkh, hf* __restrict__ wkdh,
    hf* __restrict__ wvh, hf* __restrict__ wvdh)
{
    const int s = blockIdx.y;
    const float* src; hf* dst; int n;
    switch (s){
        case 0:  src = Wq;  dst = wqh;  n = 262144; break;
        case 1:  src = Wqd; dst = wqdh; n = 262144; break;
        case 2:  src = Wk;  dst = wkh;  n = 65536;  break;
        case 3:  src = Wkd; dst = wkdh; n = 65536;  break;
        case 4:  src = Wv;  dst = wvh;  n = 65536;  break;
        default: src = Wvd; dst = wvdh; n = 65536;  break;
    }
    int i = (blockIdx.x*256 + threadIdx.x) * 4;
    if (i >= n) return;
    float4 v = *reinterpret_cast<const float4*>(src + i);
    dst[i]   = __float2half_rn(v.x);
    dst[i+1] = __float2half_rn(v.y);
    dst[i+2] = __float2half_rn(v.z);
    dst[i+3] = __float2half_rn(v.w);
}
__global__ void __launch_bounds__(256) k_splitWo(const float* __restrict__ Wo,
                                                 const float* __restrict__ Wod,
                                                 hf* __restrict__ h){
    const float* s = blockIdx.y ? Wod : Wo;
    int idx = blockIdx.x*256 + threadIdx.x;
    int j = idx >> 10, t = idx & 1023;
    h[(size_t)blockIdx.y*1048576 + idx] =
        __float2half_rn(s[((size_t)j<<10) + ((t & 255)<<2) + (t>>8)]);
}
// split-K x4 reduce
__global__ void __launch_bounds__(256) k_reduce(){
    int idx = blockIdx.x*256 + threadIdx.x;
    int pb = idx >> 20, r = idx & 1048575;
    const float* p = g_sp + (size_t)pb*4194304 + r;
    float s = 0.f;
#pragma unroll
    for (int sl = 0; sl < 4; ++sl) s += p[(size_t)sl*1048576];
    g_s[idx] = s * SCALEV;
}
__global__ void __launch_bounds__(256) k_moments(){
    const int idx = blockIdx.x;
    const float* s = g_s + (size_t)idx*65536;
    __shared__ float sh[256], sh2[256];
    float sum = 0.f, sq = 0.f;
    for (int i = threadIdx.x; i < 65536; i += 256){ float v = s[i]; sum += v; sq = fmaf(v,v,sq); }
    sh[threadIdx.x] = sum; sh2[threadIdx.x] = sq;
    __syncthreads();
    for (int o = 128; o; o >>= 1){
        if (threadIdx.x < o){ sh[threadIdx.x] += sh[threadIdx.x+o]; sh2[threadIdx.x] += sh2[threadIdx.x+o]; }
        __syncthreads();
    }
    if (threadIdx.x == 0){
        float m = sh[0]*(1.f/65536.f);
        g_mv[idx*2] = m;
        g_mv[idx*2+1] = sh2[0]*(1.f/65536.f) - m*m;
    }
}
__global__ void __launch_bounds__(256) k_softmax(){
    const int pb = blockIdx.z*16 + blockIdx.y;
    const size_t rb = ((size_t)pb*256 + blockIdx.x)*256;
    const float mean = g_mv[pb*2];
    const float inv  = rsqrtf(g_mv[pb*2+1] + EPSV);
    const int tid = threadIdx.x;
    float y = (g_s[rb + tid] - mean) * inv;
    __shared__ float red[8];
    float m = y;
#pragma unroll
    for (int o = 16; o; o >>= 1) m = fmaxf(m, __shfl_xor_sync(~0u, m, o));
    if ((tid & 31) == 0) red[tid>>5] = m;
    __syncthreads();
    if (tid == 0){ float mm = red[0]; for (int i=1;i<8;++i) mm = fmaxf(mm, red[i]); red[0] = mm; }
    __syncthreads();
    float e = expf(y - red[0]);
    __syncthreads();
    float ssum = e;
#pragma unroll
    for (int o = 16; o; o >>= 1) ssum += __shfl_xor_sync(~0u, ssum, o);
    if ((tid & 31) == 0) red[tid>>5] = ssum;
    __syncthreads();
    if (tid == 0){ float t = 0.f; for (int i=0;i<8;++i) t += red[i]; red[0] = t; }
    __syncthreads();
    g_ph[rb + tid] = __float2half_rn(e / red[0]);
}

// ---------------- launch ----------------
static void* dsym(const void* s){ void* p = 0; cudaGetSymbolAddress(&p, s); return p; }

extern "C" void kernel_launch(void* const* d_in, const int* in_sizes, int n_in,
                              void* d_out, int out_size)
{
    const float* emb1     = (const float*)d_in[0];
    const float* emb_all  = (const float*)d_in[1];
    const float* embd1    = (const float*)d_in[2];
    const float* emb_alld = (const float*)d_in[3];
    const float* Wq = (const float*)d_in[4];  const float* Wqd = (const float*)d_in[5];
    const float* Wk = (const float*)d_in[6];  const float* Wv  = (const float*)d_in[7];
    const float* Wkd= (const float*)d_in[8];  const float* Wvd = (const float*)d_in[9];
    const float* Wo = (const float*)d_in[10]; const float* Wod = (const float*)d_in[11];
    float* out = (float*)d_out;

    const int SM0 = 110592;   // k_gemm<0>: 3 buf x 2 tiles x 18432
    const int SMP = 66048;    // k_proj
    cudaFuncSetAttribute(k_gemm<0>, cudaFuncAttributeMaxDynamicSharedMemorySize, SM0);
    cudaFuncSetAttribute(k_proj,    cudaFuncAttributeMaxDynamicSharedMemorySize, SMP);

#define GH(x) ((hf*)dsym(x))
    hf *qAh = GH(g_qAh);
    hf *kBh = GH(g_kBh), *vAh = GH(g_vAh);
    hf *ch = GH(g_ch), *ph = GH(g_ph), *woh = GH(g_woh);
    float* sp = (float*)dsym(g_sp);

    // weight conversions (merged)
    k_splitW6<<<dim3(256,6),256>>>(Wq,Wqd,Wk,Wkd,Wv,Wvd,
                                   GH(g_wqh),GH(g_wqdh),GH(g_wkh),GH(g_wkdh),GH(g_wvh),GH(g_wvdh));
    k_splitWo<<<dim3(4096,2),256>>>(Wo, Wod, woh);

    // projections: 1-pass, all 6 stages in one launch
    k_proj<<<dim3(32,2,96),256,SMP>>>(emb1, emb_all, embd1, emb_alld,
                                      GH(g_wqh),GH(g_wqdh),GH(g_wkh),GH(g_wkdh),GH(g_wvh),GH(g_wvdh),
                                      qAh, kBh, vAh);

    // scores: 1-pass (Q hi x K hi), split-K x4, one launch
    dim3 gsc(2,2,128);
    k_gemm<0><<<gsc,256,SM0>>>(qAh,(hf*)0, 16777216,1048576,1024, 4096,
                               kBh, 16777216,1048576,1024, 4096,
                               1024, 64,4, 0,
                               sp, (hf*)0, 4194304,65536,1048576, 256);
    k_reduce<<<8192,256>>>();
    k_moments<<<32,256>>>();
    k_softmax<<<dim3(256,16,2),256>>>();

    // ctx: 1-pass (V hi x probs hi), both paths in one launch
    dim3 gc(32,2,32);
    k_gemm<0><<<gc,256,SM0>>>(vAh,(hf*)0, 16777216,4194304,1048576, 256,
                              ph, 1048576,262144,65536, 256,
                              256, 16,4, 1,
                              (float*)0, ch, 16777216,4194304,256, 1024);

    // out: 1-pass (ctx hi x Wo hi), both paths in one launch
    dim3 go(128,8,2);
    k_gemm<0><<<go,256,SM0>>>(ch,(hf*)0, 16777216,0,0, 1024,
                              woh, 1048576,0,0, 1024,
                              1024, 1,1, 0,
                              out, (hf*)0, 16777216,0,0, 1024);
#undef GH
}

// round 15
// speedup vs baseline: 8.2171x; 1.0408x over previous
#include <cuda_runtime.h>
#include <cuda_fp16.h>
#include <stdint.h>
#include <math.h>

typedef __half hf;

#define EPSV 1e-5f
#define SCALEV 0.03125f

// ---------------- scratch ----------------
__device__ __align__(16) hf g_qAh[33554432];                   // Qt hi [path][bh][c][n]
__device__ __align__(16) hf g_kBh[33554432];                   // [Kdt; Kt] hi
__device__ __align__(16) hf g_vAh[33554432];                   // [Vd; V] hi [bh][n][k]
__device__ __align__(16) hf g_wqh[262144], g_wqdh[262144];
__device__ __align__(16) hf g_wkh[65536], g_wvh[65536], g_wkdh[65536], g_wvdh[65536];
__device__ __align__(16) hf g_woh[2097152];                    // blocked, both paths
__device__ __align__(16) float g_sp[16777216];                 // score partials
__device__ __align__(16) float g_s[2097152];
__device__ __align__(16) float g_red[4096];                    // per-block {sum,sumsq}
__device__ __align__(16) hf g_ph[2097152];
__device__ __align__(16) hf g_ch[33554432];                    // ctx fp16 blocked, both paths
__device__ float g_mv[64];

// ---------------- helpers ----------------
__device__ __forceinline__ uint32_t smem_u32(const void* p){
    uint32_t a;
    asm("{ .reg .u64 t; cvta.to.shared.u64 t, %1; cvt.u32.u64 %0, t; }" : "=r"(a) : "l"(p));
    return a;
}
__device__ __forceinline__ void cp16(uint32_t sa, const void* g){
    asm volatile("cp.async.cg.shared.global [%0], [%1], 16;" :: "r"(sa), "l"(g));
}
__device__ __forceinline__ void mma16816(float* d, const uint32_t* a, const uint32_t* b){
    asm volatile("mma.sync.aligned.m16n8k16.row.col.f32.f16.f16.f32 "
        "{%0,%1,%2,%3}, {%4,%5,%6,%7}, {%8,%9}, {%0,%1,%2,%3};"
        : "+f"(d[0]),"+f"(d[1]),"+f"(d[2]),"+f"(d[3])
        : "r"(a[0]),"r"(a[1]),"r"(a[2]),"r"(a[3]),"r"(b[0]),"r"(b[1]));
}
__device__ __forceinline__ void ldsm4(uint32_t* r, uint32_t addr){
    asm volatile("ldmatrix.sync.aligned.m8n8.x4.shared.b16 {%0,%1,%2,%3}, [%4];"
        : "=r"(r[0]),"=r"(r[1]),"=r"(r[2]),"=r"(r[3]) : "r"(addr));
}
__device__ __forceinline__ void ldsm2(uint32_t* r, uint32_t addr){
    asm volatile("ldmatrix.sync.aligned.m8n8.x2.shared.b16 {%0,%1}, [%2];"
        : "=r"(r[0]),"=r"(r[1]) : "r"(addr));
}

template<int HASAL, int PITCH, int TILEB, int NKS>
__device__ __forceinline__ void mma_tile(uint32_t tbase, const uint32_t* aoff, const uint32_t* boff,
                                         float acc[4][4][4])
{
    const uint32_t tB = tbase + (1+HASAL)*TILEB;
#pragma unroll
    for (int ks = 0; ks < NKS; ++ks){
        const int kb = ks * 32;
        uint32_t bX[4][2];
#pragma unroll
        for (int nt = 0; nt < 4; ++nt) ldsm2(bX[nt], tB + boff[nt] + kb);
#pragma unroll
        for (int pass = 0; pass <= HASAL; ++pass){
            const uint32_t tAp = tbase + pass*TILEB;
            uint32_t aH[4][4];
#pragma unroll
            for (int mt = 0; mt < 4; ++mt) ldsm4(aH[mt], tAp + aoff[mt] + kb);
#pragma unroll
            for (int mt = 0; mt < 4; ++mt)
#pragma unroll
                for (int nt = 0; nt < 4; ++nt) mma16816(acc[mt][nt], aH[mt], bX[nt]);
        }
    }
}

template<int SPITCH>
__device__ __forceinline__ void stage_acc(char* dyn, float acc[4][4][4],
                                          int wm, int wn, int quad, int lane2)
{
    float* stg = reinterpret_cast<float*>(dyn);
#pragma unroll
    for (int mt = 0; mt < 4; ++mt){
        const int r = wm*64 + mt*16 + quad;
#pragma unroll
        for (int nt = 0; nt < 4; ++nt){
            const int cc = wn*32 + nt*8 + lane2;
            stg[r*SPITCH + cc]       = acc[mt][nt][0];
            stg[r*SPITCH + cc + 1]   = acc[mt][nt][1];
            stg[(r+8)*SPITCH + cc]   = acc[mt][nt][2];
            stg[(r+8)*SPITCH + cc+1] = acc[mt][nt][3];
        }
    }
}

template<int PITCH>
__device__ __forceinline__ void frag_offsets(int l, int wm, int wn, uint32_t* aoff, uint32_t* boff){
    const int li8 = l & 7, lq = (l >> 3) & 1, lh = (l >> 4) & 1;
#pragma unroll
    for (int mt = 0; mt < 4; ++mt)
        aoff[mt] = (uint32_t)((wm*64 + mt*16 + li8 + lq*8)*PITCH + lh*16);
#pragma unroll
    for (int nt = 0; nt < 4; ++nt)
        boff[nt] = (uint32_t)((wn*32 + nt*8 + li8)*PITCH + lq*16);
}

// ---------------- generic GEMM, BK=64, 3-stage single-sync pipeline ----------------
// mode 0: fp32 -> oF ; mode 1: fp16 hi -> oH
template<int HASAL>
__global__ void __launch_bounds__(256, 2) k_gemm(
    const hf* __restrict__ Ah, const hf* __restrict__ Al,
    long sA1, long sA2, long sA3, int lda,
    const hf* __restrict__ Bh, long sB1, long sB2, long sB3, int ldb,
    int K, int zm1, int zm2, int mode,
    float* __restrict__ oF, hf* __restrict__ oH,
    long sO1, long sO2, long sO3, int ldo)
{
    const int PITCH = 144, TILEB = 18432;
    extern __shared__ char dyn[];
    const uint32_t smb = smem_u32(dyn);
    const int bufB = (2+HASAL)*TILEB;
    const int tid = threadIdx.x;
    const int l = tid & 31, wid = tid >> 5;
    const int wm = wid >> 2, wn = wid & 3;
    const int quad = l >> 2, lane2 = (l & 3) * 2;
    const int z = blockIdx.z;
    const int z1 = z / zm1, zr = z % zm1;
    const int z2 = zr / zm2, z3 = zr % zm2;
    const int m0 = blockIdx.x * 128, n0 = blockIdx.y * 128;
    const long offA = z1*sA1 + z2*sA2 + z3*sA3;
    const long offB = z1*sB1 + z2*sB2 + z3*sB3;
    const long offO = z1*sO1 + z2*sO2 + z3*sO3;

    const hf* pAh = Ah + offA + (size_t)m0*lda;
    const hf* pAl = HASAL ? (Al + offA + (size_t)m0*lda) : pAh;
    const hf* pBh = Bh + offB + (size_t)n0*ldb;

    float acc[4][4][4];
#pragma unroll
    for (int a = 0; a < 4; ++a)
#pragma unroll
        for (int b = 0; b < 4; ++b)
#pragma unroll
            for (int c = 0; c < 4; ++c) acc[a][b][c] = 0.f;

    const int NC = K / 64;

    auto copy_chunk = [&](int c, int bufi){
        const hf* srcs[3];
        int lds[3];
        int nt = 0;
        srcs[nt] = pAh + c*64; lds[nt] = lda; nt++;
        if (HASAL){ srcs[nt] = pAl + c*64; lds[nt] = lda; nt++; }
        srcs[nt] = pBh + c*64; lds[nt] = ldb; nt++;
#pragma unroll
        for (int t = 0; t < 2+HASAL; ++t){
            const uint32_t sb = smb + bufi*bufB + t*TILEB;
#pragma unroll
            for (int i = 0; i < 4; ++i){
                int e = tid + i*256;
                int row = e >> 3, cc = e & 7;
                cp16(sb + row*PITCH + cc*16, srcs[t] + (size_t)row*lds[t] + cc*8);
            }
        }
    };

    copy_chunk(0, 0);
    asm volatile("cp.async.commit_group;");
    copy_chunk(1, 1);
    asm volatile("cp.async.commit_group;");

    uint32_t aoff[4], boff[4];
    frag_offsets<PITCH>(l, wm, wn, aoff, boff);

    int bufc = 0;
    for (int c = 0; c < NC; ++c){
        if (c + 1 < NC) asm volatile("cp.async.wait_group 1;");
        else            asm volatile("cp.async.wait_group 0;");
        __syncthreads();
        if (c + 2 < NC){
            int b2 = bufc + 2; if (b2 >= 3) b2 -= 3;
            copy_chunk(c+2, b2);
            asm volatile("cp.async.commit_group;");
        }
        mma_tile<HASAL, PITCH, TILEB, 4>(smb + bufc*bufB, aoff, boff, acc);
        if (++bufc == 3) bufc = 0;
    }
    __syncthreads();

    stage_acc<132>(dyn, acc, wm, wn, quad, lane2);
    __syncthreads();
    float* stg = reinterpret_cast<float*>(dyn);
    if (mode == 0){
        for (int idx = tid; idx < 4096; idx += 256){
            int r = idx >> 5, c4 = (idx & 31) * 4;
            float4 v = *reinterpret_cast<const float4*>(stg + r*132 + c4);
            *reinterpret_cast<float4*>(oF + offO + (size_t)(m0+r)*ldo + n0 + c4) = v;
        }
    } else {
        for (int idx = tid; idx < 4096; idx += 256){
            int r = idx >> 5, c4 = (idx & 31) * 4;
            float4 v = *reinterpret_cast<const float4*>(stg + r*132 + c4);
            __half2 h0 = __floats2half2_rn(v.x, v.y);
            __half2 h1 = __floats2half2_rn(v.z, v.w);
            hf* p = oH + offO + (size_t)(m0+r)*ldo + n0 + c4;
            *reinterpret_cast<__half2*>(p)     = h0;
            *reinterpret_cast<__half2*>(p + 2) = h1;
        }
    }
}

// ---------------- merged projection GEMM: 1-pass, 6 stages, BK=32, 3-buffer single-sync ----------------
__global__ void __launch_bounds__(256, 2) k_proj(
    const float* __restrict__ e1, const float* __restrict__ ea,
    const float* __restrict__ ed, const float* __restrict__ eb,
    const hf* __restrict__ wq, const hf* __restrict__ wqd,
    const hf* __restrict__ wk, const hf* __restrict__ wkd,
    const hf* __restrict__ wv, const hf* __restrict__ wvd,
    hf* __restrict__ qAh, hf* __restrict__ kBh, hf* __restrict__ vAh)
{
    extern __shared__ char dyn[];
    const uint32_t smb = smem_u32(dyn);
    const int tid = threadIdx.x;
    const int l = tid & 31, wid = tid >> 5;
    const int wm = wid >> 2, wn = wid & 3;
    const int quad = l >> 2, lane2 = (l & 3) * 2;
    const int z = blockIdx.z;
    const int s = z >> 4, zz = z & 15;
    const int z2 = zz >> 2, z3 = zz & 3;
    const int m0 = blockIdx.x * 128, n0 = blockIdx.y * 128;

    const float* A; const hf* W; hf* oH; long sB3; int mode; int ldo;
    switch (s){
        case 0:  A = e1; W = wq;  sB3 = 65536; mode = 3; oH = qAh;            ldo = 4096; break;
        case 1:  A = ed; W = wqd; sB3 = 65536; mode = 3; oH = qAh + 16777216; ldo = 4096; break;
        case 2:  A = eb; W = wkd; sB3 = 0;     mode = 3; oH = kBh;            ldo = 4096; break;
        case 3:  A = ea; W = wk;  sB3 = 0;     mode = 3; oH = kBh + 16777216; ldo = 4096; break;
        case 4:  A = eb; W = wvd; sB3 = 0;     mode = 1; oH = vAh;            ldo = 256;  break;
        default: A = ea; W = wv;  sB3 = 0;     mode = 1; oH = vAh + 16777216; ldo = 256;  break;
    }
    const long offA = (long)z2*4194304 + (long)z3*256;
    const long offO = (long)z2*4194304 + (long)z3*1048576;
    const float* pA = A + offA + (size_t)m0*1024;
    const hf* pBh = W + z3*sB3 + (size_t)n0*256;

    float acc[4][4][4];
#pragma unroll
    for (int a = 0; a < 4; ++a)
#pragma unroll
        for (int b = 0; b < 4; ++b)
#pragma unroll
            for (int c = 0; c < 4; ++c) acc[a][b][c] = 0.f;

    auto copyB = [&](int c, int bufi){
        const uint32_t sb = smb + bufi*20480 + 10240;
#pragma unroll
        for (int i = 0; i < 2; ++i){
            int e = tid + i*256;
            int row = e >> 2, cc = e & 3;
            cp16(sb + row*80 + cc*16, pBh + c*32 + (size_t)row*256 + cc*8);
        }
    };
    auto ldgA = [&](float4* r, int c){
        const float* base = pA + c*32;
#pragma unroll
        for (int i = 0; i < 4; ++i){
            int e = tid + 256*i;
            int row = e >> 3, cg = e & 7;
            r[i] = *reinterpret_cast<const float4*>(base + (size_t)row*1024 + cg*4);
        }
    };
    auto stsA = [&](float4* r, int bufi){
        char* tA = dyn + bufi*20480;
#pragma unroll
        for (int i = 0; i < 4; ++i){
            int e = tid + 256*i;
            int row = e >> 3, cg = e & 7;
            float4 f = r[i];
            __half2 h0 = __floats2half2_rn(f.x, f.y);
            __half2 h1 = __floats2half2_rn(f.z, f.w);
            char* p = tA + row*80 + cg*8;
            *reinterpret_cast<__half2*>(p)     = h0;
            *reinterpret_cast<__half2*>(p + 4) = h1;
        }
    };

    uint32_t aoff[4], boff[4];
    frag_offsets<80>(l, wm, wn, aoff, boff);

    const int NC = 8;
    float4 rA[4];
    ldgA(rA, 0);
    stsA(rA, 0);
    copyB(0, 0);
    asm volatile("cp.async.commit_group;");
    ldgA(rA, 1);
    stsA(rA, 1);
    copyB(1, 1);
    asm volatile("cp.async.commit_group;");
    ldgA(rA, 2);

    int bufc = 0;
    for (int c = 0; c < NC; ++c){
        if (c + 1 < NC) asm volatile("cp.async.wait_group 1;");
        else            asm volatile("cp.async.wait_group 0;");
        __syncthreads();
        if (c + 2 < NC){
            int b2 = bufc + 2; if (b2 >= 3) b2 -= 3;
            stsA(rA, b2);
            copyB(c+2, b2);
            asm volatile("cp.async.commit_group;");
            if (c + 3 < NC) ldgA(rA, c+3);
        }
        mma_tile<0, 80, 10240, 2>(smb + bufc*20480, aoff, boff, acc);
        if (++bufc == 3) bufc = 0;
    }
    __syncthreads();

    stage_acc<129>(dyn, acc, wm, wn, quad, lane2);
    __syncthreads();
    float* stg = reinterpret_cast<float*>(dyn);
    if (mode == 1){
        for (int idx = tid; idx < 16384; idx += 256){
            int r = idx >> 7, cc = idx & 127;
            oH[offO + (size_t)(m0+r)*ldo + n0 + cc] = __float2half_rn(stg[r*129 + cc]);
        }
    } else {
        for (int idx = tid; idx < 16384; idx += 256){
            int cc = idx >> 7, r = idx & 127;
            oH[offO + (size_t)(n0+cc)*ldo + m0 + r] = __float2half_rn(stg[r*129 + cc]);
        }
    }
}

// ---------------- elementwise ----------------
__global__ void __launch_bounds__(256) k_splitW6(
    const float* __restrict__ Wq, const float* __restrict__ Wqd,
    const float* __restrict__ Wk, const float* __restrict__ Wkd,
    const float* __restrict__ Wv, const float* __restrict__ Wvd,
    hf* __restrict__ wqh, hf* __restrict__ wqdh,
    hf* __restrict__ wkh, hf* __restrict__ wkdh,
    hf* __restrict__ wvh, hf* __restrict__ wvdh)
{
    const int s = blockIdx.y;
    const float* src; hf* dst; int n;
    switch (s){
        case 0:  src = Wq;  dst = wqh;  n = 262144; break;
        case 1:  src = Wqd; dst = wqdh; n = 262144; break;
        case 2:  src = Wk;  dst = wkh;  n = 65536;  break;
        case 3:  src = Wkd; dst = wkdh; n = 65536;  break;
        case 4:  src = Wv;  dst = wvh;  n = 65536;  break;
        default: src = Wvd; dst = wvdh; n = 65536;  break;
    }
    int i = (blockIdx.x*256 + threadIdx.x) * 4;
    if (i >= n) return;
    float4 v = *reinterpret_cast<const float4*>(src + i);
    dst[i]   = __float2half_rn(v.x);
    dst[i+1] = __float2half_rn(v.y);
    dst[i+2] = __float2half_rn(v.z);
    dst[i+3] = __float2half_rn(v.w);
}
__global__ void __launch_bounds__(256) k_splitWo(const float* __restrict__ Wo,
                                                 const float* __restrict__ Wod,
                                                 hf* __restrict__ h){
    const float* s = blockIdx.y ? Wod : Wo;
    int idx = blockIdx.x*256 + threadIdx.x;
    int j = idx >> 10, t = idx & 1023;
    h[(size_t)blockIdx.y*1048576 + idx] =
        __float2half_rn(s[((size_t)j<<10) + ((t & 255)<<2) + (t>>8)]);
}
// split-K x4 reduce + moments partials (float4; 2048 blocks x 256 thr x 4 elems)
__global__ void __launch_bounds__(256) k_reduce(){
    const int t = threadIdx.x, b = blockIdx.x;
    const size_t i4 = ((size_t)b*256 + t)*4;
    const int path = (int)(i4 >> 20);
    const int r = (int)(i4 & 1048575);
    const float* p = g_sp + (size_t)path*4194304 + r;
    float4 sv = *reinterpret_cast<const float4*>(p);
#pragma unroll
    for (int sl = 1; sl < 4; ++sl){
        float4 v = *reinterpret_cast<const float4*>(p + (size_t)sl*1048576);
        sv.x += v.x; sv.y += v.y; sv.z += v.z; sv.w += v.w;
    }
    sv.x *= SCALEV; sv.y *= SCALEV; sv.z *= SCALEV; sv.w *= SCALEV;
    *reinterpret_cast<float4*>(g_s + i4) = sv;
    float sum = sv.x + sv.y + sv.z + sv.w;
    float sq  = sv.x*sv.x + sv.y*sv.y + sv.z*sv.z + sv.w*sv.w;
    __shared__ float sh[256], sh2[256];
    sh[t] = sum; sh2[t] = sq;
    __syncthreads();
    for (int o = 128; o; o >>= 1){
        if (t < o){ sh[t] += sh[t+o]; sh2[t] += sh2[t+o]; }
        __syncthreads();
    }
    if (t == 0){ g_red[b*2] = sh[0]; g_red[b*2+1] = sh2[0]; }
}
// 32 blocks x 32 threads: fold 64 partials per plane
__global__ void __launch_bounds__(32) k_moments(){
    const int p = blockIdx.x, t = threadIdx.x;
    float s = g_red[(p*64 + t)*2]     + g_red[(p*64 + 32 + t)*2];
    float q = g_red[(p*64 + t)*2 + 1] + g_red[(p*64 + 32 + t)*2 + 1];
#pragma unroll
    for (int o = 16; o; o >>= 1){
        s += __shfl_xor_sync(~0u, s, o);
        q += __shfl_xor_sync(~0u, q, o);
    }
    if (t == 0){
        float m = s * (1.f/65536.f);
        g_mv[p*2] = m;
        g_mv[p*2+1] = q * (1.f/65536.f) - m*m;
    }
}
__global__ void __launch_bounds__(256) k_softmax(){
    const int pb = blockIdx.z*16 + blockIdx.y;
    const size_t rb = ((size_t)pb*256 + blockIdx.x)*256;
    const float mean = g_mv[pb*2];
    const float inv  = rsqrtf(g_mv[pb*2+1] + EPSV);
    const int tid = threadIdx.x;
    float y = (g_s[rb + tid] - mean) * inv;
    __shared__ float red[8];
    float m = y;
#pragma unroll
    for (int o = 16; o; o >>= 1) m = fmaxf(m, __shfl_xor_sync(~0u, m, o));
    if ((tid & 31) == 0) red[tid>>5] = m;
    __syncthreads();
    if (tid == 0){ float mm = red[0]; for (int i=1;i<8;++i) mm = fmaxf(mm, red[i]); red[0] = mm; }
    __syncthreads();
    float e = expf(y - red[0]);
    __syncthreads();
    float ssum = e;
#pragma unroll
    for (int o = 16; o; o >>= 1) ssum += __shfl_xor_sync(~0u, ssum, o);
    if ((tid & 31) == 0) red[tid>>5] = ssum;
    __syncthreads();
    if (tid == 0){ float t = 0.f; for (int i=0;i<8;++i) t += red[i]; red[0] = t; }
    __syncthreads();
    g_ph[rb + tid] = __float2half_rn(e / red[0]);
}

// ---------------- launch ----------------
static void* dsym(const void* s){ void* p = 0; cudaGetSymbolAddress(&p, s); return p; }

extern "C" void kernel_launch(void* const* d_in, const int* in_sizes, int n_in,
                              void* d_out, int out_size)
{
    const float* emb1     = (const float*)d_in[0];
    const float* emb_all  = (const float*)d_in[1];
    const float* embd1    = (const float*)d_in[2];
    const float* emb_alld = (const float*)d_in[3];
    const float* Wq = (const float*)d_in[4];  const float* Wqd = (const float*)d_in[5];
    const float* Wk = (const float*)d_in[6];  const float* Wv  = (const float*)d_in[7];
    const float* Wkd= (const float*)d_in[8];  const float* Wvd = (const float*)d_in[9];
    const float* Wo = (const float*)d_in[10]; const float* Wod = (const float*)d_in[11];
    float* out = (float*)d_out;

    const int SM0 = 110592;   // k_gemm<0>: 3 buf x 2 tiles x 18432 (epilogue 67584 fits)
    const int SMP = 66048;    // k_proj: 3 x 20480 buffers (61440) + 129-pitch stage 66048
    cudaFuncSetAttribute(k_gemm<0>, cudaFuncAttributeMaxDynamicSharedMemorySize, SM0);
    cudaFuncSetAttribute(k_proj,    cudaFuncAttributeMaxDynamicSharedMemorySize, SMP);

#define GH(x) ((hf*)dsym(x))
    hf *qAh = GH(g_qAh);
    hf *kBh = GH(g_kBh), *vAh = GH(g_vAh);
    hf *ch = GH(g_ch), *ph = GH(g_ph), *woh = GH(g_woh);
    float* sp = (float*)dsym(g_sp);

    // weight conversions (merged)
    k_splitW6<<<dim3(256,6),256>>>(Wq,Wqd,Wk,Wkd,Wv,Wvd,
                                   GH(g_wqh),GH(g_wqdh),GH(g_wkh),GH(g_wkdh),GH(g_wvh),GH(g_wvdh));
    k_splitWo<<<dim3(4096,2),256>>>(Wo, Wod, woh);

    // projections: 1-pass, all 6 stages in one launch
    k_proj<<<dim3(32,2,96),256,SMP>>>(emb1, emb_all, embd1, emb_alld,
                                      GH(g_wqh),GH(g_wqdh),GH(g_wkh),GH(g_wkdh),GH(g_wvh),GH(g_wvdh),
                                      qAh, kBh, vAh);

    // scores: 1-pass (Q hi x K hi), split-K x4, one launch
    dim3 gsc(2,2,128);
    k_gemm<0><<<gsc,256,SM0>>>(qAh,(hf*)0, 16777216,1048576,1024, 4096,
                               kBh, 16777216,1048576,1024, 4096,
                               1024, 64,4, 0,
                               sp, (hf*)0, 4194304,65536,1048576, 256);
    k_reduce<<<2048,256>>>();
    k_moments<<<32,32>>>();
    k_softmax<<<dim3(256,16,2),256>>>();

    // ctx: 1-pass (V hi x probs hi), both paths in one launch
    dim3 gc(32,2,32);
    k_gemm<0><<<gc,256,SM0>>>(vAh,(hf*)0, 16777216,4194304,1048576, 256,
                              ph, 1048576,262144,65536, 256,
                              256, 16,4, 1,
                              (float*)0, ch, 16777216,4194304,256, 1024);

    // out: 1-pass (ctx hi x Wo hi), both paths in one launch
    dim3 go(128,8,2);
    k_gemm<0><<<go,256,SM0>>>(ch,(hf*)0, 16777216,0,0, 1024,
                              woh, 1048576,0,0, 1024,
                              1024, 1,1, 0,
                              out, (hf*)0, 16777216,0,0, 1024);
#undef GH
}